// round 1
// baseline (speedup 1.0000x reference)
#include <cuda_runtime.h>
#include <math.h>
#include <float.h>

// ---------------- problem constants ----------------
constexpr int B_   = 4;     // batch
constexpr int T_   = 8;     // time bins
constexpr int HH   = 8;     // heads
constexpr int DH   = 75;    // dim head
constexpr int NL   = 128;   // num latents
constexpr int LD   = 512;   // latent dim
constexpr int ID2  = 435;   // input (context) dim
constexpr int IN_  = 600;   // inner dim (heads*dim_head)
constexpr int FF   = 2048;
constexpr int OC   = 64;
constexpr int DEPTH= 5;
constexpr int GH   = 32, GW = 32;        // patched grid
constexpr int NVOX = GH*GW*T_;           // 8192
constexpr float ATT_SCALE = 0.11547005383792515f; // 75^-0.5

// ---------------- scratch (static device, no cudaMalloc) ----------------
__device__ float g_dnorm[(size_t)B_*NVOX*ID2];      // normalized context data
__device__ float g_mask [(size_t)B_*NVOX];          // 1 kept / 0 masked
__device__ float g_lat  [(size_t)B_*NL*LD];
__device__ float g_xn   [(size_t)B_*NL*LD];
__device__ float g_q    [(size_t)B_*NL*IN_];
__device__ float g_kv   [(size_t)B_*NVOX*2*IN_];    // also reused for self-attn kv
__device__ float g_Qh   [(size_t)B_*HH*NL*DH];
__device__ float g_Kh   [(size_t)B_*HH*NVOX*DH];
__device__ float g_Vh   [(size_t)B_*HH*NVOX*DH];
__device__ float g_S    [(size_t)B_*HH*NL*NVOX];    // scores / probs
__device__ float g_AVp  [(size_t)8*B_*HH*NL*DH];    // split-K partials
__device__ float g_AO   [(size_t)B_*NL*IN_];
__device__ float g_hid  [(size_t)B_*NL*FF];
__device__ float g_logits[(size_t)B_*NL*OC];

// ---------------- generic batched GEMM ----------------
#define EPI_BIAS 1
#define EPI_GELU 2
#define EPI_RES  4
#define EPI_MASK 8

template<int BM,int BN,int BK,int TM,int TN,bool TB,int EPI>
__global__ void __launch_bounds__((BM/TM)*(BN/TN))
sip_gemm(int M,int N,int K,
         const float* __restrict__ A,int lda,long sA,
         const float* __restrict__ Bp,int ldb,long sB,
         float* __restrict__ C,int ldc,long sC,
         const float* __restrict__ bias,
         const float* __restrict__ resid,
         const float* __restrict__ alphaPtr,float alphaC,
         const float* __restrict__ maskPtr,int maskBdiv,int maskStride,
         int nsplit)
{
    constexpr int NT = (BM/TM)*(BN/TN);
    __shared__ float As[BK][BM];
    __shared__ float Bs[BK][BN];
    int tid = threadIdx.x;
    int z = blockIdx.z;
    int batch = z / nsplit, split = z - batch*nsplit;
    int kchunk = (K + nsplit - 1) / nsplit;
    int k0 = split * kchunk;
    int k1 = min(K, k0 + kchunk);
    const float* Ab = A + (long)batch * sA;
    const float* Bb = Bp + (long)batch * sB;
    int row0 = blockIdx.y * BM, col0 = blockIdx.x * BN;
    int tx = tid % (BN/TN), ty = tid / (BN/TN);
    float acc[TM][TN];
#pragma unroll
    for (int i=0;i<TM;i++)
#pragma unroll
        for (int j=0;j<TN;j++) acc[i][j]=0.f;

    constexpr int ALD = BM*BK/NT;
    constexpr int BLD = BN*BK/NT;
    for (int kt = k0; kt < k1; kt += BK) {
#pragma unroll
        for (int e=0;e<ALD;e++){
            int idx = tid*ALD + e;
            int m = idx / BK, k = idx % BK;
            int gm = row0 + m, gk = kt + k;
            As[k][m] = (gm < M && gk < k1) ? Ab[(long)gm*lda + gk] : 0.f;
        }
#pragma unroll
        for (int e=0;e<BLD;e++){
            int idx = tid*BLD + e;
            if (TB){
                int n = idx / BK, k = idx % BK;
                int gn = col0 + n, gk = kt + k;
                Bs[k][n] = (gn < N && gk < k1) ? Bb[(long)gn*ldb + gk] : 0.f;
            } else {
                int k = idx / BN, n = idx % BN;
                int gn = col0 + n, gk = kt + k;
                Bs[k][n] = (gn < N && gk < k1) ? Bb[(long)gk*ldb + gn] : 0.f;
            }
        }
        __syncthreads();
#pragma unroll
        for (int k=0;k<BK;k++){
            float af[TM], bf[TN];
#pragma unroll
            for (int i=0;i<TM;i++) af[i] = As[k][ty*TM+i];
#pragma unroll
            for (int j=0;j<TN;j++) bf[j] = Bs[k][tx*TN+j];
#pragma unroll
            for (int i=0;i<TM;i++)
#pragma unroll
                for (int j=0;j<TN;j++) acc[i][j] = fmaf(af[i], bf[j], acc[i][j]);
        }
        __syncthreads();
    }

    float alpha = alphaC;
    if (alphaPtr) alpha *= alphaPtr[0];
    long coff = (nsplit > 1) ? (long)z * M * ldc : (long)batch * sC;
    float* Cb = C + coff;
    const float* Rb = (EPI & EPI_RES) ? resid + (long)batch * sC : nullptr;
    const float* mrow = (EPI & EPI_MASK) ? maskPtr + (long)(batch / maskBdiv) * maskStride : nullptr;
#pragma unroll
    for (int i=0;i<TM;i++){
        int gm = row0 + ty*TM + i;
        if (gm >= M) continue;
#pragma unroll
        for (int j=0;j<TN;j++){
            int gn = col0 + tx*TN + j;
            if (gn >= N) continue;
            float v = acc[i][j] * alpha;
            if (EPI & EPI_MASK){ if (mrow[gn] < 0.5f) v = -FLT_MAX; }
            if (EPI & EPI_BIAS) v += bias[gn];
            if (EPI & EPI_GELU) v = 0.5f * v * (1.f + erff(v * 0.7071067811865476f));
            if (EPI & EPI_RES)  v += Rb[(long)gm*ldc + gn];
            Cb[(long)gm*ldc + gn] = v;
        }
    }
}

// ---------------- featurization: patch + fourier + L2-normalize + mask ----------------
__global__ void sip_build_data(const float* __restrict__ input)
{
    int vox = blockIdx.x;                 // b*NVOX + n
    int b = vox / NVOX, n = vox % NVOX;
    int hy = n / (GW*T_), wx = (n / T_) % GW, tt = n % T_;
    __shared__ float row[ID2];
    __shared__ float sh[4];
    int tid = threadIdx.x;                // 128 threads
    if (tid < 48){
        int py = tid/12, px = (tid/3)%4, c = tid%3;
        row[tid] = input[(((long)tt*B_ + b)*3 + c)*16384 + (hy*4+py)*128 + (wx*4+px)];
    }
    float pos[3] = {2.f*hy/GH - 1.f, 2.f*wx/GW - 1.f, 2.f*tt/T_ - 1.f};
    for (int e = 48 + tid; e < ID2; e += 128){
        int q = e - 48; int c = q / 129, r = q % 129;
        float x = pos[c], v;
        if (r < 64)        v = sinf(x * exp2f((float)(-r)));
        else if (r < 128)  v = cosf(x * exp2f((float)(64 - r)));
        else               v = x;
        row[e] = v;
    }
    __syncthreads();
    float ss = 0.f;
    for (int e = tid; e < ID2; e += 128){ float v = row[e]; ss += v*v; }
    for (int o=16;o>0;o>>=1) ss += __shfl_xor_sync(0xffffffffu, ss, o);
    if ((tid & 31) == 0) sh[tid>>5] = ss;
    __syncthreads();
    float tot = sh[0]+sh[1]+sh[2]+sh[3];
    float inv = 1.f / fmaxf(sqrtf(tot), 1e-5f);
    for (int e = tid; e < ID2; e += 128)
        g_dnorm[(long)vox*ID2 + e] = row[e] * inv;
    if (tid == 0){
        float mx = row[0];
#pragma unroll
        for (int j=1;j<48;j++) mx = fmaxf(mx, row[j]);
        g_mask[vox] = (fabsf(mx) > 0.3f) ? 1.f : 0.f;
    }
}

// ---------------- row L2-norm with scalar gain ----------------
__global__ void sip_rownorm(const float* __restrict__ in, float* __restrict__ out,
                            int cols, const float* __restrict__ gptr)
{
    long row = blockIdx.x;
    const float* p = in + row * cols;
    float* q = out + row * cols;
    __shared__ float sh[8];
    int tid = threadIdx.x;
    float s = 0.f;
    for (int j = tid; j < cols; j += blockDim.x){ float v = p[j]; s += v*v; }
    for (int o=16;o>0;o>>=1) s += __shfl_xor_sync(0xffffffffu, s, o);
    if ((tid & 31) == 0) sh[tid>>5] = s;
    __syncthreads();
    float tot = 0.f;
    int nw = blockDim.x >> 5;
    for (int w=0; w<nw; w++) tot += sh[w];
    float sc = gptr[0] / fmaxf(sqrtf(tot), 1e-5f);
    for (int j = tid; j < cols; j += blockDim.x) q[j] = p[j] * sc;
}

// ---------------- softmax over rows (in place) ----------------
__global__ void sip_softmax(float* __restrict__ S, int cols)
{
    long row = blockIdx.x;
    float* p = S + row * (long)cols;
    __shared__ float sh[8];
    int tid = threadIdx.x;
    int nw = blockDim.x >> 5;
    float m = -FLT_MAX;
    for (int j = tid; j < cols; j += blockDim.x) m = fmaxf(m, p[j]);
    for (int o=16;o>0;o>>=1) m = fmaxf(m, __shfl_xor_sync(0xffffffffu, m, o));
    if ((tid & 31) == 0) sh[tid>>5] = m;
    __syncthreads();
    float mm = sh[0];
    for (int w=1; w<nw; w++) mm = fmaxf(mm, sh[w]);
    __syncthreads();
    float s = 0.f;
    for (int j = tid; j < cols; j += blockDim.x){
        float e = expf(p[j] - mm);
        p[j] = e; s += e;
    }
    for (int o=16;o>0;o>>=1) s += __shfl_xor_sync(0xffffffffu, s, o);
    if ((tid & 31) == 0) sh[tid>>5] = s;
    __syncthreads();
    float tot = 0.f;
    for (int w=0; w<nw; w++) tot += sh[w];
    float inv = 1.f / tot;
    for (int j = tid; j < cols; j += blockDim.x) p[j] *= inv;
}

// ---------------- layout shuffles ----------------
__global__ void sip_split_kv(int seq)   // g_kv (b, seq, 1200) -> g_Kh/g_Vh (b,h,seq,75)
{
    long total = (long)B_ * seq * (2*IN_);
    long idx = (long)blockIdx.x * blockDim.x + threadIdx.x;
    if (idx >= total) return;
    int c = (int)(idx % (2*IN_));
    long rj = idx / (2*IN_);
    int j = (int)(rj % seq);
    int b = (int)(rj / seq);
    float v = g_kv[idx];
    if (c < IN_){
        int h = c / DH, dd = c % DH;
        g_Kh[(((long)(b*HH + h))*seq + j)*DH + dd] = v;
    } else {
        int c2 = c - IN_;
        int h = c2 / DH, dd = c2 % DH;
        g_Vh[(((long)(b*HH + h))*seq + j)*DH + dd] = v;
    }
}

__global__ void sip_split_q()           // g_q (b,128,600) -> g_Qh (b,h,128,75)
{
    long total = (long)B_ * NL * IN_;
    long idx = (long)blockIdx.x * blockDim.x + threadIdx.x;
    if (idx >= total) return;
    int c = (int)(idx % IN_);
    long ri = idx / IN_;
    int i = (int)(ri % NL);
    int b = (int)(ri / NL);
    int h = c / DH, dd = c % DH;
    g_Qh[(((long)(b*HH + h))*NL + i)*DH + dd] = g_q[idx];
}

__global__ void sip_reduce_av(int nsplit)  // partials -> g_AO (b, 128, 600)
{
    long total = (long)B_ * NL * IN_;
    long idx = (long)blockIdx.x * blockDim.x + threadIdx.x;
    if (idx >= total) return;
    int b = (int)(idx / (NL*IN_));
    int r = (int)(idx % (NL*IN_));
    int i = r / IN_, c = r % IN_;
    int h = c / DH, dd = c % DH;
    long base = ((long)(b*HH + h) * nsplit) * (NL*DH) + (long)i*DH + dd;
    float s = 0.f;
    for (int sp = 0; sp < nsplit; sp++) s += g_AVp[base + (long)sp*(NL*DH)];
    g_AO[idx] = s;
}

__global__ void sip_init_lat(const float* __restrict__ latents, const float* __restrict__ pos)
{
    long idx = (long)blockIdx.x * blockDim.x + threadIdx.x;
    if (idx >= (long)B_*NL*LD) return;
    int r = (int)(idx % (NL*LD));
    g_lat[idx] = latents[r] + pos[r];
}

__global__ void sip_permute_out(float* __restrict__ out)
{
    long idx = (long)blockIdx.x * blockDim.x + threadIdx.x;
    if (idx >= (long)T_*B_*16*OC) return;
    int o = (int)(idx % OC);
    long r = idx / OC;
    int nn = (int)(r % 16); r /= 16;
    int b = (int)(r % B_);
    int tt = (int)(r / B_);
    out[idx] = g_logits[((long)b*NL + nn*T_ + tt)*OC + o];
}

// ---------------- host ----------------
static inline int cdiv(int a, int b){ return (a + b - 1) / b; }

extern "C" void kernel_launch(void* const* d_in, const int* in_sizes, int n_in,
                              void* d_out, int out_size)
{
    const float* input    = (const float*)d_in[0];
    const float* latents  = (const float*)d_in[1];
    const float* pos_emb  = (const float*)d_in[2];
    const float* ca_g     = (const float*)d_in[3];
    const float* ca_ctx_g = (const float*)d_in[4];
    const float* ca_q     = (const float*)d_in[5];
    const float* ca_kv    = (const float*)d_in[6];
    const float* ca_ow    = (const float*)d_in[7];
    const float* ca_ob    = (const float*)d_in[8];
    const float* cf_g     = (const float*)d_in[9];
    const float* cf_w1    = (const float*)d_in[10];
    const float* cf_b1    = (const float*)d_in[11];
    const float* cf_w2    = (const float*)d_in[12];
    const float* cf_b2    = (const float*)d_in[13];
    const float* la_g     = (const float*)d_in[14];
    const float* la_q     = (const float*)d_in[15];
    const float* la_kv    = (const float*)d_in[16];
    const float* la_ow    = (const float*)d_in[17];
    const float* la_ob    = (const float*)d_in[18];
    const float* lf_g     = (const float*)d_in[19];
    const float* lf_w1    = (const float*)d_in[20];
    const float* lf_b1    = (const float*)d_in[21];
    const float* lf_w2    = (const float*)d_in[22];
    const float* lf_b2    = (const float*)d_in[23];
    const float* logits_w = (const float*)d_in[24];
    const float* logits_b = (const float*)d_in[25];
    float* out = (float*)d_out;

    float *p_dnorm,*p_mask,*p_lat,*p_xn,*p_q,*p_kv,*p_Qh,*p_Kh,*p_Vh,*p_S,*p_AVp,*p_AO,*p_hid,*p_logits;
#define SYM(p, s) do{ void* _t=nullptr; cudaGetSymbolAddress(&_t, s); p=(float*)_t; }while(0)
    SYM(p_dnorm, g_dnorm); SYM(p_mask, g_mask); SYM(p_lat, g_lat); SYM(p_xn, g_xn);
    SYM(p_q, g_q); SYM(p_kv, g_kv); SYM(p_Qh, g_Qh); SYM(p_Kh, g_Kh); SYM(p_Vh, g_Vh);
    SYM(p_S, g_S); SYM(p_AVp, g_AVp); SYM(p_AO, g_AO); SYM(p_hid, g_hid); SYM(p_logits, g_logits);
#undef SYM

    const int M0 = B_*NL;  // 512

    sip_build_data<<<B_*NVOX, 128>>>(input);
    sip_init_lat<<<cdiv(B_*NL*LD,256), 256>>>(latents, pos_emb);

    for (int d = 0; d < DEPTH; d++){
        // ===== cross attention =====
        sip_rownorm<<<M0, 256>>>(p_lat, p_xn, LD, ca_g + d);
        // q = xn @ ca_q[d]
        sip_gemm<64,64,16,4,4,false,0><<<dim3(cdiv(IN_,64),cdiv(M0,64),1),256>>>(
            M0, IN_, LD, p_xn, LD, 0, ca_q + (long)d*LD*IN_, IN_, 0,
            p_q, IN_, 0, nullptr, nullptr, nullptr, 1.f, nullptr, 1, 0, 1);
        // kv = (g * dnorm) @ ca_kv[d]
        sip_gemm<128,128,8,8,8,false,0><<<dim3(cdiv(2*IN_,128),cdiv(B_*NVOX,128),1),256>>>(
            B_*NVOX, 2*IN_, ID2, p_dnorm, ID2, 0, ca_kv + (long)d*ID2*2*IN_, 2*IN_, 0,
            p_kv, 2*IN_, 0, nullptr, nullptr, ca_ctx_g + d, 1.f, nullptr, 1, 0, 1);
        sip_split_q<<<cdiv(B_*NL*IN_,256), 256>>>();
        sip_split_kv<<<cdiv(B_*NVOX*2*IN_,256), 256>>>(NVOX);
        // scores = Qh @ Kh^T * scale, masked
        sip_gemm<128,128,8,8,8,true,EPI_MASK><<<dim3(cdiv(NVOX,128),1,B_*HH),256>>>(
            NL, NVOX, DH, p_Qh, DH, (long)NL*DH, p_Kh, DH, (long)NVOX*DH,
            p_S, NVOX, (long)NL*NVOX, nullptr, nullptr, nullptr, ATT_SCALE,
            p_mask, HH, NVOX, 1);
        sip_softmax<<<B_*HH*NL, 256>>>(p_S, NVOX);
        // AV: split-K=8
        sip_gemm<128,128,8,8,8,false,0><<<dim3(1,1,B_*HH*8),256>>>(
            NL, DH, NVOX, p_S, NVOX, (long)NL*NVOX, p_Vh, DH, (long)NVOX*DH,
            p_AVp, DH, 0, nullptr, nullptr, nullptr, 1.f, nullptr, 1, 0, 8);
        sip_reduce_av<<<cdiv(B_*NL*IN_,256), 256>>>(8);
        // out proj + bias + residual
        sip_gemm<64,64,16,4,4,false,EPI_BIAS|EPI_RES><<<dim3(cdiv(LD,64),cdiv(M0,64),1),256>>>(
            M0, LD, IN_, p_AO, IN_, 0, ca_ow + (long)d*IN_*LD, LD, 0,
            p_lat, LD, 0, ca_ob + (long)d*LD, p_lat, nullptr, 1.f, nullptr, 1, 0, 1);

        // ===== feed-forward (cross) =====
        sip_rownorm<<<M0, 256>>>(p_lat, p_xn, LD, cf_g + d);
        sip_gemm<64,64,16,4,4,false,EPI_BIAS|EPI_GELU><<<dim3(cdiv(FF,64),cdiv(M0,64),1),256>>>(
            M0, FF, LD, p_xn, LD, 0, cf_w1 + (long)d*LD*FF, FF, 0,
            p_hid, FF, 0, cf_b1 + (long)d*FF, nullptr, nullptr, 1.f, nullptr, 1, 0, 1);
        sip_gemm<64,64,16,4,4,false,EPI_BIAS|EPI_RES><<<dim3(cdiv(LD,64),cdiv(M0,64),1),256>>>(
            M0, LD, FF, p_hid, FF, 0, cf_w2 + (long)d*FF*LD, LD, 0,
            p_lat, LD, 0, cf_b2 + (long)d*LD, p_lat, nullptr, 1.f, nullptr, 1, 0, 1);

        // ===== latent self-attention =====
        sip_rownorm<<<M0, 256>>>(p_lat, p_xn, LD, la_g + d);
        sip_gemm<64,64,16,4,4,false,0><<<dim3(cdiv(IN_,64),cdiv(M0,64),1),256>>>(
            M0, IN_, LD, p_xn, LD, 0, la_q + (long)d*LD*IN_, IN_, 0,
            p_q, IN_, 0, nullptr, nullptr, nullptr, 1.f, nullptr, 1, 0, 1);
        sip_gemm<64,64,16,4,4,false,0><<<dim3(cdiv(2*IN_,64),cdiv(M0,64),1),256>>>(
            M0, 2*IN_, LD, p_xn, LD, 0, la_kv + (long)d*LD*2*IN_, 2*IN_, 0,
            p_kv, 2*IN_, 0, nullptr, nullptr, nullptr, 1.f, nullptr, 1, 0, 1);
        sip_split_q<<<cdiv(B_*NL*IN_,256), 256>>>();
        sip_split_kv<<<cdiv(B_*NL*2*IN_,256), 256>>>(NL);
        sip_gemm<64,64,16,4,4,true,0><<<dim3(cdiv(NL,64),cdiv(NL,64),B_*HH),256>>>(
            NL, NL, DH, p_Qh, DH, (long)NL*DH, p_Kh, DH, (long)NL*DH,
            p_S, NL, (long)NL*NL, nullptr, nullptr, nullptr, ATT_SCALE, nullptr, 1, 0, 1);
        sip_softmax<<<B_*HH*NL, 256>>>(p_S, NL);
        sip_gemm<64,64,16,4,4,false,0><<<dim3(cdiv(DH,64),cdiv(NL,64),B_*HH),256>>>(
            NL, DH, NL, p_S, NL, (long)NL*NL, p_Vh, DH, (long)NL*DH,
            p_AVp, DH, (long)NL*DH, nullptr, nullptr, nullptr, 1.f, nullptr, 1, 0, 1);
        sip_reduce_av<<<cdiv(B_*NL*IN_,256), 256>>>(1);
        sip_gemm<64,64,16,4,4,false,EPI_BIAS|EPI_RES><<<dim3(cdiv(LD,64),cdiv(M0,64),1),256>>>(
            M0, LD, IN_, p_AO, IN_, 0, la_ow + (long)d*IN_*LD, LD, 0,
            p_lat, LD, 0, la_ob + (long)d*LD, p_lat, nullptr, 1.f, nullptr, 1, 0, 1);

        // ===== feed-forward (latent) =====
        sip_rownorm<<<M0, 256>>>(p_lat, p_xn, LD, lf_g + d);
        sip_gemm<64,64,16,4,4,false,EPI_BIAS|EPI_GELU><<<dim3(cdiv(FF,64),cdiv(M0,64),1),256>>>(
            M0, FF, LD, p_xn, LD, 0, lf_w1 + (long)d*LD*FF, FF, 0,
            p_hid, FF, 0, lf_b1 + (long)d*FF, nullptr, nullptr, 1.f, nullptr, 1, 0, 1);
        sip_gemm<64,64,16,4,4,false,EPI_BIAS|EPI_RES><<<dim3(cdiv(LD,64),cdiv(M0,64),1),256>>>(
            M0, LD, FF, p_hid, FF, 0, lf_w2 + (long)d*FF*LD, LD, 0,
            p_lat, LD, 0, cf_b2 ? lf_b2 + (long)d*LD : nullptr, p_lat, nullptr, 1.f, nullptr, 1, 0, 1);
    }

    // ===== logits + output permute =====
    sip_gemm<64,64,16,4,4,false,EPI_BIAS><<<dim3(cdiv(OC,64),cdiv(M0,64),1),256>>>(
        M0, OC, LD, p_lat, LD, 0, logits_w, OC, 0,
        p_logits, OC, 0, logits_b, nullptr, nullptr, 1.f, nullptr, 1, 0, 1);
    sip_permute_out<<<cdiv(T_*B_*16*OC,256), 256>>>(out);
}

// round 2
// speedup vs baseline: 1.5027x; 1.5027x over previous
#include <cuda_runtime.h>
#include <math.h>
#include <float.h>

// ---------------- problem constants ----------------
constexpr int B_   = 4;
constexpr int T_   = 8;
constexpr int HH   = 8;
constexpr int DH   = 75;
constexpr int NL   = 128;
constexpr int LD   = 512;
constexpr int ID2  = 435;
constexpr int VC   = 48;     // value channels (patch p*p*c)
constexpr int EC   = 387;    // fourier enc channels
constexpr int IN_  = 600;
constexpr int FF   = 2048;
constexpr int OC   = 64;
constexpr int DEPTH= 5;
constexpr int GH   = 32, GW = 32;
constexpr int NVOX = GH*GW*T_;           // 8192
constexpr int NSPL = 16;                 // split-K for cross AV
constexpr float ATT_SCALE = 0.11547005383792515f;

// ---------------- scratch ----------------
__device__ float g_vals [(size_t)B_*NVOX*VC];
__device__ float g_enc  [(size_t)NVOX*EC];
__device__ float g_encss[(size_t)NVOX];
__device__ float g_invn [(size_t)B_*NVOX];
__device__ float g_mask [(size_t)B_*NVOX];
__device__ float g_EP   [(size_t)DEPTH*NVOX*2*IN_];   // enc @ We per layer
__device__ float g_lat  [(size_t)B_*NL*LD];
__device__ float g_xn   [(size_t)B_*NL*LD];
__device__ float g_Qh   [(size_t)B_*HH*NL*DH];
__device__ float g_Kh   [(size_t)B_*HH*NVOX*DH];
__device__ float g_Vh   [(size_t)B_*HH*NVOX*DH];
__device__ float g_S    [(size_t)B_*HH*NL*NVOX];
__device__ float g_AVp  [(size_t)NSPL*B_*HH*NL*DH];
__device__ float g_AO   [(size_t)B_*NL*IN_];
__device__ float g_hid  [(size_t)B_*NL*FF];
__device__ float g_logits[(size_t)B_*NL*OC];

// ---------------- generic batched GEMM w/ fused epilogues ----------------
#define EPI_BIAS 1
#define EPI_GELU 2
#define EPI_RES  4
#define EPI_MASK 8
#define EPI_KV   16   // scatter to Kh/Vh (+ optional EP add + row scale)
#define EPI_Q    32   // scatter to Qh

template<int BM,int BN,int BK,int TM,int TN,bool TB,int EPI>
__global__ void __launch_bounds__((BM/TM)*(BN/TN))
sip_gemm(int M,int N,int K,
         const float* __restrict__ A,int lda,long sA,
         const float* __restrict__ Bp,int ldb,long sB,
         float* __restrict__ C,int ldc,long sC,
         const float* __restrict__ bias,
         const float* __restrict__ resid,
         const float* __restrict__ alphaPtr,float alphaC,
         const float* __restrict__ maskPtr,int maskBdiv,int maskStride,
         int nsplit,
         const float* __restrict__ ep,
         const float* __restrict__ rowscale,
         float* __restrict__ KhD, float* __restrict__ VhD, int kvSeq)
{
    constexpr int NT = (BM/TM)*(BN/TN);
    __shared__ float As[BK][BM];
    __shared__ float Bs[BK][BN];
    int tid = threadIdx.x;
    int z = blockIdx.z;
    int batch = z / nsplit, split = z - batch*nsplit;
    int kchunk = (K + nsplit - 1) / nsplit;
    int k0 = split * kchunk;
    int k1 = min(K, k0 + kchunk);
    const float* Ab = A + (long)batch * sA;
    const float* Bb = Bp + (long)batch * sB;
    int row0 = blockIdx.y * BM, col0 = blockIdx.x * BN;
    int tx = tid % (BN/TN), ty = tid / (BN/TN);
    float acc[TM][TN];
#pragma unroll
    for (int i=0;i<TM;i++)
#pragma unroll
        for (int j=0;j<TN;j++) acc[i][j]=0.f;

    constexpr int ALD = BM*BK/NT;
    constexpr int BLD = BN*BK/NT;
    for (int kt = k0; kt < k1; kt += BK) {
#pragma unroll
        for (int e=0;e<ALD;e++){
            int idx = tid*ALD + e;
            int m = idx / BK, k = idx % BK;
            int gm = row0 + m, gk = kt + k;
            As[k][m] = (gm < M && gk < k1) ? Ab[(long)gm*lda + gk] : 0.f;
        }
#pragma unroll
        for (int e=0;e<BLD;e++){
            int idx = tid*BLD + e;
            if (TB){
                int n = idx / BK, k = idx % BK;
                int gn = col0 + n, gk = kt + k;
                Bs[k][n] = (gn < N && gk < k1) ? Bb[(long)gn*ldb + gk] : 0.f;
            } else {
                int k = idx / BN, n = idx % BN;
                int gn = col0 + n, gk = kt + k;
                Bs[k][n] = (gn < N && gk < k1) ? Bb[(long)gk*ldb + gn] : 0.f;
            }
        }
        __syncthreads();
#pragma unroll
        for (int k=0;k<BK;k++){
            float af[TM], bf[TN];
#pragma unroll
            for (int i=0;i<TM;i++) af[i] = As[k][ty*TM+i];
#pragma unroll
            for (int j=0;j<TN;j++) bf[j] = Bs[k][tx*TN+j];
#pragma unroll
            for (int i=0;i<TM;i++)
#pragma unroll
                for (int j=0;j<TN;j++) acc[i][j] = fmaf(af[i], bf[j], acc[i][j]);
        }
        __syncthreads();
    }

    float alpha = alphaC;
    if (alphaPtr) alpha *= alphaPtr[0];

    if (EPI & (EPI_KV | EPI_Q)){
#pragma unroll
        for (int i=0;i<TM;i++){
            int gm = row0 + ty*TM + i;
            if (gm >= M) continue;
            float rs = 1.f;
            int bb, jj;
            if (EPI & EPI_KV){
                bb = gm / kvSeq; jj = gm - bb*kvSeq;
                if (rowscale) rs = rowscale[gm];
            } else {
                bb = gm / NL; jj = gm - bb*NL;
            }
#pragma unroll
            for (int j=0;j<TN;j++){
                int gn = col0 + tx*TN + j;
                if (gn >= N) continue;
                float v = acc[i][j];
                if (EPI & EPI_KV){
                    if (ep) v += ep[(long)jj*N + gn];
                    v *= alpha * rs;
                    int c = gn;
                    if (c < IN_){
                        int h = c / DH, dd = c - h*DH;
                        KhD[(((long)(bb*HH + h))*kvSeq + jj)*DH + dd] = v;
                    } else {
                        c -= IN_;
                        int h = c / DH, dd = c - h*DH;
                        VhD[(((long)(bb*HH + h))*kvSeq + jj)*DH + dd] = v;
                    }
                } else {
                    v *= alpha;
                    int h = gn / DH, dd = gn - h*DH;
                    KhD[(((long)(bb*HH + h))*NL + jj)*DH + dd] = v;
                }
            }
        }
        return;
    }

    long coff = (nsplit > 1) ? (long)z * M * ldc : (long)batch * sC;
    float* Cb = C + coff;
    const float* Rb = (EPI & EPI_RES) ? resid + (long)batch * sC : nullptr;
    const float* mrow = (EPI & EPI_MASK) ? maskPtr + (long)(batch / maskBdiv) * maskStride : nullptr;
#pragma unroll
    for (int i=0;i<TM;i++){
        int gm = row0 + ty*TM + i;
        if (gm >= M) continue;
#pragma unroll
        for (int j=0;j<TN;j++){
            int gn = col0 + tx*TN + j;
            if (gn >= N) continue;
            float v = acc[i][j] * alpha;
            if (EPI & EPI_MASK){ if (mrow[gn] < 0.5f) v = -FLT_MAX; }
            if (EPI & EPI_BIAS) v += bias[gn];
            if (EPI & EPI_GELU) v = 0.5f * v * (1.f + erff(v * 0.7071067811865476f));
            if (EPI & EPI_RES)  v += Rb[(long)gm*ldc + gn];
            Cb[(long)gm*ldc + gn] = v;
        }
    }
}

// ---------------- fourier encoding (batch-invariant): enc(n, 387) + encss ----------------
__global__ void sip_build_enc()
{
    int n = blockIdx.x;                  // voxel index
    int hy = n / (GW*T_), wx = (n / T_) % GW, tt = n % T_;
    float pos[3] = {2.f*hy/GH - 1.f, 2.f*wx/GW - 1.f, 2.f*tt/T_ - 1.f};
    int tid = threadIdx.x;               // 128
    __shared__ float sh[4];
    float ss = 0.f;
    for (int e = tid; e < EC; e += 128){
        int c = e / 129, r = e % 129;
        float x = pos[c], v;
        if (r < 64)        v = sinf(x * exp2f((float)(-r)));
        else if (r < 128)  v = cosf(x * exp2f((float)(64 - r)));
        else               v = x;
        g_enc[(long)n*EC + e] = v;
        ss += v*v;
    }
    for (int o=16;o>0;o>>=1) ss += __shfl_xor_sync(0xffffffffu, ss, o);
    if ((tid & 31) == 0) sh[tid>>5] = ss;
    __syncthreads();
    if (tid == 0) g_encss[n] = sh[0]+sh[1]+sh[2]+sh[3];
}

// ---------------- vals(b,n,48), invn, mask ----------------
__global__ void sip_build_vals(const float* __restrict__ input)
{
    int vox = blockIdx.x;                // b*NVOX + n
    int b = vox / NVOX, n = vox % NVOX;
    int hy = n / (GW*T_), wx = (n / T_) % GW, tt = n % T_;
    int tid = threadIdx.x;               // 64
    __shared__ float ssh[2], msh[2];
    float val = 0.f;
    if (tid < VC){
        int py = tid/12, px = (tid/3)%4, c = tid%3;
        val = input[(((long)tt*B_ + b)*3 + c)*16384 + (hy*4+py)*128 + (wx*4+px)];
        g_vals[(long)vox*VC + tid] = val;
    }
    float ss = val*val;
    float mx = (tid < VC) ? val : -FLT_MAX;
    for (int o=16;o>0;o>>=1){
        ss += __shfl_xor_sync(0xffffffffu, ss, o);
        mx = fmaxf(mx, __shfl_xor_sync(0xffffffffu, mx, o));
    }
    if ((tid & 31) == 0){ ssh[tid>>5] = ss; msh[tid>>5] = mx; }
    __syncthreads();
    if (tid == 0){
        float tot = ssh[0] + ssh[1] + g_encss[n];
        g_invn[vox] = 1.f / fmaxf(sqrtf(tot), 1e-5f);
        float m = fmaxf(msh[0], msh[1]);
        g_mask[vox] = (fabsf(m) > 0.3f) ? 1.f : 0.f;
    }
}

// ---------------- row L2-norm with scalar gain ----------------
__global__ void sip_rownorm(const float* __restrict__ in, float* __restrict__ out,
                            int cols, const float* __restrict__ gptr)
{
    long row = blockIdx.x;
    const float* p = in + row * cols;
    float* q = out + row * cols;
    __shared__ float sh[8];
    int tid = threadIdx.x;
    float s = 0.f;
    for (int j = tid; j < cols; j += blockDim.x){ float v = p[j]; s += v*v; }
    for (int o=16;o>0;o>>=1) s += __shfl_xor_sync(0xffffffffu, s, o);
    if ((tid & 31) == 0) sh[tid>>5] = s;
    __syncthreads();
    float tot = 0.f;
    int nw = blockDim.x >> 5;
    for (int w=0; w<nw; w++) tot += sh[w];
    float sc = gptr[0] / fmaxf(sqrtf(tot), 1e-5f);
    for (int j = tid; j < cols; j += blockDim.x) q[j] = p[j] * sc;
}

// ---------------- softmax over rows (in place) ----------------
__global__ void sip_softmax(float* __restrict__ S, int cols)
{
    long row = blockIdx.x;
    float* p = S + row * (long)cols;
    __shared__ float sh[8];
    int tid = threadIdx.x;
    int nw = blockDim.x >> 5;
    float m = -FLT_MAX;
    for (int j = tid; j < cols; j += blockDim.x) m = fmaxf(m, p[j]);
    for (int o=16;o>0;o>>=1) m = fmaxf(m, __shfl_xor_sync(0xffffffffu, m, o));
    if ((tid & 31) == 0) sh[tid>>5] = m;
    __syncthreads();
    float mm = sh[0];
    for (int w=1; w<nw; w++) mm = fmaxf(mm, sh[w]);
    __syncthreads();
    float s = 0.f;
    for (int j = tid; j < cols; j += blockDim.x){
        float e = __expf(p[j] - mm);
        p[j] = e; s += e;
    }
    for (int o=16;o>0;o>>=1) s += __shfl_xor_sync(0xffffffffu, s, o);
    if ((tid & 31) == 0) sh[tid>>5] = s;
    __syncthreads();
    float tot = 0.f;
    for (int w=0; w<nw; w++) tot += sh[w];
    float inv = 1.f / tot;
    for (int j = tid; j < cols; j += blockDim.x) p[j] *= inv;
}

// ---------------- AV partial reduce + head merge: partials -> AO (b, 128, 600) ----------------
__global__ void sip_reduce_av(int nsplit)
{
    long total = (long)B_ * NL * IN_;
    long idx = (long)blockIdx.x * blockDim.x + threadIdx.x;
    if (idx >= total) return;
    int b = (int)(idx / (NL*IN_));
    int r = (int)(idx % (NL*IN_));
    int i = r / IN_, c = r % IN_;
    int h = c / DH, dd = c % DH;
    long base = ((long)(b*HH + h) * nsplit) * (NL*DH) + (long)i*DH + dd;
    float s = 0.f;
    for (int sp = 0; sp < nsplit; sp++) s += g_AVp[base + (long)sp*(NL*DH)];
    g_AO[idx] = s;
}

__global__ void sip_init_lat(const float* __restrict__ latents, const float* __restrict__ pos)
{
    long idx = (long)blockIdx.x * blockDim.x + threadIdx.x;
    if (idx >= (long)B_*NL*LD) return;
    int r = (int)(idx % (NL*LD));
    g_lat[idx] = latents[r] + pos[r];
}

__global__ void sip_permute_out(float* __restrict__ out)
{
    long idx = (long)blockIdx.x * blockDim.x + threadIdx.x;
    if (idx >= (long)T_*B_*16*OC) return;
    int o = (int)(idx % OC);
    long r = idx / OC;
    int nn = (int)(r % 16); r /= 16;
    int b = (int)(r % B_);
    int tt = (int)(r / B_);
    out[idx] = g_logits[((long)b*NL + nn*T_ + tt)*OC + o];
}

// ---------------- host ----------------
static inline int cdiv(int a, int b){ return (a + b - 1) / b; }

extern "C" void kernel_launch(void* const* d_in, const int* in_sizes, int n_in,
                              void* d_out, int out_size)
{
    const float* input    = (const float*)d_in[0];
    const float* latents  = (const float*)d_in[1];
    const float* pos_emb  = (const float*)d_in[2];
    const float* ca_g     = (const float*)d_in[3];
    const float* ca_ctx_g = (const float*)d_in[4];
    const float* ca_q     = (const float*)d_in[5];
    const float* ca_kv    = (const float*)d_in[6];
    const float* ca_ow    = (const float*)d_in[7];
    const float* ca_ob    = (const float*)d_in[8];
    const float* cf_g     = (const float*)d_in[9];
    const float* cf_w1    = (const float*)d_in[10];
    const float* cf_b1    = (const float*)d_in[11];
    const float* cf_w2    = (const float*)d_in[12];
    const float* cf_b2    = (const float*)d_in[13];
    const float* la_g     = (const float*)d_in[14];
    const float* la_q     = (const float*)d_in[15];
    const float* la_kv    = (const float*)d_in[16];
    const float* la_ow    = (const float*)d_in[17];
    const float* la_ob    = (const float*)d_in[18];
    const float* lf_g     = (const float*)d_in[19];
    const float* lf_w1    = (const float*)d_in[20];
    const float* lf_b1    = (const float*)d_in[21];
    const float* lf_w2    = (const float*)d_in[22];
    const float* lf_b2    = (const float*)d_in[23];
    const float* logits_w = (const float*)d_in[24];
    const float* logits_b = (const float*)d_in[25];
    float* out = (float*)d_out;

    float *p_vals,*p_enc,*p_invn,*p_mask,*p_EP,*p_lat,*p_xn,*p_Qh,*p_Kh,*p_Vh,*p_S,*p_AVp,*p_AO,*p_hid,*p_logits;
#define SYM(p, s) do{ void* _t=nullptr; cudaGetSymbolAddress(&_t, s); p=(float*)_t; }while(0)
    SYM(p_vals, g_vals); SYM(p_enc, g_enc); SYM(p_invn, g_invn); SYM(p_mask, g_mask);
    SYM(p_EP, g_EP); SYM(p_lat, g_lat); SYM(p_xn, g_xn);
    SYM(p_Qh, g_Qh); SYM(p_Kh, g_Kh); SYM(p_Vh, g_Vh);
    SYM(p_S, g_S); SYM(p_AVp, g_AVp); SYM(p_AO, g_AO); SYM(p_hid, g_hid); SYM(p_logits, g_logits);
#undef SYM

    const int M0 = B_*NL;  // 512
    const long EPL = (long)NVOX * 2 * IN_;  // per-layer EP stride

    // -------- preamble (layer-invariant) --------
    sip_build_enc<<<NVOX, 128>>>();
    sip_build_vals<<<B_*NVOX, 64>>>(input);
    sip_init_lat<<<cdiv(B_*NL*LD,256), 256>>>(latents, pos_emb);
    // EP[d] = enc @ ca_kv[d][48:435, :]   (batched over d)
    sip_gemm<128,128,8,8,8,false,0><<<dim3(cdiv(2*IN_,128),cdiv(NVOX,128),DEPTH),256>>>(
        NVOX, 2*IN_, EC, p_enc, EC, 0, ca_kv + (long)VC*2*IN_, 2*IN_, (long)ID2*2*IN_,
        p_EP, 2*IN_, EPL, nullptr, nullptr, nullptr, 1.f, nullptr, 1, 0, 1,
        nullptr, nullptr, nullptr, nullptr, 0);

    for (int d = 0; d < DEPTH; d++){
        // ===== cross attention =====
        sip_rownorm<<<M0, 256>>>(p_lat, p_xn, LD, ca_g + d);
        // Q = xn @ ca_q[d] * ATT_SCALE -> Qh scatter
        sip_gemm<64,64,16,4,4,false,EPI_Q><<<dim3(cdiv(IN_,64),cdiv(M0,64),1),256>>>(
            M0, IN_, LD, p_xn, LD, 0, ca_q + (long)d*LD*IN_, IN_, 0,
            nullptr, 0, 0, nullptr, nullptr, nullptr, ATT_SCALE, nullptr, 1, 0, 1,
            nullptr, nullptr, p_Qh, nullptr, 0);
        // KV = (vals @ Wv + EP[d]) * invn * g -> Kh/Vh scatter
        sip_gemm<128,128,8,8,8,false,EPI_KV><<<dim3(cdiv(2*IN_,128),cdiv(B_*NVOX,128),1),256>>>(
            B_*NVOX, 2*IN_, VC, p_vals, VC, 0, ca_kv + (long)d*ID2*2*IN_, 2*IN_, 0,
            nullptr, 0, 0, nullptr, nullptr, ca_ctx_g + d, 1.f, nullptr, 1, 0, 1,
            p_EP + (long)d*EPL, p_invn, p_Kh, p_Vh, NVOX);
        // scores = Qh @ Kh^T (scale pre-folded), masked
        sip_gemm<128,128,8,8,8,true,EPI_MASK><<<dim3(cdiv(NVOX,128),1,B_*HH),256>>>(
            NL, NVOX, DH, p_Qh, DH, (long)NL*DH, p_Kh, DH, (long)NVOX*DH,
            p_S, NVOX, (long)NL*NVOX, nullptr, nullptr, nullptr, 1.f,
            p_mask, HH, NVOX, 1, nullptr, nullptr, nullptr, nullptr, 0);
        sip_softmax<<<B_*HH*NL, 256>>>(p_S, NVOX);
        // AV split-K
        sip_gemm<128,128,8,8,8,false,0><<<dim3(1,1,B_*HH*NSPL),256>>>(
            NL, DH, NVOX, p_S, NVOX, (long)NL*NVOX, p_Vh, DH, (long)NVOX*DH,
            p_AVp, DH, 0, nullptr, nullptr, nullptr, 1.f, nullptr, 1, 0, NSPL,
            nullptr, nullptr, nullptr, nullptr, 0);
        sip_reduce_av<<<cdiv(B_*NL*IN_,256), 256>>>(NSPL);
        sip_gemm<64,64,16,4,4,false,EPI_BIAS|EPI_RES><<<dim3(cdiv(LD,64),cdiv(M0,64),1),256>>>(
            M0, LD, IN_, p_AO, IN_, 0, ca_ow + (long)d*IN_*LD, LD, 0,
            p_lat, LD, 0, ca_ob + (long)d*LD, p_lat, nullptr, 1.f, nullptr, 1, 0, 1,
            nullptr, nullptr, nullptr, nullptr, 0);

        // ===== feed-forward (cross) =====
        sip_rownorm<<<M0, 256>>>(p_lat, p_xn, LD, cf_g + d);
        sip_gemm<64,64,16,4,4,false,EPI_BIAS|EPI_GELU><<<dim3(cdiv(FF,64),cdiv(M0,64),1),256>>>(
            M0, FF, LD, p_xn, LD, 0, cf_w1 + (long)d*LD*FF, FF, 0,
            p_hid, FF, 0, cf_b1 + (long)d*FF, nullptr, nullptr, 1.f, nullptr, 1, 0, 1,
            nullptr, nullptr, nullptr, nullptr, 0);
        sip_gemm<64,64,16,4,4,false,EPI_BIAS|EPI_RES><<<dim3(cdiv(LD,64),cdiv(M0,64),1),256>>>(
            M0, LD, FF, p_hid, FF, 0, cf_w2 + (long)d*FF*LD, LD, 0,
            p_lat, LD, 0, cf_b2 + (long)d*LD, p_lat, nullptr, 1.f, nullptr, 1, 0, 1,
            nullptr, nullptr, nullptr, nullptr, 0);

        // ===== latent self-attention =====
        sip_rownorm<<<M0, 256>>>(p_lat, p_xn, LD, la_g + d);
        sip_gemm<64,64,16,4,4,false,EPI_Q><<<dim3(cdiv(IN_,64),cdiv(M0,64),1),256>>>(
            M0, IN_, LD, p_xn, LD, 0, la_q + (long)d*LD*IN_, IN_, 0,
            nullptr, 0, 0, nullptr, nullptr, nullptr, ATT_SCALE, nullptr, 1, 0, 1,
            nullptr, nullptr, p_Qh, nullptr, 0);
        sip_gemm<64,64,16,4,4,false,EPI_KV><<<dim3(cdiv(2*IN_,64),cdiv(M0,64),1),256>>>(
            M0, 2*IN_, LD, p_xn, LD, 0, la_kv + (long)d*LD*2*IN_, 2*IN_, 0,
            nullptr, 0, 0, nullptr, nullptr, nullptr, 1.f, nullptr, 1, 0, 1,
            nullptr, nullptr, p_Kh, p_Vh, NL);
        sip_gemm<64,64,16,4,4,true,0><<<dim3(cdiv(NL,64),cdiv(NL,64),B_*HH),256>>>(
            NL, NL, DH, p_Qh, DH, (long)NL*DH, p_Kh, DH, (long)NL*DH,
            p_S, NL, (long)NL*NL, nullptr, nullptr, nullptr, 1.f, nullptr, 1, 0, 1,
            nullptr, nullptr, nullptr, nullptr, 0);
        sip_softmax<<<B_*HH*NL, 128>>>(p_S, NL);
        sip_gemm<64,64,16,4,4,false,0><<<dim3(cdiv(DH,64),cdiv(NL,64),B_*HH),256>>>(
            NL, DH, NL, p_S, NL, (long)NL*NL, p_Vh, DH, (long)NL*DH,
            p_AVp, DH, (long)NL*DH, nullptr, nullptr, nullptr, 1.f, nullptr, 1, 0, 1,
            nullptr, nullptr, nullptr, nullptr, 0);
        sip_reduce_av<<<cdiv(B_*NL*IN_,256), 256>>>(1);
        sip_gemm<64,64,16,4,4,false,EPI_BIAS|EPI_RES><<<dim3(cdiv(LD,64),cdiv(M0,64),1),256>>>(
            M0, LD, IN_, p_AO, IN_, 0, la_ow + (long)d*IN_*LD, LD, 0,
            p_lat, LD, 0, la_ob + (long)d*LD, p_lat, nullptr, 1.f, nullptr, 1, 0, 1,
            nullptr, nullptr, nullptr, nullptr, 0);

        // ===== feed-forward (latent) =====
        sip_rownorm<<<M0, 256>>>(p_lat, p_xn, LD, lf_g + d);
        sip_gemm<64,64,16,4,4,false,EPI_BIAS|EPI_GELU><<<dim3(cdiv(FF,64),cdiv(M0,64),1),256>>>(
            M0, FF, LD, p_xn, LD, 0, lf_w1 + (long)d*LD*FF, FF, 0,
            p_hid, FF, 0, lf_b1 + (long)d*FF, nullptr, nullptr, 1.f, nullptr, 1, 0, 1,
            nullptr, nullptr, nullptr, nullptr, 0);
        sip_gemm<64,64,16,4,4,false,EPI_BIAS|EPI_RES><<<dim3(cdiv(LD,64),cdiv(M0,64),1),256>>>(
            M0, LD, FF, p_hid, FF, 0, lf_w2 + (long)d*FF*LD, LD, 0,
            p_lat, LD, 0, lf_b2 + (long)d*LD, p_lat, nullptr, 1.f, nullptr, 1, 0, 1,
            nullptr, nullptr, nullptr, nullptr, 0);
    }

    // ===== logits + output permute =====
    sip_gemm<64,64,16,4,4,false,EPI_BIAS><<<dim3(cdiv(OC,64),cdiv(M0,64),1),256>>>(
        M0, OC, LD, p_lat, LD, 0, logits_w, OC, 0,
        p_logits, OC, 0, logits_b, nullptr, nullptr, 1.f, nullptr, 1, 0, 1,
        nullptr, nullptr, nullptr, nullptr, 0);
    sip_permute_out<<<cdiv(T_*B_*16*OC,256), 256>>>(out);
}

// round 3
// speedup vs baseline: 1.9094x; 1.2707x over previous
#include <cuda_runtime.h>
#include <math.h>
#include <float.h>

// ---------------- problem constants ----------------
constexpr int B_   = 4;
constexpr int T_   = 8;
constexpr int HH   = 8;
constexpr int DH   = 75;
constexpr int NL   = 128;
constexpr int LD   = 512;
constexpr int ID2  = 435;
constexpr int VC   = 48;     // value channels (patch p*p*c)
constexpr int IN_  = 600;
constexpr int FF   = 2048;
constexpr int OC   = 64;
constexpr int DEPTH= 5;
constexpr int GH   = 32, GW = 32;
constexpr int NVOX = GH*GW*T_;           // 8192
constexpr int NSPL = 16;                 // split-K for cross AV
constexpr int NKV  = 2*IN_;              // 1200
constexpr float ATT_SCALE = 0.11547005383792515f;

// ---------------- scratch ----------------
__device__ float g_vals [(size_t)B_*NVOX*VC];
__device__ float g_encS [(size_t)96*129];     // separable fourier features
__device__ float g_ssS  [(size_t)96];         // per-row sum of squares
__device__ float g_EPT  [(size_t)DEPTH*96*NKV]; // factored enc@We tables
__device__ float g_invn [(size_t)B_*NVOX];
__device__ float g_mask [(size_t)B_*NVOX];
__device__ float g_linv [(size_t)B_*HH*NL];   // softmax 1/sum
__device__ float g_lat  [(size_t)B_*NL*LD];
__device__ float g_xn   [(size_t)B_*NL*LD];
__device__ float g_Qh   [(size_t)B_*HH*NL*DH];
__device__ float g_Kh   [(size_t)B_*HH*NVOX*DH];
__device__ float g_Vh   [(size_t)B_*HH*NVOX*DH];
__device__ float g_S    [(size_t)B_*HH*NL*NVOX];
__device__ float g_AVp  [(size_t)NSPL*B_*HH*NL*DH];
__device__ float g_AO   [(size_t)B_*NL*IN_];
__device__ float g_hid  [(size_t)B_*NL*FF];
__device__ float g_logits[(size_t)B_*NL*OC];

// ---------------- generic batched GEMM w/ fused epilogues ----------------
#define EPI_BIAS 1
#define EPI_GELU 2
#define EPI_RES  4
#define EPI_MASK 8
#define EPI_KV   16   // scatter to Kh/Vh (+ optional EP add + row scale)
#define EPI_Q    32   // scatter to Qh
#define EPI_KV3  64   // EP via 3 factored table lookups

template<int BM,int BN,int BK,int TM,int TN,bool TB,int EPI>
__global__ void __launch_bounds__((BM/TM)*(BN/TN))
sip_gemm(int M,int N,int K,
         const float* __restrict__ A,int lda,long sA,
         const float* __restrict__ Bp,int ldb,long sB,
         float* __restrict__ C,int ldc,long sC,
         const float* __restrict__ bias,
         const float* __restrict__ resid,
         const float* __restrict__ alphaPtr,float alphaC,
         const float* __restrict__ maskPtr,int maskBdiv,int maskStride,
         int nsplit,
         const float* __restrict__ ep,
         const float* __restrict__ rowscale,
         float* __restrict__ KhD, float* __restrict__ VhD, int kvSeq)
{
    constexpr int NT = (BM/TM)*(BN/TN);
    __shared__ float As[BK][BM];
    __shared__ float Bs[BK][BN];
    int tid = threadIdx.x;
    int z = blockIdx.z;
    int batch = z / nsplit, split = z - batch*nsplit;
    int kchunk = (K + nsplit - 1) / nsplit;
    int k0 = split * kchunk;
    int k1 = min(K, k0 + kchunk);
    const float* Ab = A + (long)batch * sA;
    const float* Bb = Bp + (long)batch * sB;
    int row0 = blockIdx.y * BM, col0 = blockIdx.x * BN;
    int tx = tid % (BN/TN), ty = tid / (BN/TN);
    float acc[TM][TN];
#pragma unroll
    for (int i=0;i<TM;i++)
#pragma unroll
        for (int j=0;j<TN;j++) acc[i][j]=0.f;

    constexpr int ALD = BM*BK/NT;
    constexpr int BLD = BN*BK/NT;
    for (int kt = k0; kt < k1; kt += BK) {
#pragma unroll
        for (int e=0;e<ALD;e++){
            int idx = tid*ALD + e;
            int m = idx / BK, k = idx % BK;
            int gm = row0 + m, gk = kt + k;
            As[k][m] = (gm < M && gk < k1) ? Ab[(long)gm*lda + gk] : 0.f;
        }
#pragma unroll
        for (int e=0;e<BLD;e++){
            int idx = tid*BLD + e;
            if (TB){
                int n = idx / BK, k = idx % BK;
                int gn = col0 + n, gk = kt + k;
                Bs[k][n] = (gn < N && gk < k1) ? Bb[(long)gn*ldb + gk] : 0.f;
            } else {
                int k = idx / BN, n = idx % BN;
                int gn = col0 + n, gk = kt + k;
                Bs[k][n] = (gn < N && gk < k1) ? Bb[(long)gk*ldb + gn] : 0.f;
            }
        }
        __syncthreads();
#pragma unroll
        for (int k=0;k<BK;k++){
            float af[TM], bf[TN];
#pragma unroll
            for (int i=0;i<TM;i++) af[i] = As[k][ty*TM+i];
#pragma unroll
            for (int j=0;j<TN;j++) bf[j] = Bs[k][tx*TN+j];
#pragma unroll
            for (int i=0;i<TM;i++)
#pragma unroll
                for (int j=0;j<TN;j++) acc[i][j] = fmaf(af[i], bf[j], acc[i][j]);
        }
        __syncthreads();
    }

    float alpha = alphaC;
    if (alphaPtr) alpha *= alphaPtr[0];

    if (EPI & (EPI_KV | EPI_Q)){
#pragma unroll
        for (int i=0;i<TM;i++){
            int gm = row0 + ty*TM + i;
            if (gm >= M) continue;
            float rs = 1.f;
            int bb, jj;
            if (EPI & EPI_KV){
                bb = gm / kvSeq; jj = gm - bb*kvSeq;
                if (rowscale) rs = rowscale[gm];
            } else {
                bb = gm / NL; jj = gm - bb*NL;
            }
#pragma unroll
            for (int j=0;j<TN;j++){
                int gn = col0 + tx*TN + j;
                if (gn >= N) continue;
                float v = acc[i][j];
                if (EPI & EPI_KV){
                    if (EPI & EPI_KV3){
                        int y = jj>>8, xx = (jj>>3)&31, t = jj&7;
                        v += ep[(long)y*NKV + gn]
                           + ep[(long)(32+xx)*NKV + gn]
                           + ep[(long)(64+t)*NKV + gn];
                    } else if (ep){
                        v += ep[(long)jj*N + gn];
                    }
                    v *= alpha * rs;
                    int c = gn;
                    if (c < IN_){
                        int h = c / DH, dd = c - h*DH;
                        KhD[(((long)(bb*HH + h))*kvSeq + jj)*DH + dd] = v;
                    } else {
                        c -= IN_;
                        int h = c / DH, dd = c - h*DH;
                        VhD[(((long)(bb*HH + h))*kvSeq + jj)*DH + dd] = v;
                    }
                } else {
                    v *= alpha;
                    int h = gn / DH, dd = gn - h*DH;
                    KhD[(((long)(bb*HH + h))*NL + jj)*DH + dd] = v;
                }
            }
        }
        return;
    }

    long coff = (nsplit > 1) ? (long)z * M * ldc : (long)batch * sC;
    float* Cb = C + coff;
    const float* Rb = (EPI & EPI_RES) ? resid + (long)batch * sC : nullptr;
    const float* mrow = (EPI & EPI_MASK) ? maskPtr + (long)(batch / maskBdiv) * maskStride : nullptr;
#pragma unroll
    for (int i=0;i<TM;i++){
        int gm = row0 + ty*TM + i;
        if (gm >= M) continue;
#pragma unroll
        for (int j=0;j<TN;j++){
            int gn = col0 + tx*TN + j;
            if (gn >= N) continue;
            float v = acc[i][j] * alpha;
            if (EPI & EPI_MASK){ if (mrow[gn] < 0.5f) v = -FLT_MAX; }
            if (EPI & EPI_BIAS) v += bias[gn];
            if (EPI & EPI_GELU) v = 0.5f * v * (1.f + erff(v * 0.7071067811865476f));
            if (EPI & EPI_RES)  v += Rb[(long)gm*ldc + gn];
            Cb[(long)gm*ldc + gn] = v;
        }
    }
}

// ---------------- separable fourier features: encS[96][129] + ssS ----------------
__global__ void sip_build_encsmall()
{
    int ri = blockIdx.x;                 // 0..95: [y0..y31, x0..x31, t0..t7,(pad)]
    int a = ri >> 5, v = ri & 31;
    float dim = (a == 2) ? 8.f : 32.f;
    float x = 2.f*v/dim - 1.f;
    int tid = threadIdx.x;               // 160
    __shared__ float sh[5];
    float val = 0.f;
    if (tid < 129){
        int r = tid;
        if (r < 64)        val = sinf(x * exp2f((float)(-r)));
        else if (r < 128)  val = cosf(x * exp2f((float)(64 - r)));
        else               val = x;
        g_encS[ri*129 + tid] = val;
    }
    float ss = val*val;
    for (int o=16;o>0;o>>=1) ss += __shfl_xor_sync(0xffffffffu, ss, o);
    if ((tid & 31) == 0) sh[tid>>5] = ss;
    __syncthreads();
    if (tid == 0) g_ssS[ri] = sh[0]+sh[1]+sh[2]+sh[3]+sh[4];
}

// ---------------- tiny factored EP tables: EPT[d][96][1200] ----------------
__global__ void sip_ep_small(const float* __restrict__ kvw)
{
    int c = blockIdx.x*128 + threadIdx.x;
    if (c >= NKV) return;
    int ri = blockIdx.y, d = blockIdx.z;
    int a = ri >> 5;
    const float* W = kvw + (long)d*ID2*NKV + (long)(VC + a*129)*NKV + c;
    const float* E = g_encS + ri*129;
    float acc = 0.f;
#pragma unroll 4
    for (int r = 0; r < 129; r++) acc += E[r] * W[(long)r*NKV];
    g_EPT[((long)d*96 + ri)*NKV + c] = acc;
}

// ---------------- vals(b,n,48), invn, mask ----------------
__global__ void sip_build_vals(const float* __restrict__ input)
{
    int vox = blockIdx.x;                // b*NVOX + n
    int b = vox / NVOX, n = vox % NVOX;
    int hy = n / (GW*T_), wx = (n / T_) % GW, tt = n % T_;
    int tid = threadIdx.x;               // 64
    __shared__ float ssh[2], msh[2];
    float val = 0.f;
    if (tid < VC){
        int py = tid/12, px = (tid/3)%4, c = tid%3;
        val = input[(((long)tt*B_ + b)*3 + c)*16384 + (hy*4+py)*128 + (wx*4+px)];
        g_vals[(long)vox*VC + tid] = val;
    }
    float ss = val*val;
    float mx = (tid < VC) ? val : -FLT_MAX;
    for (int o=16;o>0;o>>=1){
        ss += __shfl_xor_sync(0xffffffffu, ss, o);
        mx = fmaxf(mx, __shfl_xor_sync(0xffffffffu, mx, o));
    }
    if ((tid & 31) == 0){ ssh[tid>>5] = ss; msh[tid>>5] = mx; }
    __syncthreads();
    if (tid == 0){
        float tot = ssh[0] + ssh[1] + g_ssS[hy] + g_ssS[32+wx] + g_ssS[64+tt];
        g_invn[vox] = 1.f / fmaxf(sqrtf(tot), 1e-5f);
        float m = fmaxf(msh[0], msh[1]);
        g_mask[vox] = (fabsf(m) > 0.3f) ? 1.f : 0.f;
    }
}

// ---------------- row L2-norm with scalar gain ----------------
__global__ void sip_rownorm(const float* __restrict__ in, float* __restrict__ out,
                            int cols, const float* __restrict__ gptr)
{
    long row = blockIdx.x;
    const float* p = in + row * cols;
    float* q = out + row * cols;
    __shared__ float sh[8];
    int tid = threadIdx.x;
    float s = 0.f;
    for (int j = tid; j < cols; j += blockDim.x){ float v = p[j]; s += v*v; }
    for (int o=16;o>0;o>>=1) s += __shfl_xor_sync(0xffffffffu, s, o);
    if ((tid & 31) == 0) sh[tid>>5] = s;
    __syncthreads();
    float tot = 0.f;
    int nw = blockDim.x >> 5;
    for (int w=0; w<nw; w++) tot += sh[w];
    float sc = gptr[0] / fmaxf(sqrtf(tot), 1e-5f);
    for (int j = tid; j < cols; j += blockDim.x) q[j] = p[j] * sc;
}

// ---------------- softmax; if linv!=null skip normalize and record 1/sum ----------------
__global__ void sip_softmax(float* __restrict__ S, int cols, float* __restrict__ linv)
{
    long row = blockIdx.x;
    float* p = S + row * (long)cols;
    __shared__ float sh[8];
    int tid = threadIdx.x;
    int nw = blockDim.x >> 5;
    float m = -FLT_MAX;
    for (int j = tid; j < cols; j += blockDim.x) m = fmaxf(m, p[j]);
    for (int o=16;o>0;o>>=1) m = fmaxf(m, __shfl_xor_sync(0xffffffffu, m, o));
    if ((tid & 31) == 0) sh[tid>>5] = m;
    __syncthreads();
    float mm = sh[0];
    for (int w=1; w<nw; w++) mm = fmaxf(mm, sh[w]);
    __syncthreads();
    float s = 0.f;
    for (int j = tid; j < cols; j += blockDim.x){
        float e = __expf(p[j] - mm);
        p[j] = e; s += e;
    }
    for (int o=16;o>0;o>>=1) s += __shfl_xor_sync(0xffffffffu, s, o);
    if ((tid & 31) == 0) sh[tid>>5] = s;
    __syncthreads();
    float tot = 0.f;
    for (int w=0; w<nw; w++) tot += sh[w];
    float inv = 1.f / tot;
    if (linv){
        if (tid == 0) linv[row] = inv;
    } else {
        for (int j = tid; j < cols; j += blockDim.x) p[j] *= inv;
    }
}

// ---------------- AV partial reduce + head merge (+ optional softmax scale) ----------------
__global__ void sip_reduce_av(int nsplit, const float* __restrict__ linv)
{
    long total = (long)B_ * NL * IN_;
    long idx = (long)blockIdx.x * blockDim.x + threadIdx.x;
    if (idx >= total) return;
    int b = (int)(idx / (NL*IN_));
    int r = (int)(idx % (NL*IN_));
    int i = r / IN_, c = r % IN_;
    int h = c / DH, dd = c % DH;
    long base = ((long)(b*HH + h) * nsplit) * (NL*DH) + (long)i*DH + dd;
    float s = 0.f;
    for (int sp = 0; sp < nsplit; sp++) s += g_AVp[base + (long)sp*(NL*DH)];
    if (linv) s *= linv[(long)(b*HH + h)*NL + i];
    g_AO[idx] = s;
}

__global__ void sip_init_lat(const float* __restrict__ latents, const float* __restrict__ pos)
{
    long idx = (long)blockIdx.x * blockDim.x + threadIdx.x;
    if (idx >= (long)B_*NL*LD) return;
    int r = (int)(idx % (NL*LD));
    g_lat[idx] = latents[r] + pos[r];
}

__global__ void sip_permute_out(float* __restrict__ out)
{
    long idx = (long)blockIdx.x * blockDim.x + threadIdx.x;
    if (idx >= (long)T_*B_*16*OC) return;
    int o = (int)(idx % OC);
    long r = idx / OC;
    int nn = (int)(r % 16); r /= 16;
    int b = (int)(r % B_);
    int tt = (int)(r / B_);
    out[idx] = g_logits[((long)b*NL + nn*T_ + tt)*OC + o];
}

// ---------------- host ----------------
static inline int cdiv(int a, int b){ return (a + b - 1) / b; }

extern "C" void kernel_launch(void* const* d_in, const int* in_sizes, int n_in,
                              void* d_out, int out_size)
{
    const float* input    = (const float*)d_in[0];
    const float* latents  = (const float*)d_in[1];
    const float* pos_emb  = (const float*)d_in[2];
    const float* ca_g     = (const float*)d_in[3];
    const float* ca_ctx_g = (const float*)d_in[4];
    const float* ca_q     = (const float*)d_in[5];
    const float* ca_kv    = (const float*)d_in[6];
    const float* ca_ow    = (const float*)d_in[7];
    const float* ca_ob    = (const float*)d_in[8];
    const float* cf_g     = (const float*)d_in[9];
    const float* cf_w1    = (const float*)d_in[10];
    const float* cf_b1    = (const float*)d_in[11];
    const float* cf_w2    = (const float*)d_in[12];
    const float* cf_b2    = (const float*)d_in[13];
    const float* la_g     = (const float*)d_in[14];
    const float* la_q     = (const float*)d_in[15];
    const float* la_kv    = (const float*)d_in[16];
    const float* la_ow    = (const float*)d_in[17];
    const float* la_ob    = (const float*)d_in[18];
    const float* lf_g     = (const float*)d_in[19];
    const float* lf_w1    = (const float*)d_in[20];
    const float* lf_b1    = (const float*)d_in[21];
    const float* lf_w2    = (const float*)d_in[22];
    const float* lf_b2    = (const float*)d_in[23];
    const float* logits_w = (const float*)d_in[24];
    const float* logits_b = (const float*)d_in[25];
    float* out = (float*)d_out;

    float *p_vals,*p_invn,*p_mask,*p_EPT,*p_linv,*p_lat,*p_xn,*p_Qh,*p_Kh,*p_Vh,*p_S,*p_AVp,*p_AO,*p_hid,*p_logits;
#define SYM(p, s) do{ void* _t=nullptr; cudaGetSymbolAddress(&_t, s); p=(float*)_t; }while(0)
    SYM(p_vals, g_vals); SYM(p_invn, g_invn); SYM(p_mask, g_mask);
    SYM(p_EPT, g_EPT); SYM(p_linv, g_linv); SYM(p_lat, g_lat); SYM(p_xn, g_xn);
    SYM(p_Qh, g_Qh); SYM(p_Kh, g_Kh); SYM(p_Vh, g_Vh);
    SYM(p_S, g_S); SYM(p_AVp, g_AVp); SYM(p_AO, g_AO); SYM(p_hid, g_hid); SYM(p_logits, g_logits);
#undef SYM

    const int M0 = B_*NL;  // 512

    // -------- preamble (layer-invariant) --------
    sip_build_encsmall<<<96, 160>>>();
    sip_ep_small<<<dim3(cdiv(NKV,128), 96, DEPTH), 128>>>(ca_kv);
    sip_build_vals<<<B_*NVOX, 64>>>(input);
    sip_init_lat<<<cdiv(B_*NL*LD,256), 256>>>(latents, pos_emb);

    for (int d = 0; d < DEPTH; d++){
        // ===== cross attention =====
        sip_rownorm<<<M0, 256>>>(p_lat, p_xn, LD, ca_g + d);
        // Q = xn @ ca_q[d] * ATT_SCALE -> Qh scatter
        sip_gemm<64,64,16,4,4,false,EPI_Q><<<dim3(cdiv(IN_,64),cdiv(M0,64),1),256>>>(
            M0, IN_, LD, p_xn, LD, 0, ca_q + (long)d*LD*IN_, IN_, 0,
            nullptr, 0, 0, nullptr, nullptr, nullptr, ATT_SCALE, nullptr, 1, 0, 1,
            nullptr, nullptr, p_Qh, nullptr, 0);
        // KV = (vals @ Wv + EPy+EPx+EPt) * invn * g -> Kh/Vh scatter
        sip_gemm<128,128,8,8,8,false,EPI_KV|EPI_KV3><<<dim3(cdiv(NKV,128),cdiv(B_*NVOX,128),1),256>>>(
            B_*NVOX, NKV, VC, p_vals, VC, 0, ca_kv + (long)d*ID2*NKV, NKV, 0,
            nullptr, 0, 0, nullptr, nullptr, ca_ctx_g + d, 1.f, nullptr, 1, 0, 1,
            p_EPT + (long)d*96*NKV, p_invn, p_Kh, p_Vh, NVOX);
        // scores = Qh @ Kh^T (scale pre-folded), masked
        sip_gemm<128,128,8,8,8,true,EPI_MASK><<<dim3(cdiv(NVOX,128),1,B_*HH),256>>>(
            NL, NVOX, DH, p_Qh, DH, (long)NL*DH, p_Kh, DH, (long)NVOX*DH,
            p_S, NVOX, (long)NL*NVOX, nullptr, nullptr, nullptr, 1.f,
            p_mask, HH, NVOX, 1, nullptr, nullptr, nullptr, nullptr, 0);
        sip_softmax<<<B_*HH*NL, 256>>>(p_S, NVOX, p_linv);
        // AV split-K (unnormalized probs; 1/sum folded into reduce)
        sip_gemm<128,80,16,8,5,false,0><<<dim3(1,1,B_*HH*NSPL),256>>>(
            NL, DH, NVOX, p_S, NVOX, (long)NL*NVOX, p_Vh, DH, (long)NVOX*DH,
            p_AVp, DH, 0, nullptr, nullptr, nullptr, 1.f, nullptr, 1, 0, NSPL,
            nullptr, nullptr, nullptr, nullptr, 0);
        sip_reduce_av<<<cdiv(B_*NL*IN_,256), 256>>>(NSPL, p_linv);
        sip_gemm<64,64,16,4,4,false,EPI_BIAS|EPI_RES><<<dim3(cdiv(LD,64),cdiv(M0,64),1),256>>>(
            M0, LD, IN_, p_AO, IN_, 0, ca_ow + (long)d*IN_*LD, LD, 0,
            p_lat, LD, 0, ca_ob + (long)d*LD, p_lat, nullptr, 1.f, nullptr, 1, 0, 1,
            nullptr, nullptr, nullptr, nullptr, 0);

        // ===== feed-forward (cross) =====
        sip_rownorm<<<M0, 256>>>(p_lat, p_xn, LD, cf_g + d);
        sip_gemm<64,64,16,4,4,false,EPI_BIAS|EPI_GELU><<<dim3(cdiv(FF,64),cdiv(M0,64),1),256>>>(
            M0, FF, LD, p_xn, LD, 0, cf_w1 + (long)d*LD*FF, FF, 0,
            p_hid, FF, 0, cf_b1 + (long)d*FF, nullptr, nullptr, 1.f, nullptr, 1, 0, 1,
            nullptr, nullptr, nullptr, nullptr, 0);
        sip_gemm<64,64,16,4,4,false,EPI_BIAS|EPI_RES><<<dim3(cdiv(LD,64),cdiv(M0,64),1),256>>>(
            M0, LD, FF, p_hid, FF, 0, cf_w2 + (long)d*FF*LD, LD, 0,
            p_lat, LD, 0, cf_b2 + (long)d*LD, p_lat, nullptr, 1.f, nullptr, 1, 0, 1,
            nullptr, nullptr, nullptr, nullptr, 0);

        // ===== latent self-attention =====
        sip_rownorm<<<M0, 256>>>(p_lat, p_xn, LD, la_g + d);
        sip_gemm<64,64,16,4,4,false,EPI_Q><<<dim3(cdiv(IN_,64),cdiv(M0,64),1),256>>>(
            M0, IN_, LD, p_xn, LD, 0, la_q + (long)d*LD*IN_, IN_, 0,
            nullptr, 0, 0, nullptr, nullptr, nullptr, ATT_SCALE, nullptr, 1, 0, 1,
            nullptr, nullptr, p_Qh, nullptr, 0);
        sip_gemm<64,64,16,4,4,false,EPI_KV><<<dim3(cdiv(NKV,64),cdiv(M0,64),1),256>>>(
            M0, NKV, LD, p_xn, LD, 0, la_kv + (long)d*LD*NKV, NKV, 0,
            nullptr, 0, 0, nullptr, nullptr, nullptr, 1.f, nullptr, 1, 0, 1,
            nullptr, nullptr, p_Kh, p_Vh, NL);
        sip_gemm<64,64,16,4,4,true,0><<<dim3(cdiv(NL,64),cdiv(NL,64),B_*HH),256>>>(
            NL, NL, DH, p_Qh, DH, (long)NL*DH, p_Kh, DH, (long)NL*DH,
            p_S, NL, (long)NL*NL, nullptr, nullptr, nullptr, 1.f, nullptr, 1, 0, 1,
            nullptr, nullptr, nullptr, nullptr, 0);
        sip_softmax<<<B_*HH*NL, 128>>>(p_S, NL, nullptr);
        sip_gemm<128,80,16,8,5,false,0><<<dim3(1,1,B_*HH),256>>>(
            NL, DH, NL, p_S, NL, (long)NL*NL, p_Vh, DH, (long)NL*DH,
            p_AVp, DH, (long)NL*DH, nullptr, nullptr, nullptr, 1.f, nullptr, 1, 0, 1,
            nullptr, nullptr, nullptr, nullptr, 0);
        sip_reduce_av<<<cdiv(B_*NL*IN_,256), 256>>>(1, nullptr);
        sip_gemm<64,64,16,4,4,false,EPI_BIAS|EPI_RES><<<dim3(cdiv(LD,64),cdiv(M0,64),1),256>>>(
            M0, LD, IN_, p_AO, IN_, 0, la_ow + (long)d*IN_*LD, LD, 0,
            p_lat, LD, 0, la_ob + (long)d*LD, p_lat, nullptr, 1.f, nullptr, 1, 0, 1,
            nullptr, nullptr, nullptr, nullptr, 0);

        // ===== feed-forward (latent) =====
        sip_rownorm<<<M0, 256>>>(p_lat, p_xn, LD, lf_g + d);
        sip_gemm<64,64,16,4,4,false,EPI_BIAS|EPI_GELU><<<dim3(cdiv(FF,64),cdiv(M0,64),1),256>>>(
            M0, FF, LD, p_xn, LD, 0, lf_w1 + (long)d*LD*FF, FF, 0,
            p_hid, FF, 0, lf_b1 + (long)d*FF, nullptr, nullptr, 1.f, nullptr, 1, 0, 1,
            nullptr, nullptr, nullptr, nullptr, 0);
        sip_gemm<64,64,16,4,4,false,EPI_BIAS|EPI_RES><<<dim3(cdiv(LD,64),cdiv(M0,64),1),256>>>(
            M0, LD, FF, p_hid, FF, 0, lf_w2 + (long)d*FF*LD, LD, 0,
            p_lat, LD, 0, lf_b2 + (long)d*LD, p_lat, nullptr, 1.f, nullptr, 1, 0, 1,
            nullptr, nullptr, nullptr, nullptr, 0);
    }

    // ===== logits + output permute =====
    sip_gemm<64,64,16,4,4,false,EPI_BIAS><<<dim3(cdiv(OC,64),cdiv(M0,64),1),256>>>(
        M0, OC, LD, p_lat, LD, 0, logits_w, OC, 0,
        p_logits, OC, 0, logits_b, nullptr, nullptr, 1.f, nullptr, 1, 0, 1,
        nullptr, nullptr, nullptr, nullptr, 0);
    sip_permute_out<<<cdiv(T_*B_*16*OC,256), 256>>>(out);
}

// round 4
// speedup vs baseline: 2.1315x; 1.1163x over previous
#include <cuda_runtime.h>
#include <math.h>
#include <float.h>
#include <stdint.h>

// ---------------- problem constants ----------------
constexpr int B_   = 4;
constexpr int T_   = 8;
constexpr int HH   = 8;
constexpr int DH   = 75;
constexpr int NL   = 128;
constexpr int LD   = 512;
constexpr int ID2  = 435;
constexpr int VC   = 48;
constexpr int IN_  = 600;
constexpr int FF   = 2048;
constexpr int OC   = 64;
constexpr int DEPTH= 5;
constexpr int GH   = 32, GW = 32;
constexpr int NVOX = GH*GW*T_;           // 8192
constexpr int NSPL = 16;
constexpr int NKV  = 2*IN_;              // 1200
constexpr float ATT_SCALE = 0.11547005383792515f;

// ---------------- scratch ----------------
__device__ float g_vals [(size_t)B_*NVOX*VC];
__device__ float g_encS [(size_t)96*129];
__device__ float g_ssS  [(size_t)96];
__device__ float g_EPT  [(size_t)DEPTH*96*NKV];
__device__ float g_invn [(size_t)B_*NVOX];
__device__ float g_mask [(size_t)B_*NVOX];
__device__ float g_linv [(size_t)B_*HH*NL];
__device__ float g_lat  [(size_t)B_*NL*LD];
__device__ float g_xn   [(size_t)B_*NL*LD];
__device__ float g_Qh   [(size_t)B_*HH*NL*DH];
__device__ float g_Kh   [(size_t)B_*HH*NVOX*DH];
__device__ float g_Vh   [(size_t)B_*HH*NVOX*DH];
__device__ float g_S    [(size_t)B_*HH*NL*NVOX];
__device__ float g_AVp  [(size_t)NSPL*B_*HH*NL*DH];
__device__ float g_AO   [(size_t)B_*NL*IN_];
__device__ float g_hid  [(size_t)B_*NL*FF];
__device__ float g_logits[(size_t)B_*NL*OC];

// ---------------- tf32 helpers ----------------
__device__ __forceinline__ uint32_t f2tf32(float f){
    uint32_t r; asm("cvt.rna.tf32.f32 %0, %1;" : "=r"(r) : "f"(f)); return r;
}
__device__ __forceinline__ void mma_tf32(float c[4], const uint32_t a[4], const uint32_t b[2]){
    asm("mma.sync.aligned.m16n8k8.row.col.f32.tf32.tf32.f32 "
        "{%0,%1,%2,%3}, {%4,%5,%6,%7}, {%8,%9}, {%0,%1,%2,%3};"
        : "+f"(c[0]), "+f"(c[1]), "+f"(c[2]), "+f"(c[3])
        : "r"(a[0]), "r"(a[1]), "r"(a[2]), "r"(a[3]), "r"(b[0]), "r"(b[1]));
}

// ---------------- epilogue flags ----------------
#define EPI_BIAS 1
#define EPI_GELU 2
#define EPI_RES  4
#define EPI_MASK 8
#define EPI_KV   16
#define EPI_Q    32
#define EPI_KV3  64

// ---------------- tf32 tensor-core GEMM with fused epilogues ----------------
template<int BM,int BN,int BK,int WM,int WN,bool TB,int EPI>
__global__ void __launch_bounds__((BM/WM)*(BN/WN)*32)
sip_mma(int M,int N,int K,
        const float* __restrict__ A,int lda,long sA,
        const float* __restrict__ Bp,int ldb,long sB,
        float* __restrict__ C,int ldc,long sC,
        const float* __restrict__ bias,
        const float* __restrict__ resid,
        const float* __restrict__ alphaPtr,float alphaC,
        const float* __restrict__ maskPtr,int maskBdiv,int maskStride,
        int nsplit,
        const float* __restrict__ ep,
        const float* __restrict__ rowscale,
        float* __restrict__ KhD, float* __restrict__ VhD, int kvSeq)
{
    constexpr int NWARP = (BM/WM)*(BN/WN);
    constexpr int NT = NWARP*32;
    constexpr int LDA = BM + 4;
    constexpr int LDB = BN + 4;
    __shared__ uint32_t As[BK][LDA];
    __shared__ uint32_t Bs[BK][LDB];

    int tid = threadIdx.x;
    int z = blockIdx.z;
    int batch = z / nsplit, split = z - batch*nsplit;
    int kchunk = (K + nsplit - 1) / nsplit;
    int k0 = split * kchunk;
    int k1 = min(K, k0 + kchunk);
    const float* Ab = A + (long)batch * sA;
    const float* Bb = Bp + (long)batch * sB;
    int row0 = blockIdx.y * BM, col0 = blockIdx.x * BN;
    int wid = tid >> 5, lane = tid & 31;
    int g = lane >> 2, tig = lane & 3;
    int wm0 = (wid % (BM/WM)) * WM;
    int wn0 = (wid / (BM/WM)) * WN;
    constexpr int MT = WM/16, NTN = WN/8;

    float acc[MT][NTN][4];
#pragma unroll
    for (int i=0;i<MT;i++)
#pragma unroll
        for (int j=0;j<NTN;j++)
#pragma unroll
            for (int r=0;r<4;r++) acc[i][j][r] = 0.f;

    constexpr int AE = BM*BK/NT;
    constexpr int BE = BN*BK/NT;

    for (int kt = k0; kt < k1; kt += BK){
#pragma unroll
        for (int e=0;e<AE;e++){
            int idx = e*NT + tid;
            int m = idx / BK, k = idx % BK;
            int gm = row0 + m, gk = kt + k;
            float v = (gm < M && gk < k1) ? Ab[(long)gm*lda + gk] : 0.f;
            As[k][m] = f2tf32(v);
        }
#pragma unroll
        for (int e=0;e<BE;e++){
            int idx = e*NT + tid;
            if (TB){
                int n = idx / BK, k = idx % BK;
                int gn = col0 + n, gk = kt + k;
                float v = (gn < N && gk < k1) ? Bb[(long)gn*ldb + gk] : 0.f;
                Bs[k][n] = f2tf32(v);
            } else {
                int k = idx / BN, n = idx % BN;
                int gn = col0 + n, gk = kt + k;
                float v = (gn < N && gk < k1) ? Bb[(long)gk*ldb + gn] : 0.f;
                Bs[k][n] = f2tf32(v);
            }
        }
        __syncthreads();
#pragma unroll
        for (int ks=0; ks<BK/8; ks++){
            uint32_t af[MT][4], bf[NTN][2];
#pragma unroll
            for (int mt=0; mt<MT; mt++){
                int mb = wm0 + mt*16;
                af[mt][0] = As[ks*8 + tig    ][mb + g    ];
                af[mt][1] = As[ks*8 + tig    ][mb + g + 8];
                af[mt][2] = As[ks*8 + tig + 4][mb + g    ];
                af[mt][3] = As[ks*8 + tig + 4][mb + g + 8];
            }
#pragma unroll
            for (int nt=0; nt<NTN; nt++){
                int nb = wn0 + nt*8;
                bf[nt][0] = Bs[ks*8 + tig    ][nb + g];
                bf[nt][1] = Bs[ks*8 + tig + 4][nb + g];
            }
#pragma unroll
            for (int mt=0; mt<MT; mt++)
#pragma unroll
                for (int nt=0; nt<NTN; nt++)
                    mma_tf32(acc[mt][nt], af[mt], bf[nt]);
        }
        __syncthreads();
    }

    float alpha = alphaC;
    if (alphaPtr) alpha *= alphaPtr[0];

    if (EPI & (EPI_KV | EPI_Q)){
#pragma unroll
        for (int mt=0; mt<MT; mt++)
#pragma unroll
        for (int r2=0; r2<2; r2++){
            int gm = row0 + wm0 + mt*16 + g + r2*8;
            if (gm >= M) continue;
            float rs = 1.f;
            int bb, jj;
            if (EPI & EPI_KV){
                bb = gm / kvSeq; jj = gm - bb*kvSeq;
                if (rowscale) rs = rowscale[gm];
            } else {
                bb = gm / NL; jj = gm - bb*NL;
            }
#pragma unroll
            for (int nt=0; nt<NTN; nt++)
#pragma unroll
            for (int c2=0; c2<2; c2++){
                int gn = col0 + wn0 + nt*8 + tig*2 + c2;
                if (gn >= N) continue;
                float v = acc[mt][nt][r2*2 + c2];
                if (EPI & EPI_KV){
                    if (EPI & EPI_KV3){
                        int y = jj>>8, xx = (jj>>3)&31, t = jj&7;
                        v += ep[(long)y*NKV + gn]
                           + ep[(long)(32+xx)*NKV + gn]
                           + ep[(long)(64+t)*NKV + gn];
                    } else if (ep){
                        v += ep[(long)jj*N + gn];
                    }
                    v *= alpha * rs;
                    int c = gn;
                    if (c < IN_){
                        int h = c / DH, dd = c - h*DH;
                        KhD[(((long)(bb*HH + h))*kvSeq + jj)*DH + dd] = v;
                    } else {
                        c -= IN_;
                        int h = c / DH, dd = c - h*DH;
                        VhD[(((long)(bb*HH + h))*kvSeq + jj)*DH + dd] = v;
                    }
                } else {
                    v *= alpha;
                    int h = gn / DH, dd = gn - h*DH;
                    KhD[(((long)(bb*HH + h))*NL + jj)*DH + dd] = v;
                }
            }
        }
        return;
    }

    long coff = (nsplit > 1) ? (long)z * M * ldc : (long)batch * sC;
    float* Cb = C + coff;
    const float* Rb = (EPI & EPI_RES) ? resid + (long)batch * sC : nullptr;
    const float* mrow = (EPI & EPI_MASK) ? maskPtr + (long)(batch / maskBdiv) * maskStride : nullptr;
#pragma unroll
    for (int mt=0; mt<MT; mt++)
#pragma unroll
    for (int r2=0; r2<2; r2++){
        int gm = row0 + wm0 + mt*16 + g + r2*8;
        if (gm >= M) continue;
#pragma unroll
        for (int nt=0; nt<NTN; nt++)
#pragma unroll
        for (int c2=0; c2<2; c2++){
            int gn = col0 + wn0 + nt*8 + tig*2 + c2;
            if (gn >= N) continue;
            float v = acc[mt][nt][r2*2 + c2] * alpha;
            if (EPI & EPI_MASK){ if (mrow[gn] < 0.5f) v = -FLT_MAX; }
            if (EPI & EPI_BIAS) v += bias[gn];
            if (EPI & EPI_GELU) v = 0.5f * v * (1.f + erff(v * 0.7071067811865476f));
            if (EPI & EPI_RES)  v += Rb[(long)gm*ldc + gn];
            Cb[(long)gm*ldc + gn] = v;
        }
    }
}

// ---------------- separable fourier features ----------------
__global__ void sip_build_encsmall()
{
    int ri = blockIdx.x;
    int a = ri >> 5, v = ri & 31;
    float dim = (a == 2) ? 8.f : 32.f;
    float x = 2.f*v/dim - 1.f;
    int tid = threadIdx.x;               // 160
    __shared__ float sh[5];
    float val = 0.f;
    if (tid < 129){
        int r = tid;
        if (r < 64)        val = sinf(x * exp2f((float)(-r)));
        else if (r < 128)  val = cosf(x * exp2f((float)(64 - r)));
        else               val = x;
        g_encS[ri*129 + tid] = val;
    }
    float ss = val*val;
    for (int o=16;o>0;o>>=1) ss += __shfl_xor_sync(0xffffffffu, ss, o);
    if ((tid & 31) == 0) sh[tid>>5] = ss;
    __syncthreads();
    if (tid == 0) g_ssS[ri] = sh[0]+sh[1]+sh[2]+sh[3]+sh[4];
}

// ---------------- tiny factored EP tables (exact fp32) ----------------
__global__ void sip_ep_small(const float* __restrict__ kvw)
{
    int c = blockIdx.x*128 + threadIdx.x;
    if (c >= NKV) return;
    int ri = blockIdx.y, d = blockIdx.z;
    int a = ri >> 5;
    const float* W = kvw + (long)d*ID2*NKV + (long)(VC + a*129)*NKV + c;
    const float* E = g_encS + ri*129;
    float acc = 0.f;
#pragma unroll 4
    for (int r = 0; r < 129; r++) acc += E[r] * W[(long)r*NKV];
    g_EPT[((long)d*96 + ri)*NKV + c] = acc;
}

// ---------------- vals(b,n,48), invn, mask ----------------
__global__ void sip_build_vals(const float* __restrict__ input)
{
    int vox = blockIdx.x;
    int b = vox / NVOX, n = vox % NVOX;
    int hy = n / (GW*T_), wx = (n / T_) % GW, tt = n % T_;
    int tid = threadIdx.x;               // 64
    __shared__ float ssh[2], msh[2];
    float val = 0.f;
    if (tid < VC){
        int py = tid/12, px = (tid/3)%4, c = tid%3;
        val = input[(((long)tt*B_ + b)*3 + c)*16384 + (hy*4+py)*128 + (wx*4+px)];
        g_vals[(long)vox*VC + tid] = val;
    }
    float ss = val*val;
    float mx = (tid < VC) ? val : -FLT_MAX;
    for (int o=16;o>0;o>>=1){
        ss += __shfl_xor_sync(0xffffffffu, ss, o);
        mx = fmaxf(mx, __shfl_xor_sync(0xffffffffu, mx, o));
    }
    if ((tid & 31) == 0){ ssh[tid>>5] = ss; msh[tid>>5] = mx; }
    __syncthreads();
    if (tid == 0){
        float tot = ssh[0] + ssh[1] + g_ssS[hy] + g_ssS[32+wx] + g_ssS[64+tt];
        g_invn[vox] = 1.f / fmaxf(sqrtf(tot), 1e-5f);
        float m = fmaxf(msh[0], msh[1]);
        g_mask[vox] = (fabsf(m) > 0.3f) ? 1.f : 0.f;
    }
}

// ---------------- row L2-norm with scalar gain ----------------
__global__ void sip_rownorm(const float* __restrict__ in, float* __restrict__ out,
                            int cols, const float* __restrict__ gptr)
{
    long row = blockIdx.x;
    const float* p = in + row * cols;
    float* q = out + row * cols;
    __shared__ float sh[8];
    int tid = threadIdx.x;
    float s = 0.f;
    for (int j = tid; j < cols; j += blockDim.x){ float v = p[j]; s += v*v; }
    for (int o=16;o>0;o>>=1) s += __shfl_xor_sync(0xffffffffu, s, o);
    if ((tid & 31) == 0) sh[tid>>5] = s;
    __syncthreads();
    float tot = 0.f;
    int nw = blockDim.x >> 5;
    for (int w=0; w<nw; w++) tot += sh[w];
    float sc = gptr[0] / fmaxf(sqrtf(tot), 1e-5f);
    for (int j = tid; j < cols; j += blockDim.x) q[j] = p[j] * sc;
}

// ---------------- softmax; if linv!=null skip normalize and record 1/sum ----------------
__global__ void sip_softmax(float* __restrict__ S, int cols, float* __restrict__ linv)
{
    long row = blockIdx.x;
    float* p = S + row * (long)cols;
    __shared__ float sh[8];
    int tid = threadIdx.x;
    int nw = blockDim.x >> 5;
    float m = -FLT_MAX;
    for (int j = tid; j < cols; j += blockDim.x) m = fmaxf(m, p[j]);
    for (int o=16;o>0;o>>=1) m = fmaxf(m, __shfl_xor_sync(0xffffffffu, m, o));
    if ((tid & 31) == 0) sh[tid>>5] = m;
    __syncthreads();
    float mm = sh[0];
    for (int w=1; w<nw; w++) mm = fmaxf(mm, sh[w]);
    __syncthreads();
    float s = 0.f;
    for (int j = tid; j < cols; j += blockDim.x){
        float e = __expf(p[j] - mm);
        p[j] = e; s += e;
    }
    for (int o=16;o>0;o>>=1) s += __shfl_xor_sync(0xffffffffu, s, o);
    if ((tid & 31) == 0) sh[tid>>5] = s;
    __syncthreads();
    float tot = 0.f;
    for (int w=0; w<nw; w++) tot += sh[w];
    float inv = 1.f / tot;
    if (linv){
        if (tid == 0) linv[row] = inv;
    } else {
        for (int j = tid; j < cols; j += blockDim.x) p[j] *= inv;
    }
}

// ---------------- AV partial reduce + head merge ----------------
__global__ void sip_reduce_av(int nsplit, const float* __restrict__ linv)
{
    long total = (long)B_ * NL * IN_;
    long idx = (long)blockIdx.x * blockDim.x + threadIdx.x;
    if (idx >= total) return;
    int b = (int)(idx / (NL*IN_));
    int r = (int)(idx % (NL*IN_));
    int i = r / IN_, c = r % IN_;
    int h = c / DH, dd = c % DH;
    long base = ((long)(b*HH + h) * nsplit) * (NL*DH) + (long)i*DH + dd;
    float s = 0.f;
    for (int sp = 0; sp < nsplit; sp++) s += g_AVp[base + (long)sp*(NL*DH)];
    if (linv) s *= linv[(long)(b*HH + h)*NL + i];
    g_AO[idx] = s;
}

__global__ void sip_init_lat(const float* __restrict__ latents, const float* __restrict__ pos)
{
    long idx = (long)blockIdx.x * blockDim.x + threadIdx.x;
    if (idx >= (long)B_*NL*LD) return;
    int r = (int)(idx % (NL*LD));
    g_lat[idx] = latents[r] + pos[r];
}

__global__ void sip_permute_out(float* __restrict__ out)
{
    long idx = (long)blockIdx.x * blockDim.x + threadIdx.x;
    if (idx >= (long)T_*B_*16*OC) return;
    int o = (int)(idx % OC);
    long r = idx / OC;
    int nn = (int)(r % 16); r /= 16;
    int b = (int)(r % B_);
    int tt = (int)(r / B_);
    out[idx] = g_logits[((long)b*NL + nn*T_ + tt)*OC + o];
}

// ---------------- host ----------------
static inline int cdiv(int a, int b){ return (a + b - 1) / b; }

extern "C" void kernel_launch(void* const* d_in, const int* in_sizes, int n_in,
                              void* d_out, int out_size)
{
    const float* input    = (const float*)d_in[0];
    const float* latents  = (const float*)d_in[1];
    const float* pos_emb  = (const float*)d_in[2];
    const float* ca_g     = (const float*)d_in[3];
    const float* ca_ctx_g = (const float*)d_in[4];
    const float* ca_q     = (const float*)d_in[5];
    const float* ca_kv    = (const float*)d_in[6];
    const float* ca_ow    = (const float*)d_in[7];
    const float* ca_ob    = (const float*)d_in[8];
    const float* cf_g     = (const float*)d_in[9];
    const float* cf_w1    = (const float*)d_in[10];
    const float* cf_b1    = (const float*)d_in[11];
    const float* cf_w2    = (const float*)d_in[12];
    const float* cf_b2    = (const float*)d_in[13];
    const float* la_g     = (const float*)d_in[14];
    const float* la_q     = (const float*)d_in[15];
    const float* la_kv    = (const float*)d_in[16];
    const float* la_ow    = (const float*)d_in[17];
    const float* la_ob    = (const float*)d_in[18];
    const float* lf_g     = (const float*)d_in[19];
    const float* lf_w1    = (const float*)d_in[20];
    const float* lf_b1    = (const float*)d_in[21];
    const float* lf_w2    = (const float*)d_in[22];
    const float* lf_b2    = (const float*)d_in[23];
    const float* logits_w = (const float*)d_in[24];
    const float* logits_b = (const float*)d_in[25];
    float* out = (float*)d_out;

    float *p_vals,*p_invn,*p_mask,*p_EPT,*p_linv,*p_lat,*p_xn,*p_Qh,*p_Kh,*p_Vh,*p_S,*p_AVp,*p_AO,*p_hid,*p_logits;
#define SYM(p, s) do{ void* _t=nullptr; cudaGetSymbolAddress(&_t, s); p=(float*)_t; }while(0)
    SYM(p_vals, g_vals); SYM(p_invn, g_invn); SYM(p_mask, g_mask);
    SYM(p_EPT, g_EPT); SYM(p_linv, g_linv); SYM(p_lat, g_lat); SYM(p_xn, g_xn);
    SYM(p_Qh, g_Qh); SYM(p_Kh, g_Kh); SYM(p_Vh, g_Vh);
    SYM(p_S, g_S); SYM(p_AVp, g_AVp); SYM(p_AO, g_AO); SYM(p_hid, g_hid); SYM(p_logits, g_logits);
#undef SYM

    const int M0 = B_*NL;  // 512

    // -------- preamble (layer-invariant) --------
    sip_build_encsmall<<<96, 160>>>();
    sip_ep_small<<<dim3(cdiv(NKV,128), 96, DEPTH), 128>>>(ca_kv);
    sip_build_vals<<<B_*NVOX, 64>>>(input);
    sip_init_lat<<<cdiv(B_*NL*LD,256), 256>>>(latents, pos_emb);

    for (int d = 0; d < DEPTH; d++){
        // ===== cross attention =====
        sip_rownorm<<<M0, 256>>>(p_lat, p_xn, LD, ca_g + d);
        // Q = xn @ ca_q[d] * ATT_SCALE -> Qh scatter
        sip_mma<64,64,16,32,32,false,EPI_Q><<<dim3(cdiv(IN_,64),cdiv(M0,64),1),128>>>(
            M0, IN_, LD, p_xn, LD, 0, ca_q + (long)d*LD*IN_, IN_, 0,
            nullptr, 0, 0, nullptr, nullptr, nullptr, ATT_SCALE, nullptr, 1, 0, 1,
            nullptr, nullptr, p_Qh, nullptr, 0);
        // KV = (vals @ Wv + EPy+EPx+EPt) * invn * g -> Kh/Vh scatter
        sip_mma<128,128,16,64,32,false,EPI_KV|EPI_KV3><<<dim3(cdiv(NKV,128),cdiv(B_*NVOX,128),1),256>>>(
            B_*NVOX, NKV, VC, p_vals, VC, 0, ca_kv + (long)d*ID2*NKV, NKV, 0,
            nullptr, 0, 0, nullptr, nullptr, ca_ctx_g + d, 1.f, nullptr, 1, 0, 1,
            p_EPT + (long)d*96*NKV, p_invn, p_Kh, p_Vh, NVOX);
        // scores = Qh @ Kh^T (scale pre-folded), masked
        sip_mma<128,128,16,64,32,true,EPI_MASK><<<dim3(cdiv(NVOX,128),1,B_*HH),256>>>(
            NL, NVOX, DH, p_Qh, DH, (long)NL*DH, p_Kh, DH, (long)NVOX*DH,
            p_S, NVOX, (long)NL*NVOX, nullptr, nullptr, nullptr, 1.f,
            p_mask, HH, NVOX, 1, nullptr, nullptr, nullptr, nullptr, 0);
        sip_softmax<<<B_*HH*NL, 256>>>(p_S, NVOX, p_linv);
        // AV split-K (unnormalized probs; 1/sum folded into reduce)
        sip_mma<128,80,16,64,40,false,0><<<dim3(1,1,B_*HH*NSPL),128>>>(
            NL, DH, NVOX, p_S, NVOX, (long)NL*NVOX, p_Vh, DH, (long)NVOX*DH,
            p_AVp, DH, 0, nullptr, nullptr, nullptr, 1.f, nullptr, 1, 0, NSPL,
            nullptr, nullptr, nullptr, nullptr, 0);
        sip_reduce_av<<<cdiv(B_*NL*IN_,256), 256>>>(NSPL, p_linv);
        sip_mma<64,64,16,32,32,false,EPI_BIAS|EPI_RES><<<dim3(cdiv(LD,64),cdiv(M0,64),1),128>>>(
            M0, LD, IN_, p_AO, IN_, 0, ca_ow + (long)d*IN_*LD, LD, 0,
            p_lat, LD, 0, ca_ob + (long)d*LD, p_lat, nullptr, 1.f, nullptr, 1, 0, 1,
            nullptr, nullptr, nullptr, nullptr, 0);

        // ===== feed-forward (cross) =====
        sip_rownorm<<<M0, 256>>>(p_lat, p_xn, LD, cf_g + d);
        sip_mma<64,64,16,32,32,false,EPI_BIAS|EPI_GELU><<<dim3(cdiv(FF,64),cdiv(M0,64),1),128>>>(
            M0, FF, LD, p_xn, LD, 0, cf_w1 + (long)d*LD*FF, FF, 0,
            p_hid, FF, 0, cf_b1 + (long)d*FF, nullptr, nullptr, 1.f, nullptr, 1, 0, 1,
            nullptr, nullptr, nullptr, nullptr, 0);
        sip_mma<64,64,16,32,32,false,EPI_BIAS|EPI_RES><<<dim3(cdiv(LD,64),cdiv(M0,64),1),128>>>(
            M0, LD, FF, p_hid, FF, 0, cf_w2 + (long)d*FF*LD, LD, 0,
            p_lat, LD, 0, cf_b2 + (long)d*LD, p_lat, nullptr, 1.f, nullptr, 1, 0, 1,
            nullptr, nullptr, nullptr, nullptr, 0);

        // ===== latent self-attention =====
        sip_rownorm<<<M0, 256>>>(p_lat, p_xn, LD, la_g + d);
        sip_mma<64,64,16,32,32,false,EPI_Q><<<dim3(cdiv(IN_,64),cdiv(M0,64),1),128>>>(
            M0, IN_, LD, p_xn, LD, 0, la_q + (long)d*LD*IN_, IN_, 0,
            nullptr, 0, 0, nullptr, nullptr, nullptr, ATT_SCALE, nullptr, 1, 0, 1,
            nullptr, nullptr, p_Qh, nullptr, 0);
        sip_mma<64,64,16,32,32,false,EPI_KV><<<dim3(cdiv(NKV,64),cdiv(M0,64),1),128>>>(
            M0, NKV, LD, p_xn, LD, 0, la_kv + (long)d*LD*NKV, NKV, 0,
            nullptr, 0, 0, nullptr, nullptr, nullptr, 1.f, nullptr, 1, 0, 1,
            nullptr, nullptr, p_Kh, p_Vh, NL);
        sip_mma<64,64,16,32,32,true,0><<<dim3(cdiv(NL,64),cdiv(NL,64),B_*HH),128>>>(
            NL, NL, DH, p_Qh, DH, (long)NL*DH, p_Kh, DH, (long)NL*DH,
            p_S, NL, (long)NL*NL, nullptr, nullptr, nullptr, 1.f, nullptr, 1, 0, 1,
            nullptr, nullptr, nullptr, nullptr, 0);
        sip_softmax<<<B_*HH*NL, 128>>>(p_S, NL, nullptr);
        sip_mma<128,80,16,64,40,false,0><<<dim3(1,1,B_*HH),128>>>(
            NL, DH, NL, p_S, NL, (long)NL*NL, p_Vh, DH, (long)NL*DH,
            p_AVp, DH, (long)NL*DH, nullptr, nullptr, nullptr, 1.f, nullptr, 1, 0, 1,
            nullptr, nullptr, nullptr, nullptr, 0);
        sip_reduce_av<<<cdiv(B_*NL*IN_,256), 256>>>(1, nullptr);
        sip_mma<64,64,16,32,32,false,EPI_BIAS|EPI_RES><<<dim3(cdiv(LD,64),cdiv(M0,64),1),128>>>(
            M0, LD, IN_, p_AO, IN_, 0, la_ow + (long)d*IN_*LD, LD, 0,
            p_lat, LD, 0, la_ob + (long)d*LD, p_lat, nullptr, 1.f, nullptr, 1, 0, 1,
            nullptr, nullptr, nullptr, nullptr, 0);

        // ===== feed-forward (latent) =====
        sip_rownorm<<<M0, 256>>>(p_lat, p_xn, LD, lf_g + d);
        sip_mma<64,64,16,32,32,false,EPI_BIAS|EPI_GELU><<<dim3(cdiv(FF,64),cdiv(M0,64),1),128>>>(
            M0, FF, LD, p_xn, LD, 0, lf_w1 + (long)d*LD*FF, FF, 0,
            p_hid, FF, 0, lf_b1 + (long)d*FF, nullptr, nullptr, 1.f, nullptr, 1, 0, 1,
            nullptr, nullptr, nullptr, nullptr, 0);
        sip_mma<64,64,16,32,32,false,EPI_BIAS|EPI_RES><<<dim3(cdiv(LD,64),cdiv(M0,64),1),128>>>(
            M0, LD, FF, p_hid, FF, 0, lf_w2 + (long)d*FF*LD, LD, 0,
            p_lat, LD, 0, lf_b2 + (long)d*LD, p_lat, nullptr, 1.f, nullptr, 1, 0, 1,
            nullptr, nullptr, nullptr, nullptr, 0);
    }

    // ===== logits + output permute =====
    sip_mma<64,64,16,32,32,false,EPI_BIAS><<<dim3(cdiv(OC,64),cdiv(M0,64),1),128>>>(
        M0, OC, LD, p_lat, LD, 0, logits_w, OC, 0,
        p_logits, OC, 0, logits_b, nullptr, nullptr, 1.f, nullptr, 1, 0, 1,
        nullptr, nullptr, nullptr, nullptr, 0);
    sip_permute_out<<<cdiv(T_*B_*16*OC,256), 256>>>(out);
}

// round 5
// speedup vs baseline: 2.4586x; 1.1535x over previous
#include <cuda_runtime.h>
#include <math.h>
#include <float.h>
#include <stdint.h>

// ---------------- problem constants ----------------
constexpr int B_   = 4;
constexpr int T_   = 8;
constexpr int HH   = 8;
constexpr int DH   = 75;
constexpr int NL   = 128;
constexpr int LD   = 512;
constexpr int ID2  = 435;
constexpr int VC   = 48;
constexpr int IN_  = 600;
constexpr int FF   = 2048;
constexpr int OC   = 64;
constexpr int DEPTH= 5;
constexpr int GH   = 32, GW = 32;
constexpr int NVOX = GH*GW*T_;           // 8192
constexpr int NKV  = 2*IN_;              // 1200
constexpr float ATT_SCALE = 0.11547005383792515f;

// flash params
constexpr int NSPL2 = 8;                 // KV splits for cross flash
constexpr int DHP   = 80;                // padded head dim
constexpr int BKV   = 32;                // KV rows per inner tile
constexpr int FITERS= (NVOX/NSPL2)/BKV;  // 32

// ---------------- scratch ----------------
__device__ float g_vals [(size_t)B_*NVOX*VC];
__device__ float g_encS [(size_t)96*129];
__device__ float g_ssS  [(size_t)96];
__device__ float g_EPT  [(size_t)DEPTH*96*NKV];
__device__ float g_invn [(size_t)B_*NVOX];
__device__ float g_mask [(size_t)B_*NVOX];
__device__ float g_lat  [(size_t)B_*NL*LD];
__device__ float g_xn   [(size_t)B_*NL*LD];
__device__ float g_Qh   [(size_t)B_*HH*NL*DH];
__device__ float g_Kh   [(size_t)B_*HH*NVOX*DH];
__device__ float g_Vh   [(size_t)B_*HH*NVOX*DH];
__device__ float g_S    [(size_t)B_*HH*NL*NL];      // latent self-attn only
__device__ float g_AVp  [(size_t)B_*HH*NL*DH];      // latent AV
__device__ float g_AO   [(size_t)B_*NL*IN_];
__device__ float g_hid  [(size_t)B_*NL*FF];
__device__ float g_logits[(size_t)B_*NL*OC];
// flash partials
__device__ float g_fo   [(size_t)NSPL2*B_*HH*NL*DHP];
__device__ float g_fm   [(size_t)NSPL2*B_*HH*NL];
__device__ float g_fl   [(size_t)NSPL2*B_*HH*NL];

// ---------------- tf32 helpers ----------------
__device__ __forceinline__ uint32_t f2tf32(float f){
    uint32_t r; asm("cvt.rna.tf32.f32 %0, %1;" : "=r"(r) : "f"(f)); return r;
}
__device__ __forceinline__ void mma_tf32(float c[4], const uint32_t a[4], const uint32_t b[2]){
    asm("mma.sync.aligned.m16n8k8.row.col.f32.tf32.tf32.f32 "
        "{%0,%1,%2,%3}, {%4,%5,%6,%7}, {%8,%9}, {%0,%1,%2,%3};"
        : "+f"(c[0]), "+f"(c[1]), "+f"(c[2]), "+f"(c[3])
        : "r"(a[0]), "r"(a[1]), "r"(a[2]), "r"(a[3]), "r"(b[0]), "r"(b[1]));
}

// ---------------- epilogue flags ----------------
#define EPI_BIAS 1
#define EPI_GELU 2
#define EPI_RES  4
#define EPI_MASK 8
#define EPI_KV   16
#define EPI_Q    32
#define EPI_KV3  64

// ---------------- tf32 tensor-core GEMM with fused epilogues ----------------
template<int BM,int BN,int BK,int WM,int WN,bool TB,int EPI>
__global__ void __launch_bounds__((BM/WM)*(BN/WN)*32)
sip_mma(int M,int N,int K,
        const float* __restrict__ A,int lda,long sA,
        const float* __restrict__ Bp,int ldb,long sB,
        float* __restrict__ C,int ldc,long sC,
        const float* __restrict__ bias,
        const float* __restrict__ resid,
        const float* __restrict__ alphaPtr,float alphaC,
        const float* __restrict__ maskPtr,int maskBdiv,int maskStride,
        int nsplit,
        const float* __restrict__ ep,
        const float* __restrict__ rowscale,
        float* __restrict__ KhD, float* __restrict__ VhD, int kvSeq)
{
    constexpr int NWARP = (BM/WM)*(BN/WN);
    constexpr int NT = NWARP*32;
    constexpr int LDA = BM + 4;
    constexpr int LDB = BN + 4;
    __shared__ uint32_t As[BK][LDA];
    __shared__ uint32_t Bs[BK][LDB];

    int tid = threadIdx.x;
    int z = blockIdx.z;
    int batch = z / nsplit, split = z - batch*nsplit;
    int kchunk = (K + nsplit - 1) / nsplit;
    int k0 = split * kchunk;
    int k1 = min(K, k0 + kchunk);
    const float* Ab = A + (long)batch * sA;
    const float* Bb = Bp + (long)batch * sB;
    int row0 = blockIdx.y * BM, col0 = blockIdx.x * BN;
    int wid = tid >> 5, lane = tid & 31;
    int g = lane >> 2, tig = lane & 3;
    int wm0 = (wid % (BM/WM)) * WM;
    int wn0 = (wid / (BM/WM)) * WN;
    constexpr int MT = WM/16, NTN = WN/8;

    float acc[MT][NTN][4];
#pragma unroll
    for (int i=0;i<MT;i++)
#pragma unroll
        for (int j=0;j<NTN;j++)
#pragma unroll
            for (int r=0;r<4;r++) acc[i][j][r] = 0.f;

    constexpr int AE = BM*BK/NT;
    constexpr int BE = BN*BK/NT;

    for (int kt = k0; kt < k1; kt += BK){
#pragma unroll
        for (int e=0;e<AE;e++){
            int idx = e*NT + tid;
            int m = idx / BK, k = idx % BK;
            int gm = row0 + m, gk = kt + k;
            float v = (gm < M && gk < k1) ? Ab[(long)gm*lda + gk] : 0.f;
            As[k][m] = f2tf32(v);
        }
#pragma unroll
        for (int e=0;e<BE;e++){
            int idx = e*NT + tid;
            if (TB){
                int n = idx / BK, k = idx % BK;
                int gn = col0 + n, gk = kt + k;
                float v = (gn < N && gk < k1) ? Bb[(long)gn*ldb + gk] : 0.f;
                Bs[k][n] = f2tf32(v);
            } else {
                int k = idx / BN, n = idx % BN;
                int gn = col0 + n, gk = kt + k;
                float v = (gn < N && gk < k1) ? Bb[(long)gk*ldb + gn] : 0.f;
                Bs[k][n] = f2tf32(v);
            }
        }
        __syncthreads();
#pragma unroll
        for (int ks=0; ks<BK/8; ks++){
            uint32_t af[MT][4], bf[NTN][2];
#pragma unroll
            for (int mt=0; mt<MT; mt++){
                int mb = wm0 + mt*16;
                af[mt][0] = As[ks*8 + tig    ][mb + g    ];
                af[mt][1] = As[ks*8 + tig    ][mb + g + 8];
                af[mt][2] = As[ks*8 + tig + 4][mb + g    ];
                af[mt][3] = As[ks*8 + tig + 4][mb + g + 8];
            }
#pragma unroll
            for (int nt=0; nt<NTN; nt++){
                int nb = wn0 + nt*8;
                bf[nt][0] = Bs[ks*8 + tig    ][nb + g];
                bf[nt][1] = Bs[ks*8 + tig + 4][nb + g];
            }
#pragma unroll
            for (int mt=0; mt<MT; mt++)
#pragma unroll
                for (int nt=0; nt<NTN; nt++)
                    mma_tf32(acc[mt][nt], af[mt], bf[nt]);
        }
        __syncthreads();
    }

    float alpha = alphaC;
    if (alphaPtr) alpha *= alphaPtr[0];

    if (EPI & (EPI_KV | EPI_Q)){
#pragma unroll
        for (int mt=0; mt<MT; mt++)
#pragma unroll
        for (int r2=0; r2<2; r2++){
            int gm = row0 + wm0 + mt*16 + g + r2*8;
            if (gm >= M) continue;
            float rs = 1.f;
            int bb, jj;
            if (EPI & EPI_KV){
                bb = gm / kvSeq; jj = gm - bb*kvSeq;
                if (rowscale) rs = rowscale[gm];
            } else {
                bb = gm / NL; jj = gm - bb*NL;
            }
#pragma unroll
            for (int nt=0; nt<NTN; nt++)
#pragma unroll
            for (int c2=0; c2<2; c2++){
                int gn = col0 + wn0 + nt*8 + tig*2 + c2;
                if (gn >= N) continue;
                float v = acc[mt][nt][r2*2 + c2];
                if (EPI & EPI_KV){
                    if (EPI & EPI_KV3){
                        int y = jj>>8, xx = (jj>>3)&31, t = jj&7;
                        v += ep[(long)y*NKV + gn]
                           + ep[(long)(32+xx)*NKV + gn]
                           + ep[(long)(64+t)*NKV + gn];
                    } else if (ep){
                        v += ep[(long)jj*N + gn];
                    }
                    v *= alpha * rs;
                    int c = gn;
                    if (c < IN_){
                        int h = c / DH, dd = c - h*DH;
                        KhD[(((long)(bb*HH + h))*kvSeq + jj)*DH + dd] = v;
                    } else {
                        c -= IN_;
                        int h = c / DH, dd = c - h*DH;
                        VhD[(((long)(bb*HH + h))*kvSeq + jj)*DH + dd] = v;
                    }
                } else {
                    v *= alpha;
                    int h = gn / DH, dd = gn - h*DH;
                    KhD[(((long)(bb*HH + h))*NL + jj)*DH + dd] = v;
                }
            }
        }
        return;
    }

    long coff = (nsplit > 1) ? (long)z * M * ldc : (long)batch * sC;
    float* Cb = C + coff;
    const float* Rb = (EPI & EPI_RES) ? resid + (long)batch * sC : nullptr;
    const float* mrow = (EPI & EPI_MASK) ? maskPtr + (long)(batch / maskBdiv) * maskStride : nullptr;
#pragma unroll
    for (int mt=0; mt<MT; mt++)
#pragma unroll
    for (int r2=0; r2<2; r2++){
        int gm = row0 + wm0 + mt*16 + g + r2*8;
        if (gm >= M) continue;
#pragma unroll
        for (int nt=0; nt<NTN; nt++)
#pragma unroll
        for (int c2=0; c2<2; c2++){
            int gn = col0 + wn0 + nt*8 + tig*2 + c2;
            if (gn >= N) continue;
            float v = acc[mt][nt][r2*2 + c2] * alpha;
            if (EPI & EPI_MASK){ if (mrow[gn] < 0.5f) v = -FLT_MAX; }
            if (EPI & EPI_BIAS) v += bias[gn];
            if (EPI & EPI_GELU) v = 0.5f * v * (1.f + erff(v * 0.7071067811865476f));
            if (EPI & EPI_RES)  v += Rb[(long)gm*ldc + gn];
            Cb[(long)gm*ldc + gn] = v;
        }
    }
}

// ---------------- fused cross-attention flash kernel (split-KV) ----------------
// grid (NSPL2, B_*HH), 256 threads. Q pre-scaled by ATT_SCALE in g_Qh.
__global__ void __launch_bounds__(256)
sip_flash()
{
    __shared__ uint32_t Ks[DHP][BKV+8];   // K^T tile, stride 40 (conflict-free b-frag)
    __shared__ uint32_t Vs[BKV][DHP+4];   // V tile,   stride 84
    __shared__ uint32_t Ps[NL][BKV+4];    // P tile,   stride 36 (conflict-free a-frag)
    __shared__ float msk[BKV];

    int split = blockIdx.x, bh = blockIdx.y;
    int b = bh / HH;
    int tid = threadIdx.x, w = tid>>5, lane = tid&31;
    int g = lane>>2, tig = lane&3;
    int kv0 = split * (NVOX/NSPL2);

    // Q rows (warp-owned 16 rows) as persistent A-fragments
    uint32_t qf[10][4];
    {
        const float* Qb = g_Qh + (long)bh*NL*DH;
        int r0 = w*16 + g;
#pragma unroll
        for (int ks=0; ks<10; ks++){
            int c0 = ks*8 + tig;
            float v00 = (c0   < DH) ? Qb[(long)r0*DH + c0]       : 0.f;
            float v10 = (c0   < DH) ? Qb[(long)(r0+8)*DH + c0]   : 0.f;
            float v01 = (c0+4 < DH) ? Qb[(long)r0*DH + c0+4]     : 0.f;
            float v11 = (c0+4 < DH) ? Qb[(long)(r0+8)*DH + c0+4] : 0.f;
            qf[ks][0]=f2tf32(v00); qf[ks][1]=f2tf32(v10);
            qf[ks][2]=f2tf32(v01); qf[ks][3]=f2tf32(v11);
        }
    }

    float o[10][4];
#pragma unroll
    for (int nt=0;nt<10;nt++)
#pragma unroll
        for (int r=0;r<4;r++) o[nt][r]=0.f;
    float mrun[2] = {-FLT_MAX, -FLT_MAX};
    float lrun[2] = {0.f, 0.f};

    const float* Kb = g_Kh + (long)bh*NVOX*DH;
    const float* Vb = g_Vh + (long)bh*NVOX*DH;
    const float* Mb = g_mask + (long)b*NVOX;

    for (int it=0; it<FITERS; it++){
        int j0 = kv0 + it*BKV;
        // cooperative K^T / V tile load (2560 elems each, 10 per thread)
#pragma unroll
        for (int e=0;e<10;e++){
            int idx = e*256 + tid;
            int r = idx / DHP, c = idx - r*DHP;
            float kv = (c < DH) ? Kb[(long)(j0+r)*DH + c] : 0.f;
            Ks[c][r] = f2tf32(kv);
            float vv = (c < DH) ? Vb[(long)(j0+r)*DH + c] : 0.f;
            Vs[r][c] = f2tf32(vv);
        }
        if (tid < BKV) msk[tid] = Mb[j0 + tid];
        __syncthreads();

        // S = Q @ K^T  (16 rows x 32 cols per warp)
        float s[4][4];
#pragma unroll
        for (int nt=0;nt<4;nt++)
#pragma unroll
            for (int r=0;r<4;r++) s[nt][r]=0.f;
#pragma unroll
        for (int ks=0; ks<10; ks++){
            uint32_t bfr[4][2];
#pragma unroll
            for (int nt=0;nt<4;nt++){
                bfr[nt][0] = Ks[ks*8 + tig    ][nt*8 + g];
                bfr[nt][1] = Ks[ks*8 + tig + 4][nt*8 + g];
            }
#pragma unroll
            for (int nt=0;nt<4;nt++) mma_tf32(s[nt], qf[ks], bfr[nt]);
        }
        // mask
#pragma unroll
        for (int nt=0;nt<4;nt++)
#pragma unroll
        for (int r=0;r<4;r++){
            int jl = nt*8 + tig*2 + (r & 1);
            if (msk[jl] < 0.5f) s[nt][r] = -FLT_MAX;
        }
        // online softmax per owned row (r2 = 0,1)
#pragma unroll
        for (int r2=0;r2<2;r2++){
            float mx = -FLT_MAX;
#pragma unroll
            for (int nt=0;nt<4;nt++){
                mx = fmaxf(mx, s[nt][r2*2+0]);
                mx = fmaxf(mx, s[nt][r2*2+1]);
            }
            mx = fmaxf(mx, __shfl_xor_sync(0xffffffffu, mx, 1));
            mx = fmaxf(mx, __shfl_xor_sync(0xffffffffu, mx, 2));
            float mnew = fmaxf(mrun[r2], mx);
            float sc = __expf(mrun[r2] - mnew);
            mrun[r2] = mnew;
            lrun[r2] *= sc;
#pragma unroll
            for (int nt=0;nt<10;nt++){
                o[nt][r2*2+0] *= sc;
                o[nt][r2*2+1] *= sc;
            }
            float ps = 0.f;
#pragma unroll
            for (int nt=0;nt<4;nt++){
                float p0 = __expf(s[nt][r2*2+0] - mnew);
                float p1 = __expf(s[nt][r2*2+1] - mnew);
                s[nt][r2*2+0] = p0; s[nt][r2*2+1] = p1;
                ps += p0 + p1;
            }
            ps += __shfl_xor_sync(0xffffffffu, ps, 1);
            ps += __shfl_xor_sync(0xffffffffu, ps, 2);
            lrun[r2] += ps;
        }
        // P -> smem (warp-private rows)
#pragma unroll
        for (int nt=0;nt<4;nt++)
#pragma unroll
        for (int r=0;r<4;r++){
            int row = w*16 + g + (r>>1)*8;
            int col = nt*8 + tig*2 + (r&1);
            Ps[row][col] = f2tf32(s[nt][r]);
        }
        __syncwarp();
        // O += P @ V
#pragma unroll
        for (int ks=0; ks<4; ks++){
            uint32_t af[4];
            af[0] = Ps[w*16 + g    ][ks*8 + tig    ];
            af[1] = Ps[w*16 + g + 8][ks*8 + tig    ];
            af[2] = Ps[w*16 + g    ][ks*8 + tig + 4];
            af[3] = Ps[w*16 + g + 8][ks*8 + tig + 4];
#pragma unroll
            for (int nt=0;nt<10;nt++){
                uint32_t bfr[2];
                bfr[0] = Vs[ks*8 + tig    ][nt*8 + g];
                bfr[1] = Vs[ks*8 + tig + 4][nt*8 + g];
                mma_tf32(o[nt], af, bfr);
            }
        }
        __syncthreads();
    }

    // write partials
    long base = ((long)split*B_*HH + bh) * NL;
#pragma unroll
    for (int r2=0;r2<2;r2++){
        int row = w*16 + g + r2*8;
        if (tig == 0){
            g_fm[base + row] = mrun[r2];
            g_fl[base + row] = lrun[r2];
        }
#pragma unroll
        for (int nt=0;nt<10;nt++){
            g_fo[(base + row)*DHP + nt*8 + tig*2 + 0] = o[nt][r2*2+0];
            g_fo[(base + row)*DHP + nt*8 + tig*2 + 1] = o[nt][r2*2+1];
        }
    }
}

// ---------------- flash split combine + head merge -> AO ----------------
__global__ void sip_flash_combine()
{
    int blk = blockIdx.x;            // bh*NL + row
    int bh = blk / NL, row = blk - bh*NL;
    int b = bh / HH, h = bh - b*HH;
    int tid = threadIdx.x;           // 128
    __shared__ float sm[NSPL2], sl[NSPL2];
    __shared__ float sms, sden;
    if (tid < NSPL2){
        long idx = ((long)tid*B_*HH + bh)*NL + row;
        sm[tid] = g_fm[idx];
        sl[tid] = g_fl[idx];
    }
    __syncthreads();
    if (tid == 0){
        float mx = sm[0];
#pragma unroll
        for (int s2=1;s2<NSPL2;s2++) mx = fmaxf(mx, sm[s2]);
        float den = 0.f;
#pragma unroll
        for (int s2=0;s2<NSPL2;s2++) den += sl[s2] * __expf(sm[s2] - mx);
        sms = mx; sden = den;
    }
    __syncthreads();
    if (tid < DH){
        float acc = 0.f;
#pragma unroll
        for (int s2=0;s2<NSPL2;s2++){
            float wgt = __expf(sm[s2] - sms);
            acc += g_fo[(((long)s2*B_*HH + bh)*NL + row)*DHP + tid] * wgt;
        }
        g_AO[((long)b*NL + row)*IN_ + h*DH + tid] = acc / sden;
    }
}

// ---------------- separable fourier features ----------------
__global__ void sip_build_encsmall()
{
    int ri = blockIdx.x;
    int a = ri >> 5, v = ri & 31;
    float dim = (a == 2) ? 8.f : 32.f;
    float x = 2.f*v/dim - 1.f;
    int tid = threadIdx.x;               // 160
    __shared__ float sh[5];
    float val = 0.f;
    if (tid < 129){
        int r = tid;
        if (r < 64)        val = sinf(x * exp2f((float)(-r)));
        else if (r < 128)  val = cosf(x * exp2f((float)(64 - r)));
        else               val = x;
        g_encS[ri*129 + tid] = val;
    }
    float ss = val*val;
    for (int o=16;o>0;o>>=1) ss += __shfl_xor_sync(0xffffffffu, ss, o);
    if ((tid & 31) == 0) sh[tid>>5] = ss;
    __syncthreads();
    if (tid == 0) g_ssS[ri] = sh[0]+sh[1]+sh[2]+sh[3]+sh[4];
}

// ---------------- tiny factored EP tables (exact fp32) ----------------
__global__ void sip_ep_small(const float* __restrict__ kvw)
{
    int c = blockIdx.x*128 + threadIdx.x;
    if (c >= NKV) return;
    int ri = blockIdx.y, d = blockIdx.z;
    int a = ri >> 5;
    const float* W = kvw + (long)d*ID2*NKV + (long)(VC + a*129)*NKV + c;
    const float* E = g_encS + ri*129;
    float acc = 0.f;
#pragma unroll 4
    for (int r = 0; r < 129; r++) acc += E[r] * W[(long)r*NKV];
    g_EPT[((long)d*96 + ri)*NKV + c] = acc;
}

// ---------------- vals(b,n,48), invn, mask ----------------
__global__ void sip_build_vals(const float* __restrict__ input)
{
    int vox = blockIdx.x;
    int b = vox / NVOX, n = vox % NVOX;
    int hy = n / (GW*T_), wx = (n / T_) % GW, tt = n % T_;
    int tid = threadIdx.x;               // 64
    __shared__ float ssh[2], msh[2];
    float val = 0.f;
    if (tid < VC){
        int py = tid/12, px = (tid/3)%4, c = tid%3;
        val = input[(((long)tt*B_ + b)*3 + c)*16384 + (hy*4+py)*128 + (wx*4+px)];
        g_vals[(long)vox*VC + tid] = val;
    }
    float ss = val*val;
    float mx = (tid < VC) ? val : -FLT_MAX;
    for (int o=16;o>0;o>>=1){
        ss += __shfl_xor_sync(0xffffffffu, ss, o);
        mx = fmaxf(mx, __shfl_xor_sync(0xffffffffu, mx, o));
    }
    if ((tid & 31) == 0){ ssh[tid>>5] = ss; msh[tid>>5] = mx; }
    __syncthreads();
    if (tid == 0){
        float tot = ssh[0] + ssh[1] + g_ssS[hy] + g_ssS[32+wx] + g_ssS[64+tt];
        g_invn[vox] = 1.f / fmaxf(sqrtf(tot), 1e-5f);
        float m = fmaxf(msh[0], msh[1]);
        g_mask[vox] = (fabsf(m) > 0.3f) ? 1.f : 0.f;
    }
}

// ---------------- row L2-norm with scalar gain ----------------
__global__ void sip_rownorm(const float* __restrict__ in, float* __restrict__ out,
                            int cols, const float* __restrict__ gptr)
{
    long row = blockIdx.x;
    const float* p = in + row * cols;
    float* q = out + row * cols;
    __shared__ float sh[8];
    int tid = threadIdx.x;
    float s = 0.f;
    for (int j = tid; j < cols; j += blockDim.x){ float v = p[j]; s += v*v; }
    for (int o=16;o>0;o>>=1) s += __shfl_xor_sync(0xffffffffu, s, o);
    if ((tid & 31) == 0) sh[tid>>5] = s;
    __syncthreads();
    float tot = 0.f;
    int nw = blockDim.x >> 5;
    for (int w=0; w<nw; w++) tot += sh[w];
    float sc = gptr[0] / fmaxf(sqrtf(tot), 1e-5f);
    for (int j = tid; j < cols; j += blockDim.x) q[j] = p[j] * sc;
}

// ---------------- softmax (latent path; full normalize) ----------------
__global__ void sip_softmax(float* __restrict__ S, int cols)
{
    long row = blockIdx.x;
    float* p = S + row * (long)cols;
    __shared__ float sh[8];
    int tid = threadIdx.x;
    int nw = blockDim.x >> 5;
    float m = -FLT_MAX;
    for (int j = tid; j < cols; j += blockDim.x) m = fmaxf(m, p[j]);
    for (int o=16;o>0;o>>=1) m = fmaxf(m, __shfl_xor_sync(0xffffffffu, m, o));
    if ((tid & 31) == 0) sh[tid>>5] = m;
    __syncthreads();
    float mm = sh[0];
    for (int w=1; w<nw; w++) mm = fmaxf(mm, sh[w]);
    __syncthreads();
    float s = 0.f;
    for (int j = tid; j < cols; j += blockDim.x){
        float e = __expf(p[j] - mm);
        p[j] = e; s += e;
    }
    for (int o=16;o>0;o>>=1) s += __shfl_xor_sync(0xffffffffu, s, o);
    if ((tid & 31) == 0) sh[tid>>5] = s;
    __syncthreads();
    float tot = 0.f;
    for (int w=0; w<nw; w++) tot += sh[w];
    float inv = 1.f / tot;
    for (int j = tid; j < cols; j += blockDim.x) p[j] *= inv;
}

// ---------------- latent AV head-merge: AVp -> AO ----------------
__global__ void sip_reduce_av()
{
    long total = (long)B_ * NL * IN_;
    long idx = (long)blockIdx.x * blockDim.x + threadIdx.x;
    if (idx >= total) return;
    int b = (int)(idx / (NL*IN_));
    int r = (int)(idx % (NL*IN_));
    int i = r / IN_, c = r % IN_;
    int h = c / DH, dd = c % DH;
    g_AO[idx] = g_AVp[((long)(b*HH + h))*(NL*DH) + (long)i*DH + dd];
}

__global__ void sip_init_lat(const float* __restrict__ latents, const float* __restrict__ pos)
{
    long idx = (long)blockIdx.x * blockDim.x + threadIdx.x;
    if (idx >= (long)B_*NL*LD) return;
    int r = (int)(idx % (NL*LD));
    g_lat[idx] = latents[r] + pos[r];
}

__global__ void sip_permute_out(float* __restrict__ out)
{
    long idx = (long)blockIdx.x * blockDim.x + threadIdx.x;
    if (idx >= (long)T_*B_*16*OC) return;
    int o = (int)(idx % OC);
    long r = idx / OC;
    int nn = (int)(r % 16); r /= 16;
    int b = (int)(r % B_);
    int tt = (int)(r / B_);
    out[idx] = g_logits[((long)b*NL + nn*T_ + tt)*OC + o];
}

// ---------------- host ----------------
static inline int cdiv(int a, int b){ return (a + b - 1) / b; }

extern "C" void kernel_launch(void* const* d_in, const int* in_sizes, int n_in,
                              void* d_out, int out_size)
{
    const float* input    = (const float*)d_in[0];
    const float* latents  = (const float*)d_in[1];
    const float* pos_emb  = (const float*)d_in[2];
    const float* ca_g     = (const float*)d_in[3];
    const float* ca_ctx_g = (const float*)d_in[4];
    const float* ca_q     = (const float*)d_in[5];
    const float* ca_kv    = (const float*)d_in[6];
    const float* ca_ow    = (const float*)d_in[7];
    const float* ca_ob    = (const float*)d_in[8];
    const float* cf_g     = (const float*)d_in[9];
    const float* cf_w1    = (const float*)d_in[10];
    const float* cf_b1    = (const float*)d_in[11];
    const float* cf_w2    = (const float*)d_in[12];
    const float* cf_b2    = (const float*)d_in[13];
    const float* la_g     = (const float*)d_in[14];
    const float* la_q     = (const float*)d_in[15];
    const float* la_kv    = (const float*)d_in[16];
    const float* la_ow    = (const float*)d_in[17];
    const float* la_ob    = (const float*)d_in[18];
    const float* lf_g     = (const float*)d_in[19];
    const float* lf_w1    = (const float*)d_in[20];
    const float* lf_b1    = (const float*)d_in[21];
    const float* lf_w2    = (const float*)d_in[22];
    const float* lf_b2    = (const float*)d_in[23];
    const float* logits_w = (const float*)d_in[24];
    const float* logits_b = (const float*)d_in[25];
    float* out = (float*)d_out;

    float *p_vals,*p_EPT,*p_invn,*p_lat,*p_xn,*p_Qh,*p_Kh,*p_Vh,*p_S,*p_AVp,*p_AO,*p_hid,*p_logits;
#define SYM(p, s) do{ void* _t=nullptr; cudaGetSymbolAddress(&_t, s); p=(float*)_t; }while(0)
    SYM(p_vals, g_vals); SYM(p_EPT, g_EPT); SYM(p_invn, g_invn);
    SYM(p_lat, g_lat); SYM(p_xn, g_xn);
    SYM(p_Qh, g_Qh); SYM(p_Kh, g_Kh); SYM(p_Vh, g_Vh);
    SYM(p_S, g_S); SYM(p_AVp, g_AVp); SYM(p_AO, g_AO); SYM(p_hid, g_hid); SYM(p_logits, g_logits);
#undef SYM

    const int M0 = B_*NL;  // 512

    // -------- preamble (layer-invariant) --------
    sip_build_encsmall<<<96, 160>>>();
    sip_ep_small<<<dim3(cdiv(NKV,128), 96, DEPTH), 128>>>(ca_kv);
    sip_build_vals<<<B_*NVOX, 64>>>(input);
    sip_init_lat<<<cdiv(B_*NL*LD,256), 256>>>(latents, pos_emb);

    for (int d = 0; d < DEPTH; d++){
        // ===== cross attention =====
        sip_rownorm<<<M0, 256>>>(p_lat, p_xn, LD, ca_g + d);
        sip_mma<64,64,16,32,32,false,EPI_Q><<<dim3(cdiv(IN_,64),cdiv(M0,64),1),128>>>(
            M0, IN_, LD, p_xn, LD, 0, ca_q + (long)d*LD*IN_, IN_, 0,
            nullptr, 0, 0, nullptr, nullptr, nullptr, ATT_SCALE, nullptr, 1, 0, 1,
            nullptr, nullptr, p_Qh, nullptr, 0);
        sip_mma<128,128,16,64,32,false,EPI_KV|EPI_KV3><<<dim3(cdiv(NKV,128),cdiv(B_*NVOX,128),1),256>>>(
            B_*NVOX, NKV, VC, p_vals, VC, 0, ca_kv + (long)d*ID2*NKV, NKV, 0,
            nullptr, 0, 0, nullptr, nullptr, ca_ctx_g + d, 1.f, nullptr, 1, 0, 1,
            p_EPT + (long)d*96*NKV, p_invn, p_Kh, p_Vh, NVOX);
        // fused flash attention (scores + softmax + AV + head merge)
        sip_flash<<<dim3(NSPL2, B_*HH), 256>>>();
        sip_flash_combine<<<B_*HH*NL, 128>>>();
        sip_mma<64,64,16,32,32,false,EPI_BIAS|EPI_RES><<<dim3(cdiv(LD,64),cdiv(M0,64),1),128>>>(
            M0, LD, IN_, p_AO, IN_, 0, ca_ow + (long)d*IN_*LD, LD, 0,
            p_lat, LD, 0, ca_ob + (long)d*LD, p_lat, nullptr, 1.f, nullptr, 1, 0, 1,
            nullptr, nullptr, nullptr, nullptr, 0);

        // ===== feed-forward (cross) =====
        sip_rownorm<<<M0, 256>>>(p_lat, p_xn, LD, cf_g + d);
        sip_mma<64,64,16,32,32,false,EPI_BIAS|EPI_GELU><<<dim3(cdiv(FF,64),cdiv(M0,64),1),128>>>(
            M0, FF, LD, p_xn, LD, 0, cf_w1 + (long)d*LD*FF, FF, 0,
            p_hid, FF, 0, cf_b1 + (long)d*FF, nullptr, nullptr, 1.f, nullptr, 1, 0, 1,
            nullptr, nullptr, nullptr, nullptr, 0);
        sip_mma<64,64,16,32,32,false,EPI_BIAS|EPI_RES><<<dim3(cdiv(LD,64),cdiv(M0,64),1),128>>>(
            M0, LD, FF, p_hid, FF, 0, cf_w2 + (long)d*FF*LD, LD, 0,
            p_lat, LD, 0, cf_b2 + (long)d*LD, p_lat, nullptr, 1.f, nullptr, 1, 0, 1,
            nullptr, nullptr, nullptr, nullptr, 0);

        // ===== latent self-attention =====
        sip_rownorm<<<M0, 256>>>(p_lat, p_xn, LD, la_g + d);
        sip_mma<64,64,16,32,32,false,EPI_Q><<<dim3(cdiv(IN_,64),cdiv(M0,64),1),128>>>(
            M0, IN_, LD, p_xn, LD, 0, la_q + (long)d*LD*IN_, IN_, 0,
            nullptr, 0, 0, nullptr, nullptr, nullptr, ATT_SCALE, nullptr, 1, 0, 1,
            nullptr, nullptr, p_Qh, nullptr, 0);
        sip_mma<64,64,16,32,32,false,EPI_KV><<<dim3(cdiv(NKV,64),cdiv(M0,64),1),128>>>(
            M0, NKV, LD, p_xn, LD, 0, la_kv + (long)d*LD*NKV, NKV, 0,
            nullptr, 0, 0, nullptr, nullptr, nullptr, 1.f, nullptr, 1, 0, 1,
            nullptr, nullptr, p_Kh, p_Vh, NL);
        sip_mma<64,64,16,32,32,true,0><<<dim3(cdiv(NL,64),cdiv(NL,64),B_*HH),128>>>(
            NL, NL, DH, p_Qh, DH, (long)NL*DH, p_Kh, DH, (long)NL*DH,
            p_S, NL, (long)NL*NL, nullptr, nullptr, nullptr, 1.f, nullptr, 1, 0, 1,
            nullptr, nullptr, nullptr, nullptr, 0);
        sip_softmax<<<B_*HH*NL, 128>>>(p_S, NL);
        sip_mma<128,80,16,64,40,false,0><<<dim3(1,1,B_*HH),128>>>(
            NL, DH, NL, p_S, NL, (long)NL*NL, p_Vh, DH, (long)NL*DH,
            p_AVp, DH, (long)NL*DH, nullptr, nullptr, nullptr, 1.f, nullptr, 1, 0, 1,
            nullptr, nullptr, nullptr, nullptr, 0);
        sip_reduce_av<<<cdiv(B_*NL*IN_,256), 256>>>();
        sip_mma<64,64,16,32,32,false,EPI_BIAS|EPI_RES><<<dim3(cdiv(LD,64),cdiv(M0,64),1),128>>>(
            M0, LD, IN_, p_AO, IN_, 0, la_ow + (long)d*IN_*LD, LD, 0,
            p_lat, LD, 0, la_ob + (long)d*LD, p_lat, nullptr, 1.f, nullptr, 1, 0, 1,
            nullptr, nullptr, nullptr, nullptr, 0);

        // ===== feed-forward (latent) =====
        sip_rownorm<<<M0, 256>>>(p_lat, p_xn, LD, lf_g + d);
        sip_mma<64,64,16,32,32,false,EPI_BIAS|EPI_GELU><<<dim3(cdiv(FF,64),cdiv(M0,64),1),128>>>(
            M0, FF, LD, p_xn, LD, 0, lf_w1 + (long)d*LD*FF, FF, 0,
            p_hid, FF, 0, lf_b1 + (long)d*FF, nullptr, nullptr, 1.f, nullptr, 1, 0, 1,
            nullptr, nullptr, nullptr, nullptr, 0);
        sip_mma<64,64,16,32,32,false,EPI_BIAS|EPI_RES><<<dim3(cdiv(LD,64),cdiv(M0,64),1),128>>>(
            M0, LD, FF, p_hid, FF, 0, lf_w2 + (long)d*FF*LD, LD, 0,
            p_lat, LD, 0, lf_b2 + (long)d*LD, p_lat, nullptr, 1.f, nullptr, 1, 0, 1,
            nullptr, nullptr, nullptr, nullptr, 0);
    }

    // ===== logits + output permute =====
    sip_mma<64,64,16,32,32,false,EPI_BIAS><<<dim3(cdiv(OC,64),cdiv(M0,64),1),128>>>(
        M0, OC, LD, p_lat, LD, 0, logits_w, OC, 0,
        p_logits, OC, 0, logits_b, nullptr, nullptr, 1.f, nullptr, 1, 0, 1,
        nullptr, nullptr, nullptr, nullptr, 0);
    sip_permute_out<<<cdiv(T_*B_*16*OC,256), 256>>>(out);
}

// round 6
// speedup vs baseline: 2.5685x; 1.0447x over previous
#include <cuda_runtime.h>
#include <math.h>
#include <float.h>
#include <stdint.h>

// ---------------- problem constants ----------------
constexpr int B_   = 4;
constexpr int T_   = 8;
constexpr int HH   = 8;
constexpr int DH   = 75;
constexpr int NL   = 128;
constexpr int LD   = 512;
constexpr int ID2  = 435;
constexpr int VC   = 48;
constexpr int IN_  = 600;
constexpr int FF   = 2048;
constexpr int OC   = 64;
constexpr int DEPTH= 5;
constexpr int GH   = 32, GW = 32;
constexpr int NVOX = GH*GW*T_;           // 8192
constexpr int NKV  = 2*IN_;              // 1200
constexpr int NQKV = IN_ + NKV;          // 1800
constexpr float ATT_SCALE = 0.11547005383792515f;

// flash params
constexpr int NSPL2 = 8;
constexpr int DHP   = 80;
constexpr int BKV   = 32;
constexpr int FITERS= (NVOX/NSPL2)/BKV;  // 32

// ---------------- scratch ----------------
__device__ float g_vals [(size_t)B_*NVOX*VC];
__device__ float g_encS [(size_t)96*129];
__device__ float g_ssS  [(size_t)96];
__device__ float g_EPT  [(size_t)DEPTH*96*NKV];
__device__ float g_invn [(size_t)B_*NVOX];
__device__ float g_mask [(size_t)B_*NVOX];
__device__ float g_rsc  [(size_t)B_*NL];
__device__ float g_Wcat [(size_t)DEPTH*LD*NQKV];    // [la_q*scale | la_kv]
__device__ float g_lat  [(size_t)B_*NL*LD];
__device__ float g_Q    [(size_t)B_*NL*IN_];        // cross Q (natural layout)
__device__ float g_KV   [(size_t)B_*NVOX*NKV];      // cross K|V (natural layout)
__device__ float g_QKV  [(size_t)B_*NL*NQKV];       // latent Q|K|V
__device__ float g_S    [(size_t)B_*HH*NL*NL];
__device__ float g_AO   [(size_t)B_*NL*IN_];
__device__ float g_hid  [(size_t)B_*NL*FF];
__device__ float g_logits[(size_t)B_*NL*OC];
// flash partials
__device__ float g_fo   [(size_t)NSPL2*B_*HH*NL*DHP];
__device__ float g_fm   [(size_t)NSPL2*B_*HH*NL];
__device__ float g_fl   [(size_t)NSPL2*B_*HH*NL];

// ---------------- helpers ----------------
__device__ __forceinline__ uint32_t f2tf32(float f){
    uint32_t r; asm("cvt.rna.tf32.f32 %0, %1;" : "=r"(r) : "f"(f)); return r;
}
__device__ __forceinline__ void mma_tf32(float c[4], const uint32_t a[4], const uint32_t b[2]){
    asm("mma.sync.aligned.m16n8k8.row.col.f32.tf32.tf32.f32 "
        "{%0,%1,%2,%3}, {%4,%5,%6,%7}, {%8,%9}, {%0,%1,%2,%3};"
        : "+f"(c[0]), "+f"(c[1]), "+f"(c[2]), "+f"(c[3])
        : "r"(a[0]), "r"(a[1]), "r"(a[2]), "r"(a[3]), "r"(b[0]), "r"(b[1]));
}
// fast exp for x <= 0 (FMA pipe, rel err ~1.5e-5)
__device__ __forceinline__ float fexp(float x){
    float t = x * 1.4426950408889634f;
    t = fmaxf(t, -126.0f);
    float fi = floorf(t);
    float f = t - fi;
    float p = 1.5403530e-4f;
    p = fmaf(p, f, 1.3333558e-3f);
    p = fmaf(p, f, 9.6181291e-3f);
    p = fmaf(p, f, 5.5504109e-2f);
    p = fmaf(p, f, 2.4022651e-1f);
    p = fmaf(p, f, 6.9314718e-1f);
    p = fmaf(p, f, 1.0f);
    return p * __int_as_float(((int)fi + 127) << 23);
}

// ---------------- epilogue flags ----------------
#define EPI_BIAS 1
#define EPI_GELU 2
#define EPI_RES  4
#define EPI_KV3  8     // add 3 factored enc@We tables (jj = gm % NVOX)
// BHM bits: 1=A per-(b,h) offset, 2=B per-(b,h), 4=C per-(b,h)

// ---------------- tf32 tensor-core GEMM with fused epilogues ----------------
template<int BM,int BN,int BK,int WM,int WN,bool TB,int EPI,int BHM>
__global__ void __launch_bounds__((BM/WM)*(BN/WN)*32)
sip_mma(int M,int N,int K,
        const float* __restrict__ A,int lda,long sA,
        const float* __restrict__ ascale,
        const float* __restrict__ Bp,int ldb,long sB,
        float* __restrict__ C,int ldc,long sC,
        const float* __restrict__ bias,
        const float* __restrict__ resid,
        const float* __restrict__ alphaPtr,float alphaC,
        const float* __restrict__ ep,
        const float* __restrict__ rowscale)
{
    constexpr int NWARP = (BM/WM)*(BN/WN);
    constexpr int NT = NWARP*32;
    constexpr int LDA = BM + 4;
    constexpr int LDB = BN + 4;
    __shared__ uint32_t As[BK][LDA];
    __shared__ uint32_t Bs[BK][LDB];

    int tid = threadIdx.x;
    int batch = blockIdx.z;
    int b2 = batch / HH, h2 = batch - b2*HH;
    const float* Ab = A + ((BHM & 1) ? ((long)b2*sA + (long)h2*DH) : (long)batch*sA);
    const float* Bb = Bp + ((BHM & 2) ? ((long)b2*sB + (long)h2*DH) : (long)batch*sB);
    int row0 = blockIdx.y * BM, col0 = blockIdx.x * BN;
    int wid = tid >> 5, lane = tid & 31;
    int g = lane >> 2, tig = lane & 3;
    int wm0 = (wid % (BM/WM)) * WM;
    int wn0 = (wid / (BM/WM)) * WN;
    constexpr int MT = WM/16, NTN = WN/8;

    float acc[MT][NTN][4];
#pragma unroll
    for (int i=0;i<MT;i++)
#pragma unroll
        for (int j=0;j<NTN;j++)
#pragma unroll
            for (int r=0;r<4;r++) acc[i][j][r] = 0.f;

    constexpr int AE = BM*BK/NT;
    constexpr int BE = BN*BK/NT;

    for (int kt = 0; kt < K; kt += BK){
#pragma unroll
        for (int e=0;e<AE;e++){
            int idx = e*NT + tid;
            int m = idx / BK, k = idx % BK;
            int gm = row0 + m, gk = kt + k;
            float v = (gm < M && gk < K) ? Ab[(long)gm*lda + gk] : 0.f;
            if (ascale && gm < M) v *= ascale[gm];
            As[k][m] = f2tf32(v);
        }
#pragma unroll
        for (int e=0;e<BE;e++){
            int idx = e*NT + tid;
            if (TB){
                int n = idx / BK, k = idx % BK;
                int gn = col0 + n, gk = kt + k;
                float v = (gn < N && gk < K) ? Bb[(long)gn*ldb + gk] : 0.f;
                Bs[k][n] = f2tf32(v);
            } else {
                int k = idx / BN, n = idx % BN;
                int gn = col0 + n, gk = kt + k;
                float v = (gn < N && gk < K) ? Bb[(long)gk*ldb + gn] : 0.f;
                Bs[k][n] = f2tf32(v);
            }
        }
        __syncthreads();
#pragma unroll
        for (int ks=0; ks<BK/8; ks++){
            uint32_t af[MT][4], bf[NTN][2];
#pragma unroll
            for (int mt=0; mt<MT; mt++){
                int mb = wm0 + mt*16;
                af[mt][0] = As[ks*8 + tig    ][mb + g    ];
                af[mt][1] = As[ks*8 + tig    ][mb + g + 8];
                af[mt][2] = As[ks*8 + tig + 4][mb + g    ];
                af[mt][3] = As[ks*8 + tig + 4][mb + g + 8];
            }
#pragma unroll
            for (int nt=0; nt<NTN; nt++){
                int nb = wn0 + nt*8;
                bf[nt][0] = Bs[ks*8 + tig    ][nb + g];
                bf[nt][1] = Bs[ks*8 + tig + 4][nb + g];
            }
#pragma unroll
            for (int mt=0; mt<MT; mt++)
#pragma unroll
                for (int nt=0; nt<NTN; nt++)
                    mma_tf32(acc[mt][nt], af[mt], bf[nt]);
        }
        __syncthreads();
    }

    float alpha = alphaC;
    if (alphaPtr) alpha *= alphaPtr[0];

    float* Cb = C + ((BHM & 4) ? ((long)b2*sC + (long)h2*DH) : (long)batch*sC);
    const float* Rb = (EPI & EPI_RES) ? resid + (long)batch * sC : nullptr;
#pragma unroll
    for (int mt=0; mt<MT; mt++)
#pragma unroll
    for (int r2=0; r2<2; r2++){
        int gm = row0 + wm0 + mt*16 + g + r2*8;
        if (gm >= M) continue;
        float rs = alpha;
        const float *e0=nullptr,*e1=nullptr,*e2=nullptr;
        if (EPI & EPI_KV3){
            int jj = gm % NVOX;
            int y = jj>>8, xx = (jj>>3)&31, t = jj&7;
            e0 = ep + (long)y*NKV;
            e1 = ep + (long)(32+xx)*NKV;
            e2 = ep + (long)(64+t)*NKV;
            if (rowscale) rs *= rowscale[gm];
        }
#pragma unroll
        for (int nt=0; nt<NTN; nt++)
#pragma unroll
        for (int c2=0; c2<2; c2++){
            int gn = col0 + wn0 + nt*8 + tig*2 + c2;
            if (gn >= N) continue;
            float v = acc[mt][nt][r2*2 + c2];
            if (EPI & EPI_KV3) v += e0[gn] + e1[gn] + e2[gn];
            v *= rs;
            if (EPI & EPI_BIAS) v += bias[gn];
            if (EPI & EPI_GELU) v = 0.5f * v * (1.f + erff(v * 0.7071067811865476f));
            if (EPI & EPI_RES)  v += Rb[(long)gm*ldc + gn];
            Cb[(long)gm*ldc + gn] = v;
        }
    }
}

// ---------------- fused cross-attention flash kernel (split-KV) ----------------
__global__ void __launch_bounds__(256)
sip_flash()
{
    __shared__ uint32_t Ks[DHP][BKV+8];
    __shared__ uint32_t Vs[BKV][DHP+4];
    __shared__ uint32_t Ps[NL][BKV+4];
    __shared__ float msk[BKV];

    int split = blockIdx.x, bh = blockIdx.y;
    int b = bh / HH, h = bh - b*HH;
    int tid = threadIdx.x, w = tid>>5, lane = tid&31;
    int g = lane>>2, tig = lane&3;
    int kv0 = split * (NVOX/NSPL2);

    uint32_t qf[10][4];
    {
        const float* Qb = g_Q + (long)b*NL*IN_ + (long)h*DH;
        int r0 = w*16 + g;
#pragma unroll
        for (int ks=0; ks<10; ks++){
            int c0 = ks*8 + tig;
            float v00 = (c0   < DH) ? Qb[(long)r0*IN_ + c0]       : 0.f;
            float v10 = (c0   < DH) ? Qb[(long)(r0+8)*IN_ + c0]   : 0.f;
            float v01 = (c0+4 < DH) ? Qb[(long)r0*IN_ + c0+4]     : 0.f;
            float v11 = (c0+4 < DH) ? Qb[(long)(r0+8)*IN_ + c0+4] : 0.f;
            qf[ks][0]=f2tf32(v00); qf[ks][1]=f2tf32(v10);
            qf[ks][2]=f2tf32(v01); qf[ks][3]=f2tf32(v11);
        }
    }

    float o[10][4];
#pragma unroll
    for (int nt=0;nt<10;nt++)
#pragma unroll
        for (int r=0;r<4;r++) o[nt][r]=0.f;
    float mrun[2] = {-FLT_MAX, -FLT_MAX};
    float lrun[2] = {0.f, 0.f};

    const float* Kb = g_KV + (long)b*NVOX*NKV + (long)h*DH;
    const float* Vb = Kb + IN_;
    const float* Mb = g_mask + (long)b*NVOX;

    for (int it=0; it<FITERS; it++){
        int j0 = kv0 + it*BKV;
#pragma unroll
        for (int e=0;e<10;e++){
            int idx = e*256 + tid;
            int r = idx / DHP, c = idx - r*DHP;
            float kv = (c < DH) ? Kb[(long)(j0+r)*NKV + c] : 0.f;
            Ks[c][r] = f2tf32(kv);
            float vv = (c < DH) ? Vb[(long)(j0+r)*NKV + c] : 0.f;
            Vs[r][c] = f2tf32(vv);
        }
        if (tid < BKV) msk[tid] = Mb[j0 + tid];
        __syncthreads();

        float s[4][4];
#pragma unroll
        for (int nt=0;nt<4;nt++)
#pragma unroll
            for (int r=0;r<4;r++) s[nt][r]=0.f;
#pragma unroll
        for (int ks=0; ks<10; ks++){
            uint32_t bfr[4][2];
#pragma unroll
            for (int nt=0;nt<4;nt++){
                bfr[nt][0] = Ks[ks*8 + tig    ][nt*8 + g];
                bfr[nt][1] = Ks[ks*8 + tig + 4][nt*8 + g];
            }
#pragma unroll
            for (int nt=0;nt<4;nt++) mma_tf32(s[nt], qf[ks], bfr[nt]);
        }
#pragma unroll
        for (int nt=0;nt<4;nt++)
#pragma unroll
        for (int r=0;r<4;r++){
            int jl = nt*8 + tig*2 + (r & 1);
            if (msk[jl] < 0.5f) s[nt][r] = -FLT_MAX;
        }
#pragma unroll
        for (int r2=0;r2<2;r2++){
            float mx = -FLT_MAX;
#pragma unroll
            for (int nt=0;nt<4;nt++){
                mx = fmaxf(mx, s[nt][r2*2+0]);
                mx = fmaxf(mx, s[nt][r2*2+1]);
            }
            mx = fmaxf(mx, __shfl_xor_sync(0xffffffffu, mx, 1));
            mx = fmaxf(mx, __shfl_xor_sync(0xffffffffu, mx, 2));
            float mnew = fmaxf(mrun[r2], mx);
            float sc = fexp(mrun[r2] - mnew);
            mrun[r2] = mnew;
            lrun[r2] *= sc;
#pragma unroll
            for (int nt=0;nt<10;nt++){
                o[nt][r2*2+0] *= sc;
                o[nt][r2*2+1] *= sc;
            }
            float ps = 0.f;
#pragma unroll
            for (int nt=0;nt<4;nt++){
                float p0 = fexp(s[nt][r2*2+0] - mnew);
                float p1 = fexp(s[nt][r2*2+1] - mnew);
                s[nt][r2*2+0] = p0; s[nt][r2*2+1] = p1;
                ps += p0 + p1;
            }
            ps += __shfl_xor_sync(0xffffffffu, ps, 1);
            ps += __shfl_xor_sync(0xffffffffu, ps, 2);
            lrun[r2] += ps;
        }
#pragma unroll
        for (int nt=0;nt<4;nt++)
#pragma unroll
        for (int r=0;r<4;r++){
            int row = w*16 + g + (r>>1)*8;
            int col = nt*8 + tig*2 + (r&1);
            Ps[row][col] = f2tf32(s[nt][r]);
        }
        __syncwarp();
#pragma unroll
        for (int ks=0; ks<4; ks++){
            uint32_t af[4];
            af[0] = Ps[w*16 + g    ][ks*8 + tig    ];
            af[1] = Ps[w*16 + g + 8][ks*8 + tig    ];
            af[2] = Ps[w*16 + g    ][ks*8 + tig + 4];
            af[3] = Ps[w*16 + g + 8][ks*8 + tig + 4];
#pragma unroll
            for (int nt=0;nt<10;nt++){
                uint32_t bfr[2];
                bfr[0] = Vs[ks*8 + tig    ][nt*8 + g];
                bfr[1] = Vs[ks*8 + tig + 4][nt*8 + g];
                mma_tf32(o[nt], af, bfr);
            }
        }
        __syncthreads();
    }

    long base = ((long)split*B_*HH + bh) * NL;
#pragma unroll
    for (int r2=0;r2<2;r2++){
        int row = w*16 + g + r2*8;
        if (tig == 0){
            g_fm[base + row] = mrun[r2];
            g_fl[base + row] = lrun[r2];
        }
#pragma unroll
        for (int nt=0;nt<10;nt++){
            g_fo[(base + row)*DHP + nt*8 + tig*2 + 0] = o[nt][r2*2+0];
            g_fo[(base + row)*DHP + nt*8 + tig*2 + 1] = o[nt][r2*2+1];
        }
    }
}

// ---------------- flash split combine + head merge -> AO ----------------
__global__ void sip_flash_combine()
{
    int blk = blockIdx.x;
    int bh = blk / NL, row = blk - bh*NL;
    int b = bh / HH, h = bh - b*HH;
    int tid = threadIdx.x;           // 128
    __shared__ float sm[NSPL2], sl[NSPL2];
    __shared__ float sms, sden;
    if (tid < NSPL2){
        long idx = ((long)tid*B_*HH + bh)*NL + row;
        sm[tid] = g_fm[idx];
        sl[tid] = g_fl[idx];
    }
    __syncthreads();
    if (tid == 0){
        float mx = sm[0];
#pragma unroll
        for (int s2=1;s2<NSPL2;s2++) mx = fmaxf(mx, sm[s2]);
        float den = 0.f;
#pragma unroll
        for (int s2=0;s2<NSPL2;s2++) den += sl[s2] * fexp(sm[s2] - mx);
        sms = mx; sden = den;
    }
    __syncthreads();
    if (tid < DH){
        float acc = 0.f;
#pragma unroll
        for (int s2=0;s2<NSPL2;s2++){
            float wgt = fexp(sm[s2] - sms);
            acc += g_fo[(((long)s2*B_*HH + bh)*NL + row)*DHP + tid] * wgt;
        }
        g_AO[((long)b*NL + row)*IN_ + h*DH + tid] = acc / sden;
    }
}

// ---------------- separable fourier features ----------------
__global__ void sip_build_encsmall()
{
    int ri = blockIdx.x;
    int a = ri >> 5, v = ri & 31;
    float dim = (a == 2) ? 8.f : 32.f;
    float x = 2.f*v/dim - 1.f;
    int tid = threadIdx.x;               // 160
    __shared__ float sh[5];
    float val = 0.f;
    if (tid < 129){
        int r = tid;
        if (r < 64)        val = sinf(x * exp2f((float)(-r)));
        else if (r < 128)  val = cosf(x * exp2f((float)(64 - r)));
        else               val = x;
        g_encS[ri*129 + tid] = val;
    }
    float ss = val*val;
    for (int o=16;o>0;o>>=1) ss += __shfl_xor_sync(0xffffffffu, ss, o);
    if ((tid & 31) == 0) sh[tid>>5] = ss;
    __syncthreads();
    if (tid == 0) g_ssS[ri] = sh[0]+sh[1]+sh[2]+sh[3]+sh[4];
}

// ---------------- factored EP tables, W read once ----------------
__global__ void __launch_bounds__(256)
sip_ep2(const float* __restrict__ kvw)
{
    __shared__ float E[32][130];
    int a = blockIdx.y, d = blockIdx.z;
    int tid = threadIdx.x;
    for (int i = tid; i < 32*129; i += 256){
        int r = i / 129, cc = i - r*129;
        E[r][cc] = g_encS[(a*32 + r)*129 + cc];
    }
    __syncthreads();
    int c = blockIdx.x*64 + (tid & 63);
    int rg = tid >> 6;                   // 0..3 -> rows rg*8..rg*8+7
    if (c >= NKV) return;
    const float* W = kvw + (long)d*ID2*NKV + (long)(VC + a*129)*NKV + c;
    float acc[8];
#pragma unroll
    for (int k=0;k<8;k++) acc[k] = 0.f;
    for (int r=0;r<129;r++){
        float w = W[(long)r*NKV];
#pragma unroll
        for (int k=0;k<8;k++) acc[k] = fmaf(E[rg*8+k][r], w, acc[k]);
    }
#pragma unroll
    for (int k=0;k<8;k++)
        g_EPT[((long)d*96 + a*32 + rg*8 + k)*NKV + c] = acc[k];
}

// ---------------- latent weight concat: [la_q*scale | la_kv] ----------------
__global__ void sip_build_wcat(const float* __restrict__ laq, const float* __restrict__ lakv)
{
    long idx = (long)blockIdx.x * blockDim.x + threadIdx.x;
    long total = (long)DEPTH*LD*NQKV;
    if (idx >= total) return;
    int c = (int)(idx % NQKV);
    long r = idx / NQKV;
    int k = (int)(r % LD);
    int d = (int)(r / LD);
    g_Wcat[idx] = (c < IN_) ? laq[((long)d*LD + k)*IN_ + c] * ATT_SCALE
                            : lakv[((long)d*LD + k)*NKV + (c - IN_)];
}

// ---------------- vals(b,n,48), invn, mask ----------------
__global__ void sip_build_vals(const float* __restrict__ input)
{
    int vox = blockIdx.x;
    int b = vox / NVOX, n = vox % NVOX;
    int hy = n / (GW*T_), wx = (n / T_) % GW, tt = n % T_;
    int tid = threadIdx.x;               // 64
    __shared__ float ssh[2], msh[2];
    float val = 0.f;
    if (tid < VC){
        int py = tid/12, px = (tid/3)%4, c = tid%3;
        val = input[(((long)tt*B_ + b)*3 + c)*16384 + (hy*4+py)*128 + (wx*4+px)];
        g_vals[(long)vox*VC + tid] = val;
    }
    float ss = val*val;
    float mx = (tid < VC) ? val : -FLT_MAX;
    for (int o=16;o>0;o>>=1){
        ss += __shfl_xor_sync(0xffffffffu, ss, o);
        mx = fmaxf(mx, __shfl_xor_sync(0xffffffffu, mx, o));
    }
    if ((tid & 31) == 0){ ssh[tid>>5] = ss; msh[tid>>5] = mx; }
    __syncthreads();
    if (tid == 0){
        float tot = ssh[0] + ssh[1] + g_ssS[hy] + g_ssS[32+wx] + g_ssS[64+tt];
        g_invn[vox] = 1.f / fmaxf(sqrtf(tot), 1e-5f);
        float m = fmaxf(msh[0], msh[1]);
        g_mask[vox] = (fabsf(m) > 0.3f) ? 1.f : 0.f;
    }
}

// ---------------- per-row scale (gain / L2 norm), warp per row ----------------
__global__ void sip_rowscale(const float* __restrict__ in, float* __restrict__ rsc,
                             const float* __restrict__ gptr)
{
    int row = blockIdx.x*8 + (threadIdx.x >> 5);
    int lane = threadIdx.x & 31;
    const float* p = in + (long)row*LD;
    float s = 0.f;
    for (int j = lane; j < LD; j += 32){ float v = p[j]; s += v*v; }
    for (int o=16;o>0;o>>=1) s += __shfl_xor_sync(0xffffffffu, s, o);
    if (lane == 0) rsc[row] = gptr[0] / fmaxf(sqrtf(s), 1e-5f);
}

// ---------------- softmax (latent path; full normalize) ----------------
__global__ void sip_softmax(float* __restrict__ S, int cols)
{
    long row = blockIdx.x;
    float* p = S + row * (long)cols;
    __shared__ float sh[8];
    int tid = threadIdx.x;
    int nw = blockDim.x >> 5;
    float m = -FLT_MAX;
    for (int j = tid; j < cols; j += blockDim.x) m = fmaxf(m, p[j]);
    for (int o=16;o>0;o>>=1) m = fmaxf(m, __shfl_xor_sync(0xffffffffu, m, o));
    if ((tid & 31) == 0) sh[tid>>5] = m;
    __syncthreads();
    float mm = sh[0];
    for (int w=1; w<nw; w++) mm = fmaxf(mm, sh[w]);
    __syncthreads();
    float s = 0.f;
    for (int j = tid; j < cols; j += blockDim.x){
        float e = fexp(p[j] - mm);
        p[j] = e; s += e;
    }
    for (int o=16;o>0;o>>=1) s += __shfl_xor_sync(0xffffffffu, s, o);
    if ((tid & 31) == 0) sh[tid>>5] = s;
    __syncthreads();
    float tot = 0.f;
    for (int w=0; w<nw; w++) tot += sh[w];
    float inv = 1.f / tot;
    for (int j = tid; j < cols; j += blockDim.x) p[j] *= inv;
}

__global__ void sip_init_lat(const float* __restrict__ latents, const float* __restrict__ pos)
{
    long idx = (long)blockIdx.x * blockDim.x + threadIdx.x;
    if (idx >= (long)B_*NL*LD) return;
    int r = (int)(idx % (NL*LD));
    g_lat[idx] = latents[r] + pos[r];
}

__global__ void sip_permute_out(float* __restrict__ out)
{
    long idx = (long)blockIdx.x * blockDim.x + threadIdx.x;
    if (idx >= (long)T_*B_*16*OC) return;
    int o = (int)(idx % OC);
    long r = idx / OC;
    int nn = (int)(r % 16); r /= 16;
    int b = (int)(r % B_);
    int tt = (int)(r / B_);
    out[idx] = g_logits[((long)b*NL + nn*T_ + tt)*OC + o];
}

// ---------------- host ----------------
static inline int cdiv(int a, int b){ return (a + b - 1) / b; }

extern "C" void kernel_launch(void* const* d_in, const int* in_sizes, int n_in,
                              void* d_out, int out_size)
{
    const float* input    = (const float*)d_in[0];
    const float* latents  = (const float*)d_in[1];
    const float* pos_emb  = (const float*)d_in[2];
    const float* ca_g     = (const float*)d_in[3];
    const float* ca_ctx_g = (const float*)d_in[4];
    const float* ca_q     = (const float*)d_in[5];
    const float* ca_kv    = (const float*)d_in[6];
    const float* ca_ow    = (const float*)d_in[7];
    const float* ca_ob    = (const float*)d_in[8];
    const float* cf_g     = (const float*)d_in[9];
    const float* cf_w1    = (const float*)d_in[10];
    const float* cf_b1    = (const float*)d_in[11];
    const float* cf_w2    = (const float*)d_in[12];
    const float* cf_b2    = (const float*)d_in[13];
    const float* la_g     = (const float*)d_in[14];
    const float* la_q     = (const float*)d_in[15];
    const float* la_kv    = (const float*)d_in[16];
    const float* la_ow    = (const float*)d_in[17];
    const float* la_ob    = (const float*)d_in[18];
    const float* lf_g     = (const float*)d_in[19];
    const float* lf_w1    = (const float*)d_in[20];
    const float* lf_b1    = (const float*)d_in[21];
    const float* lf_w2    = (const float*)d_in[22];
    const float* lf_b2    = (const float*)d_in[23];
    const float* logits_w = (const float*)d_in[24];
    const float* logits_b = (const float*)d_in[25];
    float* out = (float*)d_out;

    float *p_vals,*p_EPT,*p_invn,*p_rsc,*p_Wcat,*p_lat,*p_Q,*p_KV,*p_QKV,*p_S,*p_AO,*p_hid,*p_logits;
#define SYM(p, s) do{ void* _t=nullptr; cudaGetSymbolAddress(&_t, s); p=(float*)_t; }while(0)
    SYM(p_vals, g_vals); SYM(p_EPT, g_EPT); SYM(p_invn, g_invn); SYM(p_rsc, g_rsc);
    SYM(p_Wcat, g_Wcat); SYM(p_lat, g_lat);
    SYM(p_Q, g_Q); SYM(p_KV, g_KV); SYM(p_QKV, g_QKV);
    SYM(p_S, g_S); SYM(p_AO, g_AO); SYM(p_hid, g_hid); SYM(p_logits, g_logits);
#undef SYM

    const int M0 = B_*NL;  // 512

    // -------- preamble --------
    sip_build_encsmall<<<96, 160>>>();
    sip_ep2<<<dim3(cdiv(NKV,64), 3, DEPTH), 256>>>(ca_kv);
    sip_build_vals<<<B_*NVOX, 64>>>(input);
    sip_init_lat<<<cdiv(B_*NL*LD,256), 256>>>(latents, pos_emb);
    sip_build_wcat<<<cdiv(DEPTH*LD*NQKV,256), 256>>>(la_q, la_kv);

    for (int d = 0; d < DEPTH; d++){
        // ===== cross attention =====
        sip_rowscale<<<64, 256>>>(p_lat, p_rsc, ca_g + d);
        // Q = (lat*rsc) @ ca_q * ATT_SCALE  -> (b,i,600)
        sip_mma<64,64,16,32,32,false,0,0><<<dim3(cdiv(IN_,64),cdiv(M0,64),1),128>>>(
            M0, IN_, LD, p_lat, LD, 0, p_rsc, ca_q + (long)d*LD*IN_, IN_, 0,
            p_Q, IN_, 0, nullptr, nullptr, nullptr, ATT_SCALE, nullptr, nullptr);
        // KV = (vals @ Wv + EP) * invn * g  -> (b,j,1200)
        sip_mma<128,128,16,64,32,false,EPI_KV3,0><<<dim3(cdiv(NKV,128),cdiv(B_*NVOX,128),1),256>>>(
            B_*NVOX, NKV, VC, p_vals, VC, 0, nullptr, ca_kv + (long)d*ID2*NKV, NKV, 0,
            p_KV, NKV, 0, nullptr, nullptr, ca_ctx_g + d, 1.f,
            p_EPT + (long)d*96*NKV, p_invn);
        sip_flash<<<dim3(NSPL2, B_*HH), 256>>>();
        sip_flash_combine<<<B_*HH*NL, 128>>>();
        sip_mma<64,64,16,32,32,false,EPI_BIAS|EPI_RES,0><<<dim3(cdiv(LD,64),cdiv(M0,64),1),128>>>(
            M0, LD, IN_, p_AO, IN_, 0, nullptr, ca_ow + (long)d*IN_*LD, LD, 0,
            p_lat, LD, 0, ca_ob + (long)d*LD, p_lat, nullptr, 1.f, nullptr, nullptr);

        // ===== feed-forward (cross) =====
        sip_rowscale<<<64, 256>>>(p_lat, p_rsc, cf_g + d);
        sip_mma<64,64,16,32,32,false,EPI_BIAS|EPI_GELU,0><<<dim3(cdiv(FF,64),cdiv(M0,64),1),128>>>(
            M0, FF, LD, p_lat, LD, 0, p_rsc, cf_w1 + (long)d*LD*FF, FF, 0,
            p_hid, FF, 0, cf_b1 + (long)d*FF, nullptr, nullptr, 1.f, nullptr, nullptr);
        sip_mma<64,64,16,32,32,false,EPI_BIAS|EPI_RES,0><<<dim3(cdiv(LD,64),cdiv(M0,64),1),128>>>(
            M0, LD, FF, p_hid, FF, 0, nullptr, cf_w2 + (long)d*FF*LD, LD, 0,
            p_lat, LD, 0, cf_b2 + (long)d*LD, p_lat, nullptr, 1.f, nullptr, nullptr);

        // ===== latent self-attention =====
        sip_rowscale<<<64, 256>>>(p_lat, p_rsc, la_g + d);
        // QKV = (lat*rsc) @ Wcat -> (b,i,1800)
        sip_mma<64,64,16,32,32,false,0,0><<<dim3(cdiv(NQKV,64),cdiv(M0,64),1),128>>>(
            M0, NQKV, LD, p_lat, LD, 0, p_rsc, p_Wcat + (long)d*LD*NQKV, NQKV, 0,
            p_QKV, NQKV, 0, nullptr, nullptr, nullptr, 1.f, nullptr, nullptr);
        // S = Q @ K^T (per b,h)
        sip_mma<64,64,16,32,32,true,0,3><<<dim3(2,2,B_*HH),128>>>(
            NL, NL, DH, p_QKV, NQKV, (long)NL*NQKV, nullptr,
            p_QKV + IN_, NQKV, (long)NL*NQKV,
            p_S, NL, (long)NL*NL, nullptr, nullptr, nullptr, 1.f, nullptr, nullptr);
        sip_softmax<<<B_*HH*NL, 128>>>(p_S, NL);
        // AO = P @ V (per b,h), write head-merged
        sip_mma<128,80,16,64,40,false,0,6><<<dim3(1,1,B_*HH),128>>>(
            NL, DH, NL, p_S, NL, (long)NL*NL, nullptr,
            p_QKV + NKV, NQKV, (long)NL*NQKV,
            p_AO, IN_, (long)NL*IN_, nullptr, nullptr, nullptr, 1.f, nullptr, nullptr);
        sip_mma<64,64,16,32,32,false,EPI_BIAS|EPI_RES,0><<<dim3(cdiv(LD,64),cdiv(M0,64),1),128>>>(
            M0, LD, IN_, p_AO, IN_, 0, nullptr, la_ow + (long)d*IN_*LD, LD, 0,
            p_lat, LD, 0, la_ob + (long)d*LD, p_lat, nullptr, 1.f, nullptr, nullptr);

        // ===== feed-forward (latent) =====
        sip_rowscale<<<64, 256>>>(p_lat, p_rsc, lf_g + d);
        sip_mma<64,64,16,32,32,false,EPI_BIAS|EPI_GELU,0><<<dim3(cdiv(FF,64),cdiv(M0,64),1),128>>>(
            M0, FF, LD, p_lat, LD, 0, p_rsc, lf_w1 + (long)d*LD*FF, FF, 0,
            p_hid, FF, 0, lf_b1 + (long)d*FF, nullptr, nullptr, 1.f, nullptr, nullptr);
        sip_mma<64,64,16,32,32,false,EPI_BIAS|EPI_RES,0><<<dim3(cdiv(LD,64),cdiv(M0,64),1),128>>>(
            M0, LD, FF, p_hid, FF, 0, nullptr, lf_w2 + (long)d*FF*LD, LD, 0,
            p_lat, LD, 0, lf_b2 + (long)d*LD, p_lat, nullptr, 1.f, nullptr, nullptr);
    }

    // ===== logits + output permute =====
    sip_mma<64,64,16,32,32,false,EPI_BIAS,0><<<dim3(cdiv(OC,64),cdiv(M0,64),1),128>>>(
        M0, OC, LD, p_lat, LD, 0, nullptr, logits_w, OC, 0,
        p_logits, OC, 0, logits_b, nullptr, nullptr, 1.f, nullptr, nullptr);
    sip_permute_out<<<cdiv(T_*B_*16*OC,256), 256>>>(out);
}

// round 7
// speedup vs baseline: 4.4857x; 1.7464x over previous
#include <cuda_runtime.h>
#include <math.h>
#include <float.h>
#include <stdint.h>

// ---------------- problem constants ----------------
constexpr int B_   = 4;
constexpr int T_   = 8;
constexpr int HH   = 8;
constexpr int DH   = 75;
constexpr int NL   = 128;
constexpr int LD   = 512;
constexpr int ID2  = 435;
constexpr int VC   = 48;
constexpr int IN_  = 600;
constexpr int FF   = 2048;
constexpr int OC   = 64;
constexpr int DEPTH= 5;
constexpr int GH   = 32, GW = 32;
constexpr int NVOX = GH*GW*T_;           // 8192
constexpr int NKV  = 2*IN_;              // 1200
constexpr int NQKV = IN_ + NKV;          // 1800
constexpr float ATT_SCALE = 0.11547005383792515f;

// flash params
constexpr int NSPL2 = 8;
constexpr int DHP   = 80;
constexpr int BKV   = 32;
constexpr int FITERS= (NVOX/NSPL2)/BKV;  // 32

// ---------------- scratch ----------------
__device__ float g_vals [(size_t)B_*NVOX*VC];
__device__ float g_encS [(size_t)96*129];
__device__ float g_ssS  [(size_t)96];
__device__ float g_EPT  [(size_t)DEPTH*96*NKV];
__device__ float g_invn [(size_t)B_*NVOX];
__device__ float g_mask [(size_t)B_*NVOX];
__device__ float g_rsc  [(size_t)B_*NL];
__device__ float g_Wcat [(size_t)DEPTH*LD*NQKV];
__device__ float g_lat  [(size_t)B_*NL*LD];
__device__ float g_Q    [(size_t)B_*NL*IN_];
__device__ float g_KV   [(size_t)B_*NVOX*NKV];
__device__ float g_QKV  [(size_t)B_*NL*NQKV];
__device__ float g_S    [(size_t)B_*HH*NL*NL];
__device__ float g_AO   [(size_t)B_*NL*IN_];
__device__ float g_hid  [(size_t)B_*NL*FF];
__device__ float g_logits[(size_t)B_*NL*OC];
__device__ float g_fo   [(size_t)NSPL2*B_*HH*NL*DHP];
__device__ float g_fm   [(size_t)NSPL2*B_*HH*NL];
__device__ float g_fl   [(size_t)NSPL2*B_*HH*NL];

// ---------------- helpers ----------------
__device__ __forceinline__ uint32_t f2tf32(float f){
    uint32_t r; asm("cvt.rna.tf32.f32 %0, %1;" : "=r"(r) : "f"(f)); return r;
}
__device__ __forceinline__ void mma_tf32(float c[4], const uint32_t a[4], const uint32_t b[2]){
    asm("mma.sync.aligned.m16n8k8.row.col.f32.tf32.tf32.f32 "
        "{%0,%1,%2,%3}, {%4,%5,%6,%7}, {%8,%9}, {%0,%1,%2,%3};"
        : "+f"(c[0]), "+f"(c[1]), "+f"(c[2]), "+f"(c[3])
        : "r"(a[0]), "r"(a[1]), "r"(a[2]), "r"(a[3]), "r"(b[0]), "r"(b[1]));
}
__device__ __forceinline__ void cpa16(float* dst, const float* src, int bytes){
    uint32_t d = (uint32_t)__cvta_generic_to_shared(dst);
    asm volatile("cp.async.ca.shared.global [%0], [%1], 16, %2;" :: "r"(d), "l"(src), "r"(bytes));
}
__device__ __forceinline__ void cpa4(float* dst, const float* src, int bytes){
    uint32_t d = (uint32_t)__cvta_generic_to_shared(dst);
    asm volatile("cp.async.ca.shared.global [%0], [%1], 4, %2;" :: "r"(d), "l"(src), "r"(bytes));
}
// fast exp for x <= 0 (FMA pipe)
__device__ __forceinline__ float fexp(float x){
    float t = x * 1.4426950408889634f;
    t = fmaxf(t, -126.0f);
    float fi = floorf(t);
    float f = t - fi;
    float p = 1.5403530e-4f;
    p = fmaf(p, f, 1.3333558e-3f);
    p = fmaf(p, f, 9.6181291e-3f);
    p = fmaf(p, f, 5.5504109e-2f);
    p = fmaf(p, f, 2.4022651e-1f);
    p = fmaf(p, f, 6.9314718e-1f);
    p = fmaf(p, f, 1.0f);
    return p * __int_as_float(((int)fi + 127) << 23);
}

// ---------------- epilogue flags ----------------
#define EPI_BIAS 1
#define EPI_GELU 2
#define EPI_RES  4
#define EPI_KV3  8
// BHM bits: 1=A per-(b,h) offset, 2=B per-(b,h), 4=C per-(b,h)

// ---------------- pipelined tf32 GEMM (cp.async double buffer) ----------------
template<int BM,int BN,int BK,int WM,int WN,bool TB,int EPI,int BHM,int VEC>
__global__ void __launch_bounds__((BM/WM)*(BN/WN)*32)
sip_mma(int M,int N,int K,
        const float* __restrict__ A,int lda,long sA,
        const float* __restrict__ ascale,
        const float* __restrict__ Bp,int ldb,long sB,
        float* __restrict__ C,int ldc,long sC,
        const float* __restrict__ bias,
        const float* __restrict__ resid,
        const float* __restrict__ alphaPtr,float alphaC,
        const float* __restrict__ ep,
        const float* __restrict__ rowscale)
{
    constexpr int NWARP = (BM/WM)*(BN/WN);
    constexpr int NT = NWARP*32;
    constexpr int LDA = BK + 4;                    // A stored [m][k]
    constexpr int LDB = TB ? (BK + 4) : (BN + 4);  // B: [n][k] or [k][n]
    constexpr int ASZ = BM*LDA;
    constexpr int BSZ = TB ? BN*LDB : BK*LDB;
    constexpr int VE  = VEC/4;                     // floats per copy
    constexpr int ACP = (BM*BK)/(VE*NT);
    constexpr int BCP = (BN*BK)/(VE*NT);
    __shared__ float As[2][ASZ];
    __shared__ float Bs[2][BSZ];

    int tid = threadIdx.x;
    int batch = blockIdx.z;
    int b2 = batch / HH, h2 = batch - b2*HH;
    const float* Ab = A + ((BHM & 1) ? ((long)b2*sA + (long)h2*DH) : (long)batch*sA);
    const float* Bb = Bp + ((BHM & 2) ? ((long)b2*sB + (long)h2*DH) : (long)batch*sB);
    int row0 = blockIdx.y * BM, col0 = blockIdx.x * BN;
    int wid = tid >> 5, lane = tid & 31;
    int g = lane >> 2, tig = lane & 3;
    int wm0 = (wid % (BM/WM)) * WM;
    int wn0 = (wid / (BM/WM)) * WN;
    constexpr int MT = WM/16, NTN = WN/8;

    float rsA[MT][2];
#pragma unroll
    for (int mt=0; mt<MT; mt++){
        int r0 = row0 + wm0 + mt*16 + g;
        rsA[mt][0] = (ascale && r0   < M) ? ascale[r0]   : 1.f;
        rsA[mt][1] = (ascale && r0+8 < M) ? ascale[r0+8] : 1.f;
    }

    float acc[MT][NTN][4];
#pragma unroll
    for (int i=0;i<MT;i++)
#pragma unroll
        for (int j=0;j<NTN;j++)
#pragma unroll
            for (int r=0;r<4;r++) acc[i][j][r] = 0.f;

    int ktiles = (K + BK - 1) / BK;

    auto loadA = [&](int kt, int buf){
#pragma unroll
        for (int e=0; e<ACP; e++){
            int v = e*NT + tid;
            int m = v / (BK/VE), kq = v - m*(BK/VE);
            int gm = row0 + m, gk = kt + kq*VE;
            const float* src = Ab + (long)gm*lda + gk;
            int bytes = 0;
            if (gm < M && gk < K) bytes = min(K - gk, VE) * 4;
            if (!bytes) src = Ab;
            if (VEC == 16) cpa16(&As[buf][m*LDA + kq*VE], src, bytes);
            else           cpa4 (&As[buf][m*LDA + kq*VE], src, bytes);
        }
    };
    auto loadB = [&](int kt, int buf){
#pragma unroll
        for (int e=0; e<BCP; e++){
            int v = e*NT + tid;
            if (TB){
                int n = v / (BK/VE), kq = v - n*(BK/VE);
                int gn = col0 + n, gk = kt + kq*VE;
                const float* src = Bb + (long)gn*ldb + gk;
                int bytes = 0;
                if (gn < N && gk < K) bytes = min(K - gk, VE) * 4;
                if (!bytes) src = Bb;
                if (VEC == 16) cpa16(&Bs[buf][n*LDB + kq*VE], src, bytes);
                else           cpa4 (&Bs[buf][n*LDB + kq*VE], src, bytes);
            } else {
                int k = v / (BN/VE), nq = v - k*(BN/VE);
                int gn = col0 + nq*VE, gk = kt + k;
                const float* src = Bb + (long)gk*ldb + gn;
                int bytes = 0;
                if (gk < K && gn < N) bytes = min(N - gn, VE) * 4;
                if (!bytes) src = Bb;
                if (VEC == 16) cpa16(&Bs[buf][k*LDB + nq*VE], src, bytes);
                else           cpa4 (&Bs[buf][k*LDB + nq*VE], src, bytes);
            }
        }
    };

    loadA(0, 0); loadB(0, 0);
    asm volatile("cp.async.commit_group;");

    for (int t=0; t<ktiles; t++){
        int cur = t & 1;
        if (t+1 < ktiles){
            loadA((t+1)*BK, cur^1); loadB((t+1)*BK, cur^1);
            asm volatile("cp.async.commit_group;");
            asm volatile("cp.async.wait_group 1;");
        } else {
            asm volatile("cp.async.wait_group 0;");
        }
        __syncthreads();
#pragma unroll
        for (int ks=0; ks<BK/8; ks++){
            uint32_t af[MT][4], bf[NTN][2];
#pragma unroll
            for (int mt=0; mt<MT; mt++){
                int mb = wm0 + mt*16;
                float a0 = As[cur][(mb+g  )*LDA + ks*8 + tig    ];
                float a1 = As[cur][(mb+g+8)*LDA + ks*8 + tig    ];
                float a2 = As[cur][(mb+g  )*LDA + ks*8 + tig + 4];
                float a3 = As[cur][(mb+g+8)*LDA + ks*8 + tig + 4];
                af[mt][0] = f2tf32(a0 * rsA[mt][0]);
                af[mt][1] = f2tf32(a1 * rsA[mt][1]);
                af[mt][2] = f2tf32(a2 * rsA[mt][0]);
                af[mt][3] = f2tf32(a3 * rsA[mt][1]);
            }
#pragma unroll
            for (int nt=0; nt<NTN; nt++){
                int nb = wn0 + nt*8;
                float b0, b1;
                if (TB){
                    b0 = Bs[cur][(nb+g)*LDB + ks*8 + tig    ];
                    b1 = Bs[cur][(nb+g)*LDB + ks*8 + tig + 4];
                } else {
                    b0 = Bs[cur][(ks*8 + tig    )*LDB + nb + g];
                    b1 = Bs[cur][(ks*8 + tig + 4)*LDB + nb + g];
                }
                bf[nt][0] = f2tf32(b0); bf[nt][1] = f2tf32(b1);
            }
#pragma unroll
            for (int mt=0; mt<MT; mt++)
#pragma unroll
                for (int nt=0; nt<NTN; nt++)
                    mma_tf32(acc[mt][nt], af[mt], bf[nt]);
        }
        __syncthreads();
    }

    float alpha = alphaC;
    if (alphaPtr) alpha *= alphaPtr[0];

    float* Cb = C + ((BHM & 4) ? ((long)b2*sC + (long)h2*DH) : (long)batch*sC);
    const float* Rb = (EPI & EPI_RES) ? resid + (long)batch * sC : nullptr;
#pragma unroll
    for (int mt=0; mt<MT; mt++)
#pragma unroll
    for (int r2=0; r2<2; r2++){
        int gm = row0 + wm0 + mt*16 + g + r2*8;
        if (gm >= M) continue;
        float rs = alpha;
        const float *e0=nullptr,*e1=nullptr,*e2=nullptr;
        if (EPI & EPI_KV3){
            int jj = gm % NVOX;
            int y = jj>>8, xx = (jj>>3)&31, t = jj&7;
            e0 = ep + (long)y*NKV;
            e1 = ep + (long)(32+xx)*NKV;
            e2 = ep + (long)(64+t)*NKV;
            if (rowscale) rs *= rowscale[gm];
        }
#pragma unroll
        for (int nt=0; nt<NTN; nt++)
#pragma unroll
        for (int c2=0; c2<2; c2++){
            int gn = col0 + wn0 + nt*8 + tig*2 + c2;
            if (gn >= N) continue;
            float v = acc[mt][nt][r2*2 + c2];
            if (EPI & EPI_KV3) v += e0[gn] + e1[gn] + e2[gn];
            v *= rs;
            if (EPI & EPI_BIAS) v += bias[gn];
            if (EPI & EPI_GELU) v = 0.5f * v * (1.f + erff(v * 0.7071067811865476f));
            if (EPI & EPI_RES)  v += Rb[(long)gm*ldc + gn];
            Cb[(long)gm*ldc + gn] = v;
        }
    }
}

// ---------------- fused cross-attention flash kernel (split-KV) ----------------
__global__ void __launch_bounds__(256)
sip_flash()
{
    __shared__ uint32_t Ks[DHP][BKV+8];
    __shared__ uint32_t Vs[BKV][DHP+4];
    __shared__ uint32_t Ps[NL][BKV+4];
    __shared__ float msk[BKV];

    int split = blockIdx.x, bh = blockIdx.y;
    int b = bh / HH, h = bh - b*HH;
    int tid = threadIdx.x, w = tid>>5, lane = tid&31;
    int g = lane>>2, tig = lane&3;
    int kv0 = split * (NVOX/NSPL2);

    uint32_t qf[10][4];
    {
        const float* Qb = g_Q + (long)b*NL*IN_ + (long)h*DH;
        int r0 = w*16 + g;
#pragma unroll
        for (int ks=0; ks<10; ks++){
            int c0 = ks*8 + tig;
            float v00 = (c0   < DH) ? Qb[(long)r0*IN_ + c0]       : 0.f;
            float v10 = (c0   < DH) ? Qb[(long)(r0+8)*IN_ + c0]   : 0.f;
            float v01 = (c0+4 < DH) ? Qb[(long)r0*IN_ + c0+4]     : 0.f;
            float v11 = (c0+4 < DH) ? Qb[(long)(r0+8)*IN_ + c0+4] : 0.f;
            qf[ks][0]=f2tf32(v00); qf[ks][1]=f2tf32(v10);
            qf[ks][2]=f2tf32(v01); qf[ks][3]=f2tf32(v11);
        }
    }

    float o[10][4];
#pragma unroll
    for (int nt=0;nt<10;nt++)
#pragma unroll
        for (int r=0;r<4;r++) o[nt][r]=0.f;
    float mrun[2] = {-FLT_MAX, -FLT_MAX};
    float lrun[2] = {0.f, 0.f};

    const float* Kb = g_KV + (long)b*NVOX*NKV + (long)h*DH;
    const float* Vb = Kb + IN_;
    const float* Mb = g_mask + (long)b*NVOX;

    for (int it=0; it<FITERS; it++){
        int j0 = kv0 + it*BKV;
#pragma unroll
        for (int e=0;e<10;e++){
            int idx = e*256 + tid;
            int r = idx / DHP, c = idx - r*DHP;
            float kv = (c < DH) ? Kb[(long)(j0+r)*NKV + c] : 0.f;
            Ks[c][r] = f2tf32(kv);
            float vv = (c < DH) ? Vb[(long)(j0+r)*NKV + c] : 0.f;
            Vs[r][c] = f2tf32(vv);
        }
        if (tid < BKV) msk[tid] = Mb[j0 + tid];
        __syncthreads();

        float s[4][4];
#pragma unroll
        for (int nt=0;nt<4;nt++)
#pragma unroll
            for (int r=0;r<4;r++) s[nt][r]=0.f;
#pragma unroll
        for (int ks=0; ks<10; ks++){
            uint32_t bfr[4][2];
#pragma unroll
            for (int nt=0;nt<4;nt++){
                bfr[nt][0] = Ks[ks*8 + tig    ][nt*8 + g];
                bfr[nt][1] = Ks[ks*8 + tig + 4][nt*8 + g];
            }
#pragma unroll
            for (int nt=0;nt<4;nt++) mma_tf32(s[nt], qf[ks], bfr[nt]);
        }
#pragma unroll
        for (int nt=0;nt<4;nt++)
#pragma unroll
        for (int r=0;r<4;r++){
            int jl = nt*8 + tig*2 + (r & 1);
            if (msk[jl] < 0.5f) s[nt][r] = -FLT_MAX;
        }
#pragma unroll
        for (int r2=0;r2<2;r2++){
            float mx = -FLT_MAX;
#pragma unroll
            for (int nt=0;nt<4;nt++){
                mx = fmaxf(mx, s[nt][r2*2+0]);
                mx = fmaxf(mx, s[nt][r2*2+1]);
            }
            mx = fmaxf(mx, __shfl_xor_sync(0xffffffffu, mx, 1));
            mx = fmaxf(mx, __shfl_xor_sync(0xffffffffu, mx, 2));
            float mnew = fmaxf(mrun[r2], mx);
            float sc = fexp(mrun[r2] - mnew);
            mrun[r2] = mnew;
            lrun[r2] *= sc;
#pragma unroll
            for (int nt=0;nt<10;nt++){
                o[nt][r2*2+0] *= sc;
                o[nt][r2*2+1] *= sc;
            }
            float ps = 0.f;
#pragma unroll
            for (int nt=0;nt<4;nt++){
                float p0 = fexp(s[nt][r2*2+0] - mnew);
                float p1 = fexp(s[nt][r2*2+1] - mnew);
                s[nt][r2*2+0] = p0; s[nt][r2*2+1] = p1;
                ps += p0 + p1;
            }
            ps += __shfl_xor_sync(0xffffffffu, ps, 1);
            ps += __shfl_xor_sync(0xffffffffu, ps, 2);
            lrun[r2] += ps;
        }
#pragma unroll
        for (int nt=0;nt<4;nt++)
#pragma unroll
        for (int r=0;r<4;r++){
            int row = w*16 + g + (r>>1)*8;
            int col = nt*8 + tig*2 + (r&1);
            Ps[row][col] = f2tf32(s[nt][r]);
        }
        __syncwarp();
#pragma unroll
        for (int ks=0; ks<4; ks++){
            uint32_t af[4];
            af[0] = Ps[w*16 + g    ][ks*8 + tig    ];
            af[1] = Ps[w*16 + g + 8][ks*8 + tig    ];
            af[2] = Ps[w*16 + g    ][ks*8 + tig + 4];
            af[3] = Ps[w*16 + g + 8][ks*8 + tig + 4];
#pragma unroll
            for (int nt=0;nt<10;nt++){
                uint32_t bfr[2];
                bfr[0] = Vs[ks*8 + tig    ][nt*8 + g];
                bfr[1] = Vs[ks*8 + tig + 4][nt*8 + g];
                mma_tf32(o[nt], af, bfr);
            }
        }
        __syncthreads();
    }

    long base = ((long)split*B_*HH + bh) * NL;
#pragma unroll
    for (int r2=0;r2<2;r2++){
        int row = w*16 + g + r2*8;
        if (tig == 0){
            g_fm[base + row] = mrun[r2];
            g_fl[base + row] = lrun[r2];
        }
#pragma unroll
        for (int nt=0;nt<10;nt++){
            g_fo[(base + row)*DHP + nt*8 + tig*2 + 0] = o[nt][r2*2+0];
            g_fo[(base + row)*DHP + nt*8 + tig*2 + 1] = o[nt][r2*2+1];
        }
    }
}

// ---------------- flash split combine + head merge -> AO ----------------
__global__ void sip_flash_combine()
{
    int blk = blockIdx.x;
    int bh = blk / NL, row = blk - bh*NL;
    int b = bh / HH, h = bh - b*HH;
    int tid = threadIdx.x;           // 128
    __shared__ float sm[NSPL2], sl[NSPL2];
    __shared__ float sms, sden;
    if (tid < NSPL2){
        long idx = ((long)tid*B_*HH + bh)*NL + row;
        sm[tid] = g_fm[idx];
        sl[tid] = g_fl[idx];
    }
    __syncthreads();
    if (tid == 0){
        float mx = sm[0];
#pragma unroll
        for (int s2=1;s2<NSPL2;s2++) mx = fmaxf(mx, sm[s2]);
        float den = 0.f;
#pragma unroll
        for (int s2=0;s2<NSPL2;s2++) den += sl[s2] * fexp(sm[s2] - mx);
        sms = mx; sden = den;
    }
    __syncthreads();
    if (tid < DH){
        float acc = 0.f;
#pragma unroll
        for (int s2=0;s2<NSPL2;s2++){
            float wgt = fexp(sm[s2] - sms);
            acc += g_fo[(((long)s2*B_*HH + bh)*NL + row)*DHP + tid] * wgt;
        }
        g_AO[((long)b*NL + row)*IN_ + h*DH + tid] = acc / sden;
    }
}

// ---------------- separable fourier features ----------------
__global__ void sip_build_encsmall()
{
    int ri = blockIdx.x;
    int a = ri >> 5, v = ri & 31;
    float dim = (a == 2) ? 8.f : 32.f;
    float x = 2.f*v/dim - 1.f;
    int tid = threadIdx.x;               // 160
    __shared__ float sh[5];
    float val = 0.f;
    if (tid < 129){
        int r = tid;
        if (r < 64)        val = sinf(x * exp2f((float)(-r)));
        else if (r < 128)  val = cosf(x * exp2f((float)(64 - r)));
        else               val = x;
        g_encS[ri*129 + tid] = val;
    }
    float ss = val*val;
    for (int o=16;o>0;o>>=1) ss += __shfl_xor_sync(0xffffffffu, ss, o);
    if ((tid & 31) == 0) sh[tid>>5] = ss;
    __syncthreads();
    if (tid == 0) g_ssS[ri] = sh[0]+sh[1]+sh[2]+sh[3]+sh[4];
}

// ---------------- factored EP tables, W read once ----------------
__global__ void __launch_bounds__(256)
sip_ep2(const float* __restrict__ kvw)
{
    __shared__ float E[32][130];
    int a = blockIdx.y, d = blockIdx.z;
    int tid = threadIdx.x;
    for (int i = tid; i < 32*129; i += 256){
        int r = i / 129, cc = i - r*129;
        E[r][cc] = g_encS[(a*32 + r)*129 + cc];
    }
    __syncthreads();
    int c = blockIdx.x*64 + (tid & 63);
    int rg = tid >> 6;
    if (c >= NKV) return;
    const float* W = kvw + (long)d*ID2*NKV + (long)(VC + a*129)*NKV + c;
    float acc[8];
#pragma unroll
    for (int k=0;k<8;k++) acc[k] = 0.f;
    for (int r=0;r<129;r++){
        float w = W[(long)r*NKV];
#pragma unroll
        for (int k=0;k<8;k++) acc[k] = fmaf(E[rg*8+k][r], w, acc[k]);
    }
#pragma unroll
    for (int k=0;k<8;k++)
        g_EPT[((long)d*96 + a*32 + rg*8 + k)*NKV + c] = acc[k];
}

// ---------------- latent weight concat: [la_q*scale | la_kv] ----------------
__global__ void sip_build_wcat(const float* __restrict__ laq, const float* __restrict__ lakv)
{
    long idx = (long)blockIdx.x * blockDim.x + threadIdx.x;
    long total = (long)DEPTH*LD*NQKV;
    if (idx >= total) return;
    int c = (int)(idx % NQKV);
    long r = idx / NQKV;
    int k = (int)(r % LD);
    int d = (int)(r / LD);
    g_Wcat[idx] = (c < IN_) ? laq[((long)d*LD + k)*IN_ + c] * ATT_SCALE
                            : lakv[((long)d*LD + k)*NKV + (c - IN_)];
}

// ---------------- vals(b,n,48), invn, mask ----------------
__global__ void sip_build_vals(const float* __restrict__ input)
{
    int vox = blockIdx.x;
    int b = vox / NVOX, n = vox % NVOX;
    int hy = n / (GW*T_), wx = (n / T_) % GW, tt = n % T_;
    int tid = threadIdx.x;               // 64
    __shared__ float ssh[2], msh[2];
    float val = 0.f;
    if (tid < VC){
        int py = tid/12, px = (tid/3)%4, c = tid%3;
        val = input[(((long)tt*B_ + b)*3 + c)*16384 + (hy*4+py)*128 + (wx*4+px)];
        g_vals[(long)vox*VC + tid] = val;
    }
    float ss = val*val;
    float mx = (tid < VC) ? val : -FLT_MAX;
    for (int o=16;o>0;o>>=1){
        ss += __shfl_xor_sync(0xffffffffu, ss, o);
        mx = fmaxf(mx, __shfl_xor_sync(0xffffffffu, mx, o));
    }
    if ((tid & 31) == 0){ ssh[tid>>5] = ss; msh[tid>>5] = mx; }
    __syncthreads();
    if (tid == 0){
        float tot = ssh[0] + ssh[1] + g_ssS[hy] + g_ssS[32+wx] + g_ssS[64+tt];
        g_invn[vox] = 1.f / fmaxf(sqrtf(tot), 1e-5f);
        float m = fmaxf(msh[0], msh[1]);
        g_mask[vox] = (fabsf(m) > 0.3f) ? 1.f : 0.f;
    }
}

// ---------------- per-row scale (gain / L2 norm), warp per row ----------------
__global__ void sip_rowscale(const float* __restrict__ in, float* __restrict__ rsc,
                             const float* __restrict__ gptr)
{
    int row = blockIdx.x*8 + (threadIdx.x >> 5);
    int lane = threadIdx.x & 31;
    const float* p = in + (long)row*LD;
    float s = 0.f;
    for (int j = lane; j < LD; j += 32){ float v = p[j]; s += v*v; }
    for (int o=16;o>0;o>>=1) s += __shfl_xor_sync(0xffffffffu, s, o);
    if (lane == 0) rsc[row] = gptr[0] / fmaxf(sqrtf(s), 1e-5f);
}

// ---------------- softmax (latent path; full normalize) ----------------
__global__ void sip_softmax(float* __restrict__ S, int cols)
{
    long row = blockIdx.x;
    float* p = S + row * (long)cols;
    __shared__ float sh[8];
    int tid = threadIdx.x;
    int nw = blockDim.x >> 5;
    float m = -FLT_MAX;
    for (int j = tid; j < cols; j += blockDim.x) m = fmaxf(m, p[j]);
    for (int o=16;o>0;o>>=1) m = fmaxf(m, __shfl_xor_sync(0xffffffffu, m, o));
    if ((tid & 31) == 0) sh[tid>>5] = m;
    __syncthreads();
    float mm = sh[0];
    for (int w=1; w<nw; w++) mm = fmaxf(mm, sh[w]);
    __syncthreads();
    float s = 0.f;
    for (int j = tid; j < cols; j += blockDim.x){
        float e = fexp(p[j] - mm);
        p[j] = e; s += e;
    }
    for (int o=16;o>0;o>>=1) s += __shfl_xor_sync(0xffffffffu, s, o);
    if ((tid & 31) == 0) sh[tid>>5] = s;
    __syncthreads();
    float tot = 0.f;
    for (int w=0; w<nw; w++) tot += sh[w];
    float inv = 1.f / tot;
    for (int j = tid; j < cols; j += blockDim.x) p[j] *= inv;
}

__global__ void sip_init_lat(const float* __restrict__ latents, const float* __restrict__ pos)
{
    long idx = (long)blockIdx.x * blockDim.x + threadIdx.x;
    if (idx >= (long)B_*NL*LD) return;
    int r = (int)(idx % (NL*LD));
    g_lat[idx] = latents[r] + pos[r];
}

__global__ void sip_permute_out(float* __restrict__ out)
{
    long idx = (long)blockIdx.x * blockDim.x + threadIdx.x;
    if (idx >= (long)T_*B_*16*OC) return;
    int o = (int)(idx % OC);
    long r = idx / OC;
    int nn = (int)(r % 16); r /= 16;
    int b = (int)(r % B_);
    int tt = (int)(r / B_);
    out[idx] = g_logits[((long)b*NL + nn*T_ + tt)*OC + o];
}

// ---------------- host ----------------
static inline int cdiv(int a, int b){ return (a + b - 1) / b; }

extern "C" void kernel_launch(void* const* d_in, const int* in_sizes, int n_in,
                              void* d_out, int out_size)
{
    const float* input    = (const float*)d_in[0];
    const float* latents  = (const float*)d_in[1];
    const float* pos_emb  = (const float*)d_in[2];
    const float* ca_g     = (const float*)d_in[3];
    const float* ca_ctx_g = (const float*)d_in[4];
    const float* ca_q     = (const float*)d_in[5];
    const float* ca_kv    = (const float*)d_in[6];
    const float* ca_ow    = (const float*)d_in[7];
    const float* ca_ob    = (const float*)d_in[8];
    const float* cf_g     = (const float*)d_in[9];
    const float* cf_w1    = (const float*)d_in[10];
    const float* cf_b1    = (const float*)d_in[11];
    const float* cf_w2    = (const float*)d_in[12];
    const float* cf_b2    = (const float*)d_in[13];
    const float* la_g     = (const float*)d_in[14];
    const float* la_q     = (const float*)d_in[15];
    const float* la_kv    = (const float*)d_in[16];
    const float* la_ow    = (const float*)d_in[17];
    const float* la_ob    = (const float*)d_in[18];
    const float* lf_g     = (const float*)d_in[19];
    const float* lf_w1    = (const float*)d_in[20];
    const float* lf_b1    = (const float*)d_in[21];
    const float* lf_w2    = (const float*)d_in[22];
    const float* lf_b2    = (const float*)d_in[23];
    const float* logits_w = (const float*)d_in[24];
    const float* logits_b = (const float*)d_in[25];
    float* out = (float*)d_out;

    float *p_vals,*p_EPT,*p_invn,*p_rsc,*p_Wcat,*p_lat,*p_Q,*p_KV,*p_QKV,*p_S,*p_AO,*p_hid,*p_logits;
#define SYM(p, s) do{ void* _t=nullptr; cudaGetSymbolAddress(&_t, s); p=(float*)_t; }while(0)
    SYM(p_vals, g_vals); SYM(p_EPT, g_EPT); SYM(p_invn, g_invn); SYM(p_rsc, g_rsc);
    SYM(p_Wcat, g_Wcat); SYM(p_lat, g_lat);
    SYM(p_Q, g_Q); SYM(p_KV, g_KV); SYM(p_QKV, g_QKV);
    SYM(p_S, g_S); SYM(p_AO, g_AO); SYM(p_hid, g_hid); SYM(p_logits, g_logits);
#undef SYM

    const int M0 = B_*NL;  // 512

    // -------- preamble --------
    sip_build_encsmall<<<96, 160>>>();
    sip_ep2<<<dim3(cdiv(NKV,64), 3, DEPTH), 256>>>(ca_kv);
    sip_build_vals<<<B_*NVOX, 64>>>(input);
    sip_init_lat<<<cdiv(B_*NL*LD,256), 256>>>(latents, pos_emb);
    sip_build_wcat<<<cdiv(DEPTH*LD*NQKV,256), 256>>>(la_q, la_kv);

    for (int d = 0; d < DEPTH; d++){
        // ===== cross attention =====
        sip_rowscale<<<64, 256>>>(p_lat, p_rsc, ca_g + d);
        sip_mma<64,64,16,32,32,false,0,0,16><<<dim3(cdiv(IN_,64),cdiv(M0,64),1),128>>>(
            M0, IN_, LD, p_lat, LD, 0, p_rsc, ca_q + (long)d*LD*IN_, IN_, 0,
            p_Q, IN_, 0, nullptr, nullptr, nullptr, ATT_SCALE, nullptr, nullptr);
        sip_mma<128,128,16,64,32,false,EPI_KV3,0,16><<<dim3(cdiv(NKV,128),cdiv(B_*NVOX,128),1),256>>>(
            B_*NVOX, NKV, VC, p_vals, VC, 0, nullptr, ca_kv + (long)d*ID2*NKV, NKV, 0,
            p_KV, NKV, 0, nullptr, nullptr, ca_ctx_g + d, 1.f,
            p_EPT + (long)d*96*NKV, p_invn);
        sip_flash<<<dim3(NSPL2, B_*HH), 256>>>();
        sip_flash_combine<<<B_*HH*NL, 128>>>();
        sip_mma<64,64,16,32,32,false,EPI_BIAS|EPI_RES,0,16><<<dim3(cdiv(LD,64),cdiv(M0,64),1),128>>>(
            M0, LD, IN_, p_AO, IN_, 0, nullptr, ca_ow + (long)d*IN_*LD, LD, 0,
            p_lat, LD, 0, ca_ob + (long)d*LD, p_lat, nullptr, 1.f, nullptr, nullptr);

        // ===== feed-forward (cross) =====
        sip_rowscale<<<64, 256>>>(p_lat, p_rsc, cf_g + d);
        sip_mma<64,64,16,32,32,false,EPI_BIAS|EPI_GELU,0,16><<<dim3(cdiv(FF,64),cdiv(M0,64),1),128>>>(
            M0, FF, LD, p_lat, LD, 0, p_rsc, cf_w1 + (long)d*LD*FF, FF, 0,
            p_hid, FF, 0, cf_b1 + (long)d*FF, nullptr, nullptr, 1.f, nullptr, nullptr);
        sip_mma<64,64,16,32,32,false,EPI_BIAS|EPI_RES,0,16><<<dim3(cdiv(LD,64),cdiv(M0,64),1),128>>>(
            M0, LD, FF, p_hid, FF, 0, nullptr, cf_w2 + (long)d*FF*LD, LD, 0,
            p_lat, LD, 0, cf_b2 + (long)d*LD, p_lat, nullptr, 1.f, nullptr, nullptr);

        // ===== latent self-attention =====
        sip_rowscale<<<64, 256>>>(p_lat, p_rsc, la_g + d);
        sip_mma<64,64,16,32,32,false,0,0,16><<<dim3(cdiv(NQKV,64),cdiv(M0,64),1),128>>>(
            M0, NQKV, LD, p_lat, LD, 0, p_rsc, p_Wcat + (long)d*LD*NQKV, NQKV, 0,
            p_QKV, NQKV, 0, nullptr, nullptr, nullptr, 1.f, nullptr, nullptr);
        sip_mma<64,64,16,32,32,true,0,3,4><<<dim3(2,2,B_*HH),128>>>(
            NL, NL, DH, p_QKV, NQKV, (long)NL*NQKV, nullptr,
            p_QKV + IN_, NQKV, (long)NL*NQKV,
            p_S, NL, (long)NL*NL, nullptr, nullptr, nullptr, 1.f, nullptr, nullptr);
        sip_softmax<<<B_*HH*NL, 128>>>(p_S, NL);
        sip_mma<128,80,16,64,40,false,0,6,4><<<dim3(1,1,B_*HH),128>>>(
            NL, DH, NL, p_S, NL, (long)NL*NL, nullptr,
            p_QKV + NKV, NQKV, (long)NL*NQKV,
            p_AO, IN_, (long)NL*IN_, nullptr, nullptr, nullptr, 1.f, nullptr, nullptr);
        sip_mma<64,64,16,32,32,false,EPI_BIAS|EPI_RES,0,16><<<dim3(cdiv(LD,64),cdiv(M0,64),1),128>>>(
            M0, LD, IN_, p_AO, IN_, 0, nullptr, la_ow + (long)d*IN_*LD, LD, 0,
            p_lat, LD, 0, la_ob + (long)d*LD, p_lat, nullptr, 1.f, nullptr, nullptr);

        // ===== feed-forward (latent) =====
        sip_rowscale<<<64, 256>>>(p_lat, p_rsc, lf_g + d);
        sip_mma<64,64,16,32,32,false,EPI_BIAS|EPI_GELU,0,16><<<dim3(cdiv(FF,64),cdiv(M0,64),1),128>>>(
            M0, FF, LD, p_lat, LD, 0, p_rsc, lf_w1 + (long)d*LD*FF, FF, 0,
            p_hid, FF, 0, lf_b1 + (long)d*FF, nullptr, nullptr, 1.f, nullptr, nullptr);
        sip_mma<64,64,16,32,32,false,EPI_BIAS|EPI_RES,0,16><<<dim3(cdiv(LD,64),cdiv(M0,64),1),128>>>(
            M0, LD, FF, p_hid, FF, 0, nullptr, lf_w2 + (long)d*FF*LD, LD, 0,
            p_lat, LD, 0, lf_b2 + (long)d*LD, p_lat, nullptr, 1.f, nullptr, nullptr);
    }

    // ===== logits + output permute =====
    sip_mma<64,64,16,32,32,false,EPI_BIAS,0,16><<<dim3(cdiv(OC,64),cdiv(M0,64),1),128>>>(
        M0, OC, LD, p_lat, LD, 0, nullptr, logits_w, OC, 0,
        p_logits, OC, 0, logits_b, nullptr, nullptr, 1.f, nullptr, nullptr);
    sip_permute_out<<<cdiv(T_*B_*16*OC,256), 256>>>(out);
}

// round 8
// speedup vs baseline: 5.1878x; 1.1565x over previous
#include <cuda_runtime.h>
#include <math.h>
#include <float.h>
#include <stdint.h>

// ---------------- problem constants ----------------
constexpr int B_   = 4;
constexpr int T_   = 8;
constexpr int HH   = 8;
constexpr int DH   = 75;
constexpr int NL   = 128;
constexpr int LD   = 512;
constexpr int ID2  = 435;
constexpr int VC   = 48;
constexpr int IN_  = 600;
constexpr int FF   = 2048;
constexpr int OC   = 64;
constexpr int DEPTH= 5;
constexpr int GH   = 32, GW = 32;
constexpr int NVOX = GH*GW*T_;           // 8192
constexpr int NKV  = 2*IN_;              // 1200
constexpr int NQKV = IN_ + NKV;          // 1800
constexpr float ATT_SCALE = 0.11547005383792515f;

// flash params
constexpr int NSPL2 = 16;
constexpr int DHP   = 80;
constexpr int BKV   = 32;
constexpr int FITERS= (NVOX/NSPL2)/BKV;  // 16
constexpr int KVROW = 2*HH*DHP;          // 1280 padded floats per kv row
constexpr int LDR   = 84;                // tile row stride
constexpr int TILEF = BKV*LDR;           // 2688
constexpr int BUFF  = 2*TILEF;           // K+V per buffer
constexpr int LDP   = 36;
constexpr int FLASH_SMEM_FLOATS = 2*BUFF + NL*LDP + 2*BKV;  // 15424
constexpr int FLASH_SMEM_BYTES  = FLASH_SMEM_FLOATS*4;      // 61696

// ---------------- scratch ----------------
__device__ float g_vals [(size_t)B_*NVOX*VC];
__device__ float g_encS [(size_t)96*129];
__device__ float g_ssS  [(size_t)96];
__device__ float g_EPT  [(size_t)DEPTH*96*NKV];
__device__ float g_invn [(size_t)B_*NVOX];
__device__ float g_mask [(size_t)B_*NVOX];
__device__ float g_rsc  [(size_t)B_*NL];
__device__ float g_Wcat [(size_t)DEPTH*LD*NQKV];
__device__ float g_lat  [(size_t)B_*NL*LD];
__device__ float g_Q    [(size_t)B_*NL*IN_];
__device__ float g_KV   [(size_t)B_*NVOX*KVROW];    // padded (b,j,2,H,80)
__device__ float g_QKV  [(size_t)B_*NL*NQKV];
__device__ float g_AO   [(size_t)B_*NL*IN_];
__device__ float g_hid  [(size_t)B_*NL*FF];
__device__ float g_logits[(size_t)B_*NL*OC];
__device__ float g_fo   [(size_t)NSPL2*B_*HH*NL*DHP];
__device__ float g_fm   [(size_t)NSPL2*B_*HH*NL];
__device__ float g_fl   [(size_t)NSPL2*B_*HH*NL];

// ---------------- helpers ----------------
__device__ __forceinline__ uint32_t f2tf32(float f){
    uint32_t r; asm("cvt.rna.tf32.f32 %0, %1;" : "=r"(r) : "f"(f)); return r;
}
__device__ __forceinline__ void mma_tf32(float c[4], const uint32_t a[4], const uint32_t b[2]){
    asm("mma.sync.aligned.m16n8k8.row.col.f32.tf32.tf32.f32 "
        "{%0,%1,%2,%3}, {%4,%5,%6,%7}, {%8,%9}, {%0,%1,%2,%3};"
        : "+f"(c[0]), "+f"(c[1]), "+f"(c[2]), "+f"(c[3])
        : "r"(a[0]), "r"(a[1]), "r"(a[2]), "r"(a[3]), "r"(b[0]), "r"(b[1]));
}
__device__ __forceinline__ void cpa16(float* dst, const float* src, int bytes){
    uint32_t d = (uint32_t)__cvta_generic_to_shared(dst);
    asm volatile("cp.async.ca.shared.global [%0], [%1], 16, %2;" :: "r"(d), "l"(src), "r"(bytes));
}
__device__ __forceinline__ void cpa4(float* dst, const float* src, int bytes){
    uint32_t d = (uint32_t)__cvta_generic_to_shared(dst);
    asm volatile("cp.async.ca.shared.global [%0], [%1], 4, %2;" :: "r"(d), "l"(src), "r"(bytes));
}
// fast exp for x <= 0 (FMA pipe)
__device__ __forceinline__ float fexp(float x){
    float t = x * 1.4426950408889634f;
    t = fmaxf(t, -126.0f);
    float fi = floorf(t);
    float f = t - fi;
    float p = 1.5403530e-4f;
    p = fmaf(p, f, 1.3333558e-3f);
    p = fmaf(p, f, 9.6181291e-3f);
    p = fmaf(p, f, 5.5504109e-2f);
    p = fmaf(p, f, 2.4022651e-1f);
    p = fmaf(p, f, 6.9314718e-1f);
    p = fmaf(p, f, 1.0f);
    return p * __int_as_float(((int)fi + 127) << 23);
}

// ---------------- epilogue flags ----------------
#define EPI_BIAS 1
#define EPI_GELU 2
#define EPI_RES  4
#define EPI_KV3  8
#define EPI_KVP  16   // write to padded KV layout
// BHM bits: 1=A per-(b,h) offset, 2=B per-(b,h), 4=C per-(b,h)

// ---------------- pipelined tf32 GEMM (cp.async double buffer) ----------------
template<int BM,int BN,int BK,int WM,int WN,bool TB,int EPI,int BHM,int VEC>
__global__ void __launch_bounds__((BM/WM)*(BN/WN)*32)
sip_mma(int M,int N,int K,
        const float* __restrict__ A,int lda,long sA,
        const float* __restrict__ ascale,
        const float* __restrict__ Bp,int ldb,long sB,
        float* __restrict__ C,int ldc,long sC,
        const float* __restrict__ bias,
        const float* __restrict__ resid,
        const float* __restrict__ alphaPtr,float alphaC,
        const float* __restrict__ ep,
        const float* __restrict__ rowscale)
{
    constexpr int NWARP = (BM/WM)*(BN/WN);
    constexpr int NT = NWARP*32;
    constexpr int LDA = BK + 4;
    constexpr int LDB = TB ? (BK + 4) : (BN + 4);
    constexpr int ASZ = BM*LDA;
    constexpr int BSZ = TB ? BN*LDB : BK*LDB;
    constexpr int VE  = VEC/4;
    constexpr int ACP = (BM*BK)/(VE*NT);
    constexpr int BCP = (BN*BK)/(VE*NT);
    __shared__ float As[2][ASZ];
    __shared__ float Bs[2][BSZ];

    int tid = threadIdx.x;
    int batch = blockIdx.z;
    int b2 = batch / HH, h2 = batch - b2*HH;
    const float* Ab = A + ((BHM & 1) ? ((long)b2*sA + (long)h2*DH) : (long)batch*sA);
    const float* Bb = Bp + ((BHM & 2) ? ((long)b2*sB + (long)h2*DH) : (long)batch*sB);
    int row0 = blockIdx.y * BM, col0 = blockIdx.x * BN;
    int wid = tid >> 5, lane = tid & 31;
    int g = lane >> 2, tig = lane & 3;
    int wm0 = (wid % (BM/WM)) * WM;
    int wn0 = (wid / (BM/WM)) * WN;
    constexpr int MT = WM/16, NTN = WN/8;

    float rsA[MT][2];
#pragma unroll
    for (int mt=0; mt<MT; mt++){
        int r0 = row0 + wm0 + mt*16 + g;
        rsA[mt][0] = (ascale && r0   < M) ? ascale[r0]   : 1.f;
        rsA[mt][1] = (ascale && r0+8 < M) ? ascale[r0+8] : 1.f;
    }

    float acc[MT][NTN][4];
#pragma unroll
    for (int i=0;i<MT;i++)
#pragma unroll
        for (int j=0;j<NTN;j++)
#pragma unroll
            for (int r=0;r<4;r++) acc[i][j][r] = 0.f;

    int ktiles = (K + BK - 1) / BK;

    auto loadA = [&](int kt, int buf){
#pragma unroll
        for (int e=0; e<ACP; e++){
            int v = e*NT + tid;
            int m = v / (BK/VE), kq = v - m*(BK/VE);
            int gm = row0 + m, gk = kt + kq*VE;
            const float* src = Ab + (long)gm*lda + gk;
            int bytes = 0;
            if (gm < M && gk < K) bytes = min(K - gk, VE) * 4;
            if (!bytes) src = Ab;
            if (VEC == 16) cpa16(&As[buf][m*LDA + kq*VE], src, bytes);
            else           cpa4 (&As[buf][m*LDA + kq*VE], src, bytes);
        }
    };
    auto loadB = [&](int kt, int buf){
#pragma unroll
        for (int e=0; e<BCP; e++){
            int v = e*NT + tid;
            if (TB){
                int n = v / (BK/VE), kq = v - n*(BK/VE);
                int gn = col0 + n, gk = kt + kq*VE;
                const float* src = Bb + (long)gn*ldb + gk;
                int bytes = 0;
                if (gn < N && gk < K) bytes = min(K - gk, VE) * 4;
                if (!bytes) src = Bb;
                if (VEC == 16) cpa16(&Bs[buf][n*LDB + kq*VE], src, bytes);
                else           cpa4 (&Bs[buf][n*LDB + kq*VE], src, bytes);
            } else {
                int k = v / (BN/VE), nq = v - k*(BN/VE);
                int gn = col0 + nq*VE, gk = kt + k;
                const float* src = Bb + (long)gk*ldb + gn;
                int bytes = 0;
                if (gk < K && gn < N) bytes = min(N - gn, VE) * 4;
                if (!bytes) src = Bb;
                if (VEC == 16) cpa16(&Bs[buf][k*LDB + nq*VE], src, bytes);
                else           cpa4 (&Bs[buf][k*LDB + nq*VE], src, bytes);
            }
        }
    };

    loadA(0, 0); loadB(0, 0);
    asm volatile("cp.async.commit_group;");

    for (int t=0; t<ktiles; t++){
        int cur = t & 1;
        if (t+1 < ktiles){
            loadA((t+1)*BK, cur^1); loadB((t+1)*BK, cur^1);
            asm volatile("cp.async.commit_group;");
            asm volatile("cp.async.wait_group 1;");
        } else {
            asm volatile("cp.async.wait_group 0;");
        }
        __syncthreads();
#pragma unroll
        for (int ks=0; ks<BK/8; ks++){
            uint32_t af[MT][4], bf[NTN][2];
#pragma unroll
            for (int mt=0; mt<MT; mt++){
                int mb = wm0 + mt*16;
                float a0 = As[cur][(mb+g  )*LDA + ks*8 + tig    ];
                float a1 = As[cur][(mb+g+8)*LDA + ks*8 + tig    ];
                float a2 = As[cur][(mb+g  )*LDA + ks*8 + tig + 4];
                float a3 = As[cur][(mb+g+8)*LDA + ks*8 + tig + 4];
                af[mt][0] = f2tf32(a0 * rsA[mt][0]);
                af[mt][1] = f2tf32(a1 * rsA[mt][1]);
                af[mt][2] = f2tf32(a2 * rsA[mt][0]);
                af[mt][3] = f2tf32(a3 * rsA[mt][1]);
            }
#pragma unroll
            for (int nt=0; nt<NTN; nt++){
                int nb = wn0 + nt*8;
                float b0, b1;
                if (TB){
                    b0 = Bs[cur][(nb+g)*LDB + ks*8 + tig    ];
                    b1 = Bs[cur][(nb+g)*LDB + ks*8 + tig + 4];
                } else {
                    b0 = Bs[cur][(ks*8 + tig    )*LDB + nb + g];
                    b1 = Bs[cur][(ks*8 + tig + 4)*LDB + nb + g];
                }
                bf[nt][0] = f2tf32(b0); bf[nt][1] = f2tf32(b1);
            }
#pragma unroll
            for (int mt=0; mt<MT; mt++)
#pragma unroll
                for (int nt=0; nt<NTN; nt++)
                    mma_tf32(acc[mt][nt], af[mt], bf[nt]);
        }
        __syncthreads();
    }

    float alpha = alphaC;
    if (alphaPtr) alpha *= alphaPtr[0];

    float* Cb = C + ((BHM & 4) ? ((long)b2*sC + (long)h2*DH) : (long)batch*sC);
    const float* Rb = (EPI & EPI_RES) ? resid + (long)batch * sC : nullptr;

    int colw[NTN][2];
#pragma unroll
    for (int nt=0; nt<NTN; nt++)
#pragma unroll
    for (int c2=0; c2<2; c2++){
        int gn = col0 + wn0 + nt*8 + tig*2 + c2;
        if (EPI & EPI_KVP){
            int kvs = (gn >= IN_) ? 1 : 0;
            int c = gn - kvs*IN_;
            int hh2 = c / DH;
            colw[nt][c2] = kvs*(HH*DHP) + hh2*DHP + (c - hh2*DH);
        } else colw[nt][c2] = gn;
    }
    const long ldcE = (EPI & EPI_KVP) ? (long)KVROW : (long)ldc;

#pragma unroll
    for (int mt=0; mt<MT; mt++)
#pragma unroll
    for (int r2=0; r2<2; r2++){
        int gm = row0 + wm0 + mt*16 + g + r2*8;
        if (gm >= M) continue;
        float rs = alpha;
        const float *e0=nullptr,*e1=nullptr,*e2=nullptr;
        if (EPI & EPI_KV3){
            int jj = gm % NVOX;
            int y = jj>>8, xx = (jj>>3)&31, t = jj&7;
            e0 = ep + (long)y*NKV;
            e1 = ep + (long)(32+xx)*NKV;
            e2 = ep + (long)(64+t)*NKV;
            if (rowscale) rs *= rowscale[gm];
        }
#pragma unroll
        for (int nt=0; nt<NTN; nt++)
#pragma unroll
        for (int c2=0; c2<2; c2++){
            int gn = col0 + wn0 + nt*8 + tig*2 + c2;
            if (gn >= N) continue;
            float v = acc[mt][nt][r2*2 + c2];
            if (EPI & EPI_KV3) v += e0[gn] + e1[gn] + e2[gn];
            v *= rs;
            if (EPI & EPI_BIAS) v += bias[gn];
            if (EPI & EPI_GELU) v = 0.5f * v * (1.f + erff(v * 0.7071067811865476f));
            if (EPI & EPI_RES)  v += Rb[(long)gm*ldc + gn];
            Cb[gm*ldcE + colw[nt][c2]] = v;
        }
    }
}

// ---------------- zero KV pad columns (once; never overwritten) ----------------
__global__ void sip_zero_kvpad()
{
    long idx = (long)blockIdx.x*blockDim.x + threadIdx.x;
    long total = (long)B_*NVOX*16*5;
    if (idx >= total) return;
    long r = idx / 80;
    int s = (int)((idx % 80) / 5);
    int p = (int)(idx % 5);
    g_KV[r*KVROW + s*DHP + DH + p] = 0.f;
}

// ---------------- pipelined cross-attention flash (split-KV, cp.async) ----------------
__global__ void __launch_bounds__(256)
sip_flash()
{
    extern __shared__ float sm[];
    float* Ps  = sm + 2*BUFF;
    float* msk = Ps + NL*LDP;

    int split = blockIdx.x, bh = blockIdx.y;
    int b = bh / HH, h = bh - b*HH;
    int tid = threadIdx.x, w = tid>>5, lane = tid&31;
    int g = lane>>2, tig = lane&3;
    int kv0 = split * (NVOX/NSPL2);

    const float* KVb = g_KV + (long)b*NVOX*KVROW + h*DHP;
    const float* Mb  = g_mask + (long)b*NVOX;

    // Q fragments (persistent)
    uint32_t qf[10][4];
    {
        const float* Qb = g_Q + (long)b*NL*IN_ + (long)h*DH;
        int r0 = w*16 + g;
#pragma unroll
        for (int ks=0; ks<10; ks++){
            int c0 = ks*8 + tig;
            float v00 = (c0   < DH) ? Qb[(long)r0*IN_ + c0]       : 0.f;
            float v10 = (c0   < DH) ? Qb[(long)(r0+8)*IN_ + c0]   : 0.f;
            float v01 = (c0+4 < DH) ? Qb[(long)r0*IN_ + c0+4]     : 0.f;
            float v11 = (c0+4 < DH) ? Qb[(long)(r0+8)*IN_ + c0+4] : 0.f;
            qf[ks][0]=f2tf32(v00); qf[ks][1]=f2tf32(v10);
            qf[ks][2]=f2tf32(v01); qf[ks][3]=f2tf32(v11);
        }
    }

    float o[10][4];
#pragma unroll
    for (int nt=0;nt<10;nt++)
#pragma unroll
        for (int r=0;r<4;r++) o[nt][r]=0.f;
    float mrun[2] = {-FLT_MAX, -FLT_MAX};
    float lrun[2] = {0.f, 0.f};

    auto prefetch = [&](int it, int buf){
        int j0 = kv0 + it*BKV;
#pragma unroll
        for (int e=0;e<5;e++){
            int idx = e*256 + tid;          // 0..1279
            int t = idx / 640;
            int v = idx - t*640;
            int r = v / 20, q = v - r*20;
            cpa16(sm + buf*BUFF + t*TILEF + r*LDR + q*4,
                  KVb + (long)(j0+r)*KVROW + t*(HH*DHP) + q*4, 16);
        }
        if (tid < BKV) cpa4(msk + buf*BKV + tid, Mb + j0 + tid, 4);
    };

    prefetch(0, 0);
    asm volatile("cp.async.commit_group;");

    for (int it=0; it<FITERS; it++){
        int cur = it & 1;
        if (it+1 < FITERS){
            prefetch(it+1, cur^1);
            asm volatile("cp.async.commit_group;");
            asm volatile("cp.async.wait_group 1;");
        } else {
            asm volatile("cp.async.wait_group 0;");
        }
        __syncthreads();
        const float* Kt = sm + cur*BUFF;
        const float* Vt = Kt + TILEF;
        const float* mk = msk + cur*BKV;

        // S = Q @ K^T
        float s[4][4];
#pragma unroll
        for (int nt=0;nt<4;nt++)
#pragma unroll
            for (int r=0;r<4;r++) s[nt][r]=0.f;
#pragma unroll
        for (int ks=0; ks<10; ks++){
            uint32_t bfr[4][2];
#pragma unroll
            for (int nt=0;nt<4;nt++){
                bfr[nt][0] = f2tf32(Kt[(nt*8+g)*LDR + ks*8 + tig    ]);
                bfr[nt][1] = f2tf32(Kt[(nt*8+g)*LDR + ks*8 + tig + 4]);
            }
#pragma unroll
            for (int nt=0;nt<4;nt++) mma_tf32(s[nt], qf[ks], bfr[nt]);
        }
#pragma unroll
        for (int nt=0;nt<4;nt++)
#pragma unroll
        for (int r=0;r<4;r++){
            int jl = nt*8 + tig*2 + (r & 1);
            if (mk[jl] < 0.5f) s[nt][r] = -FLT_MAX;
        }
#pragma unroll
        for (int r2=0;r2<2;r2++){
            float mx = -FLT_MAX;
#pragma unroll
            for (int nt=0;nt<4;nt++){
                mx = fmaxf(mx, s[nt][r2*2+0]);
                mx = fmaxf(mx, s[nt][r2*2+1]);
            }
            mx = fmaxf(mx, __shfl_xor_sync(0xffffffffu, mx, 1));
            mx = fmaxf(mx, __shfl_xor_sync(0xffffffffu, mx, 2));
            float mnew = fmaxf(mrun[r2], mx);
            float sc = fexp(mrun[r2] - mnew);
            mrun[r2] = mnew;
            lrun[r2] *= sc;
#pragma unroll
            for (int nt=0;nt<10;nt++){
                o[nt][r2*2+0] *= sc;
                o[nt][r2*2+1] *= sc;
            }
            float ps = 0.f;
#pragma unroll
            for (int nt=0;nt<4;nt++){
                float p0 = fexp(s[nt][r2*2+0] - mnew);
                float p1 = fexp(s[nt][r2*2+1] - mnew);
                s[nt][r2*2+0] = p0; s[nt][r2*2+1] = p1;
                ps += p0 + p1;
            }
            ps += __shfl_xor_sync(0xffffffffu, ps, 1);
            ps += __shfl_xor_sync(0xffffffffu, ps, 2);
            lrun[r2] += ps;
        }
        // P -> smem (warp-private rows)
#pragma unroll
        for (int nt=0;nt<4;nt++)
#pragma unroll
        for (int r=0;r<4;r++){
            int row = w*16 + g + (r>>1)*8;
            int col = nt*8 + tig*2 + (r&1);
            Ps[row*LDP + col] = s[nt][r];
        }
        __syncwarp();
        // O += P @ V
#pragma unroll
        for (int ks=0; ks<4; ks++){
            uint32_t af[4];
            af[0] = f2tf32(Ps[(w*16 + g    )*LDP + ks*8 + tig    ]);
            af[1] = f2tf32(Ps[(w*16 + g + 8)*LDP + ks*8 + tig    ]);
            af[2] = f2tf32(Ps[(w*16 + g    )*LDP + ks*8 + tig + 4]);
            af[3] = f2tf32(Ps[(w*16 + g + 8)*LDP + ks*8 + tig + 4]);
#pragma unroll
            for (int nt=0;nt<10;nt++){
                uint32_t bfr[2];
                bfr[0] = f2tf32(Vt[(ks*8 + tig    )*LDR + nt*8 + g]);
                bfr[1] = f2tf32(Vt[(ks*8 + tig + 4)*LDR + nt*8 + g]);
                mma_tf32(o[nt], af, bfr);
            }
        }
        __syncthreads();
    }

    long base = ((long)split*B_*HH + bh) * NL;
#pragma unroll
    for (int r2=0;r2<2;r2++){
        int row = w*16 + g + r2*8;
        if (tig == 0){
            g_fm[base + row] = mrun[r2];
            g_fl[base + row] = lrun[r2];
        }
#pragma unroll
        for (int nt=0;nt<10;nt++){
            g_fo[(base + row)*DHP + nt*8 + tig*2 + 0] = o[nt][r2*2+0];
            g_fo[(base + row)*DHP + nt*8 + tig*2 + 1] = o[nt][r2*2+1];
        }
    }
}

// ---------------- flash split combine + head merge -> AO ----------------
__global__ void sip_flash_combine()
{
    int blk = blockIdx.x;
    int bh = blk / NL, row = blk - bh*NL;
    int b = bh / HH, h = bh - b*HH;
    int tid = threadIdx.x;           // 128
    __shared__ float sm2[NSPL2], sl[NSPL2];
    __shared__ float sms, sden;
    if (tid < NSPL2){
        long idx = ((long)tid*B_*HH + bh)*NL + row;
        sm2[tid] = g_fm[idx];
        sl[tid] = g_fl[idx];
    }
    __syncthreads();
    if (tid == 0){
        float mx = sm2[0];
#pragma unroll
        for (int s2=1;s2<NSPL2;s2++) mx = fmaxf(mx, sm2[s2]);
        float den = 0.f;
#pragma unroll
        for (int s2=0;s2<NSPL2;s2++) den += sl[s2] * fexp(sm2[s2] - mx);
        sms = mx; sden = den;
    }
    __syncthreads();
    if (tid < DH){
        float acc = 0.f;
#pragma unroll
        for (int s2=0;s2<NSPL2;s2++){
            float wgt = fexp(sm2[s2] - sms);
            acc += g_fo[(((long)s2*B_*HH + bh)*NL + row)*DHP + tid] * wgt;
        }
        g_AO[((long)b*NL + row)*IN_ + h*DH + tid] = acc / sden;
    }
}

// ---------------- fused latent self-attention (per b,h) ----------------
__global__ void __launch_bounds__(256)
sip_flash_lat()
{
    __shared__ float Kt[BKV*LDR];
    __shared__ float Vt[BKV*LDR];
    __shared__ float Ps[NL*LDP];

    int bh = blockIdx.x;
    int b = bh / HH, h = bh - b*HH;
    int tid = threadIdx.x, w = tid>>5, lane = tid&31;
    int g = lane>>2, tig = lane&3;

    const float* Qb = g_QKV + (long)b*NL*NQKV + h*DH;
    const float* Kb = Qb + IN_;
    const float* Vb = Qb + NKV;

    uint32_t qf[10][4];
    {
        int r0 = w*16 + g;
#pragma unroll
        for (int ks=0; ks<10; ks++){
            int c0 = ks*8 + tig;
            float v00 = (c0   < DH) ? Qb[(long)r0*NQKV + c0]       : 0.f;
            float v10 = (c0   < DH) ? Qb[(long)(r0+8)*NQKV + c0]   : 0.f;
            float v01 = (c0+4 < DH) ? Qb[(long)r0*NQKV + c0+4]     : 0.f;
            float v11 = (c0+4 < DH) ? Qb[(long)(r0+8)*NQKV + c0+4] : 0.f;
            qf[ks][0]=f2tf32(v00); qf[ks][1]=f2tf32(v10);
            qf[ks][2]=f2tf32(v01); qf[ks][3]=f2tf32(v11);
        }
    }

    float o[10][4];
#pragma unroll
    for (int nt=0;nt<10;nt++)
#pragma unroll
        for (int r=0;r<4;r++) o[nt][r]=0.f;
    float mrun[2] = {-FLT_MAX, -FLT_MAX};
    float lrun[2] = {0.f, 0.f};

    for (int it=0; it<NL/BKV; it++){
        int j0 = it*BKV;
#pragma unroll
        for (int e=0;e<20;e++){
            int idx = e*256 + tid;          // 0..5119 = 2*32*80
            int t = idx / 2560;
            int v = idx - t*2560;
            int r = v / 80, c = v - r*80;
            const float* src = t ? Vb : Kb;
            float val = (c < DH) ? src[(long)(j0+r)*NQKV + c] : 0.f;
            (t ? Vt : Kt)[r*LDR + c] = val;
        }
        __syncthreads();

        float s[4][4];
#pragma unroll
        for (int nt=0;nt<4;nt++)
#pragma unroll
            for (int r=0;r<4;r++) s[nt][r]=0.f;
#pragma unroll
        for (int ks=0; ks<10; ks++){
            uint32_t bfr[4][2];
#pragma unroll
            for (int nt=0;nt<4;nt++){
                bfr[nt][0] = f2tf32(Kt[(nt*8+g)*LDR + ks*8 + tig    ]);
                bfr[nt][1] = f2tf32(Kt[(nt*8+g)*LDR + ks*8 + tig + 4]);
            }
#pragma unroll
            for (int nt=0;nt<4;nt++) mma_tf32(s[nt], qf[ks], bfr[nt]);
        }
#pragma unroll
        for (int r2=0;r2<2;r2++){
            float mx = -FLT_MAX;
#pragma unroll
            for (int nt=0;nt<4;nt++){
                mx = fmaxf(mx, s[nt][r2*2+0]);
                mx = fmaxf(mx, s[nt][r2*2+1]);
            }
            mx = fmaxf(mx, __shfl_xor_sync(0xffffffffu, mx, 1));
            mx = fmaxf(mx, __shfl_xor_sync(0xffffffffu, mx, 2));
            float mnew = fmaxf(mrun[r2], mx);
            float sc = fexp(mrun[r2] - mnew);
            mrun[r2] = mnew;
            lrun[r2] *= sc;
#pragma unroll
            for (int nt=0;nt<10;nt++){
                o[nt][r2*2+0] *= sc;
                o[nt][r2*2+1] *= sc;
            }
            float ps = 0.f;
#pragma unroll
            for (int nt=0;nt<4;nt++){
                float p0 = fexp(s[nt][r2*2+0] - mnew);
                float p1 = fexp(s[nt][r2*2+1] - mnew);
                s[nt][r2*2+0] = p0; s[nt][r2*2+1] = p1;
                ps += p0 + p1;
            }
            ps += __shfl_xor_sync(0xffffffffu, ps, 1);
            ps += __shfl_xor_sync(0xffffffffu, ps, 2);
            lrun[r2] += ps;
        }
#pragma unroll
        for (int nt=0;nt<4;nt++)
#pragma unroll
        for (int r=0;r<4;r++){
            int row = w*16 + g + (r>>1)*8;
            int col = nt*8 + tig*2 + (r&1);
            Ps[row*LDP + col] = s[nt][r];
        }
        __syncwarp();
#pragma unroll
        for (int ks=0; ks<4; ks++){
            uint32_t af[4];
            af[0] = f2tf32(Ps[(w*16 + g    )*LDP + ks*8 + tig    ]);
            af[1] = f2tf32(Ps[(w*16 + g + 8)*LDP + ks*8 + tig    ]);
            af[2] = f2tf32(Ps[(w*16 + g    )*LDP + ks*8 + tig + 4]);
            af[3] = f2tf32(Ps[(w*16 + g + 8)*LDP + ks*8 + tig + 4]);
#pragma unroll
            for (int nt=0;nt<10;nt++){
                uint32_t bfr[2];
                bfr[0] = f2tf32(Vt[(ks*8 + tig    )*LDR + nt*8 + g]);
                bfr[1] = f2tf32(Vt[(ks*8 + tig + 4)*LDR + nt*8 + g]);
                mma_tf32(o[nt], af, bfr);
            }
        }
        __syncthreads();
    }

    // normalize and write AO (head-merged)
#pragma unroll
    for (int r2=0;r2<2;r2++){
        int row = w*16 + g + r2*8;
        float inv = 1.f / lrun[r2];
#pragma unroll
        for (int nt=0;nt<10;nt++)
#pragma unroll
        for (int c2=0;c2<2;c2++){
            int col = nt*8 + tig*2 + c2;
            if (col < DH)
                g_AO[((long)b*NL + row)*IN_ + h*DH + col] = o[nt][r2*2+c2] * inv;
        }
    }
}

// ---------------- separable fourier features ----------------
__global__ void sip_build_encsmall()
{
    int ri = blockIdx.x;
    int a = ri >> 5, v = ri & 31;
    float dim = (a == 2) ? 8.f : 32.f;
    float x = 2.f*v/dim - 1.f;
    int tid = threadIdx.x;               // 160
    __shared__ float sh[5];
    float val = 0.f;
    if (tid < 129){
        int r = tid;
        if (r < 64)        val = sinf(x * exp2f((float)(-r)));
        else if (r < 128)  val = cosf(x * exp2f((float)(64 - r)));
        else               val = x;
        g_encS[ri*129 + tid] = val;
    }
    float ss = val*val;
    for (int o=16;o>0;o>>=1) ss += __shfl_xor_sync(0xffffffffu, ss, o);
    if ((tid & 31) == 0) sh[tid>>5] = ss;
    __syncthreads();
    if (tid == 0) g_ssS[ri] = sh[0]+sh[1]+sh[2]+sh[3]+sh[4];
}

// ---------------- factored EP tables, W read once ----------------
__global__ void __launch_bounds__(256)
sip_ep2(const float* __restrict__ kvw)
{
    __shared__ float E[32][130];
    int a = blockIdx.y, d = blockIdx.z;
    int tid = threadIdx.x;
    for (int i = tid; i < 32*129; i += 256){
        int r = i / 129, cc = i - r*129;
        E[r][cc] = g_encS[(a*32 + r)*129 + cc];
    }
    __syncthreads();
    int c = blockIdx.x*64 + (tid & 63);
    int rg = tid >> 6;
    if (c >= NKV) return;
    const float* W = kvw + (long)d*ID2*NKV + (long)(VC + a*129)*NKV + c;
    float acc[8];
#pragma unroll
    for (int k=0;k<8;k++) acc[k] = 0.f;
    for (int r=0;r<129;r++){
        float w = W[(long)r*NKV];
#pragma unroll
        for (int k=0;k<8;k++) acc[k] = fmaf(E[rg*8+k][r], w, acc[k]);
    }
#pragma unroll
    for (int k=0;k<8;k++)
        g_EPT[((long)d*96 + a*32 + rg*8 + k)*NKV + c] = acc[k];
}

// ---------------- latent weight concat: [la_q*scale | la_kv] ----------------
__global__ void sip_build_wcat(const float* __restrict__ laq, const float* __restrict__ lakv)
{
    long idx = (long)blockIdx.x * blockDim.x + threadIdx.x;
    long total = (long)DEPTH*LD*NQKV;
    if (idx >= total) return;
    int c = (int)(idx % NQKV);
    long r = idx / NQKV;
    int k = (int)(r % LD);
    int d = (int)(r / LD);
    g_Wcat[idx] = (c < IN_) ? laq[((long)d*LD + k)*IN_ + c] * ATT_SCALE
                            : lakv[((long)d*LD + k)*NKV + (c - IN_)];
}

// ---------------- vals(b,n,48), invn, mask ----------------
__global__ void sip_build_vals(const float* __restrict__ input)
{
    int vox = blockIdx.x;
    int b = vox / NVOX, n = vox % NVOX;
    int hy = n / (GW*T_), wx = (n / T_) % GW, tt = n % T_;
    int tid = threadIdx.x;               // 64
    __shared__ float ssh[2], msh[2];
    float val = 0.f;
    if (tid < VC){
        int py = tid/12, px = (tid/3)%4, c = tid%3;
        val = input[(((long)tt*B_ + b)*3 + c)*16384 + (hy*4+py)*128 + (wx*4+px)];
        g_vals[(long)vox*VC + tid] = val;
    }
    float ss = val*val;
    float mx = (tid < VC) ? val : -FLT_MAX;
    for (int o=16;o>0;o>>=1){
        ss += __shfl_xor_sync(0xffffffffu, ss, o);
        mx = fmaxf(mx, __shfl_xor_sync(0xffffffffu, mx, o));
    }
    if ((tid & 31) == 0){ ssh[tid>>5] = ss; msh[tid>>5] = mx; }
    __syncthreads();
    if (tid == 0){
        float tot = ssh[0] + ssh[1] + g_ssS[hy] + g_ssS[32+wx] + g_ssS[64+tt];
        g_invn[vox] = 1.f / fmaxf(sqrtf(tot), 1e-5f);
        float m = fmaxf(msh[0], msh[1]);
        g_mask[vox] = (fabsf(m) > 0.3f) ? 1.f : 0.f;
    }
}

// ---------------- per-row scale (gain / L2 norm), warp per row ----------------
__global__ void sip_rowscale(const float* __restrict__ in, float* __restrict__ rsc,
                             const float* __restrict__ gptr)
{
    int row = blockIdx.x*8 + (threadIdx.x >> 5);
    int lane = threadIdx.x & 31;
    const float* p = in + (long)row*LD;
    float s = 0.f;
    for (int j = lane; j < LD; j += 32){ float v = p[j]; s += v*v; }
    for (int o=16;o>0;o>>=1) s += __shfl_xor_sync(0xffffffffu, s, o);
    if (lane == 0) rsc[row] = gptr[0] / fmaxf(sqrtf(s), 1e-5f);
}

__global__ void sip_init_lat(const float* __restrict__ latents, const float* __restrict__ pos)
{
    long idx = (long)blockIdx.x * blockDim.x + threadIdx.x;
    if (idx >= (long)B_*NL*LD) return;
    int r = (int)(idx % (NL*LD));
    g_lat[idx] = latents[r] + pos[r];
}

__global__ void sip_permute_out(float* __restrict__ out)
{
    long idx = (long)blockIdx.x * blockDim.x + threadIdx.x;
    if (idx >= (long)T_*B_*16*OC) return;
    int o = (int)(idx % OC);
    long r = idx / OC;
    int nn = (int)(r % 16); r /= 16;
    int b = (int)(r % B_);
    int tt = (int)(r / B_);
    out[idx] = g_logits[((long)b*NL + nn*T_ + tt)*OC + o];
}

// ---------------- host ----------------
static inline int cdiv(int a, int b){ return (a + b - 1) / b; }

extern "C" void kernel_launch(void* const* d_in, const int* in_sizes, int n_in,
                              void* d_out, int out_size)
{
    const float* input    = (const float*)d_in[0];
    const float* latents  = (const float*)d_in[1];
    const float* pos_emb  = (const float*)d_in[2];
    const float* ca_g     = (const float*)d_in[3];
    const float* ca_ctx_g = (const float*)d_in[4];
    const float* ca_q     = (const float*)d_in[5];
    const float* ca_kv    = (const float*)d_in[6];
    const float* ca_ow    = (const float*)d_in[7];
    const float* ca_ob    = (const float*)d_in[8];
    const float* cf_g     = (const float*)d_in[9];
    const float* cf_w1    = (const float*)d_in[10];
    const float* cf_b1    = (const float*)d_in[11];
    const float* cf_w2    = (const float*)d_in[12];
    const float* cf_b2    = (const float*)d_in[13];
    const float* la_g     = (const float*)d_in[14];
    const float* la_q     = (const float*)d_in[15];
    const float* la_kv    = (const float*)d_in[16];
    const float* la_ow    = (const float*)d_in[17];
    const float* la_ob    = (const float*)d_in[18];
    const float* lf_g     = (const float*)d_in[19];
    const float* lf_w1    = (const float*)d_in[20];
    const float* lf_b1    = (const float*)d_in[21];
    const float* lf_w2    = (const float*)d_in[22];
    const float* lf_b2    = (const float*)d_in[23];
    const float* logits_w = (const float*)d_in[24];
    const float* logits_b = (const float*)d_in[25];
    float* out = (float*)d_out;

    float *p_vals,*p_EPT,*p_invn,*p_rsc,*p_Wcat,*p_lat,*p_Q,*p_KV,*p_QKV,*p_AO,*p_hid,*p_logits;
#define SYM(p, s) do{ void* _t=nullptr; cudaGetSymbolAddress(&_t, s); p=(float*)_t; }while(0)
    SYM(p_vals, g_vals); SYM(p_EPT, g_EPT); SYM(p_invn, g_invn); SYM(p_rsc, g_rsc);
    SYM(p_Wcat, g_Wcat); SYM(p_lat, g_lat);
    SYM(p_Q, g_Q); SYM(p_KV, g_KV); SYM(p_QKV, g_QKV);
    SYM(p_AO, g_AO); SYM(p_hid, g_hid); SYM(p_logits, g_logits);
#undef SYM

    static bool attr_set = false;
    if (!attr_set){
        cudaFuncSetAttribute(sip_flash, cudaFuncAttributeMaxDynamicSharedMemorySize, FLASH_SMEM_BYTES);
        attr_set = true;
    }

    const int M0 = B_*NL;  // 512

    // -------- preamble --------
    sip_build_encsmall<<<96, 160>>>();
    sip_ep2<<<dim3(cdiv(NKV,64), 3, DEPTH), 256>>>(ca_kv);
    sip_build_vals<<<B_*NVOX, 64>>>(input);
    sip_init_lat<<<cdiv(B_*NL*LD,256), 256>>>(latents, pos_emb);
    sip_build_wcat<<<cdiv(DEPTH*LD*NQKV,256), 256>>>(la_q, la_kv);
    sip_zero_kvpad<<<cdiv(B_*NVOX*16*5,256), 256>>>();

    for (int d = 0; d < DEPTH; d++){
        // ===== cross attention =====
        sip_rowscale<<<64, 256>>>(p_lat, p_rsc, ca_g + d);
        sip_mma<64,64,16,32,32,false,0,0,16><<<dim3(cdiv(IN_,64),cdiv(M0,64),1),128>>>(
            M0, IN_, LD, p_lat, LD, 0, p_rsc, ca_q + (long)d*LD*IN_, IN_, 0,
            p_Q, IN_, 0, nullptr, nullptr, nullptr, ATT_SCALE, nullptr, nullptr);
        sip_mma<128,128,16,64,32,false,EPI_KV3|EPI_KVP,0,16><<<dim3(cdiv(NKV,128),cdiv(B_*NVOX,128),1),256>>>(
            B_*NVOX, NKV, VC, p_vals, VC, 0, nullptr, ca_kv + (long)d*ID2*NKV, NKV, 0,
            p_KV, KVROW, 0, nullptr, nullptr, ca_ctx_g + d, 1.f,
            p_EPT + (long)d*96*NKV, p_invn);
        sip_flash<<<dim3(NSPL2, B_*HH), 256, FLASH_SMEM_BYTES>>>();
        sip_flash_combine<<<B_*HH*NL, 128>>>();
        sip_mma<64,64,16,32,32,false,EPI_BIAS|EPI_RES,0,16><<<dim3(cdiv(LD,64),cdiv(M0,64),1),128>>>(
            M0, LD, IN_, p_AO, IN_, 0, nullptr, ca_ow + (long)d*IN_*LD, LD, 0,
            p_lat, LD, 0, ca_ob + (long)d*LD, p_lat, nullptr, 1.f, nullptr, nullptr);

        // ===== feed-forward (cross) =====
        sip_rowscale<<<64, 256>>>(p_lat, p_rsc, cf_g + d);
        sip_mma<64,64,16,32,32,false,EPI_BIAS|EPI_GELU,0,16><<<dim3(cdiv(FF,64),cdiv(M0,64),1),128>>>(
            M0, FF, LD, p_lat, LD, 0, p_rsc, cf_w1 + (long)d*LD*FF, FF, 0,
            p_hid, FF, 0, cf_b1 + (long)d*FF, nullptr, nullptr, 1.f, nullptr, nullptr);
        sip_mma<64,64,16,32,32,false,EPI_BIAS|EPI_RES,0,16><<<dim3(cdiv(LD,64),cdiv(M0,64),1),128>>>(
            M0, LD, FF, p_hid, FF, 0, nullptr, cf_w2 + (long)d*FF*LD, LD, 0,
            p_lat, LD, 0, cf_b2 + (long)d*LD, p_lat, nullptr, 1.f, nullptr, nullptr);

        // ===== latent self-attention (fused) =====
        sip_rowscale<<<64, 256>>>(p_lat, p_rsc, la_g + d);
        sip_mma<64,64,16,32,32,false,0,0,16><<<dim3(cdiv(NQKV,64),cdiv(M0,64),1),128>>>(
            M0, NQKV, LD, p_lat, LD, 0, p_rsc, p_Wcat + (long)d*LD*NQKV, NQKV, 0,
            p_QKV, NQKV, 0, nullptr, nullptr, nullptr, 1.f, nullptr, nullptr);
        sip_flash_lat<<<B_*HH, 256>>>();
        sip_mma<64,64,16,32,32,false,EPI_BIAS|EPI_RES,0,16><<<dim3(cdiv(LD,64),cdiv(M0,64),1),128>>>(
            M0, LD, IN_, p_AO, IN_, 0, nullptr, la_ow + (long)d*IN_*LD, LD, 0,
            p_lat, LD, 0, la_ob + (long)d*LD, p_lat, nullptr, 1.f, nullptr, nullptr);

        // ===== feed-forward (latent) =====
        sip_rowscale<<<64, 256>>>(p_lat, p_rsc, lf_g + d);
        sip_mma<64,64,16,32,32,false,EPI_BIAS|EPI_GELU,0,16><<<dim3(cdiv(FF,64),cdiv(M0,64),1),128>>>(
            M0, FF, LD, p_lat, LD, 0, p_rsc, lf_w1 + (long)d*LD*FF, FF, 0,
            p_hid, FF, 0, lf_b1 + (long)d*FF, nullptr, nullptr, 1.f, nullptr, nullptr);
        sip_mma<64,64,16,32,32,false,EPI_BIAS|EPI_RES,0,16><<<dim3(cdiv(LD,64),cdiv(M0,64),1),128>>>(
            M0, LD, FF, p_hid, FF, 0, nullptr, lf_w2 + (long)d*FF*LD, LD, 0,
            p_lat, LD, 0, lf_b2 + (long)d*LD, p_lat, nullptr, 1.f, nullptr, nullptr);
    }

    // ===== logits + output permute =====
    sip_mma<64,64,16,32,32,false,EPI_BIAS,0,16><<<dim3(cdiv(OC,64),cdiv(M0,64),1),128>>>(
        M0, OC, LD, p_lat, LD, 0, nullptr, logits_w, OC, 0,
        p_logits, OC, 0, logits_b, nullptr, nullptr, 1.f, nullptr, nullptr);
    sip_permute_out<<<cdiv(T_*B_*16*OC,256), 256>>>(out);
}

// round 9
// speedup vs baseline: 5.5523x; 1.0703x over previous
#include <cuda_runtime.h>
#include <math.h>
#include <float.h>
#include <stdint.h>

// ---------------- problem constants ----------------
constexpr int B_   = 4;
constexpr int T_   = 8;
constexpr int HH   = 8;
constexpr int DH   = 75;
constexpr int NL   = 128;
constexpr int LD   = 512;
constexpr int ID2  = 435;
constexpr int VC   = 48;
constexpr int IN_  = 600;
constexpr int FF   = 2048;
constexpr int OC   = 64;
constexpr int DEPTH= 5;
constexpr int GH   = 32, GW = 32;
constexpr int NVOX = GH*GW*T_;           // 8192
constexpr int NKV  = 2*IN_;              // 1200
constexpr int NQKV = IN_ + NKV;          // 1800
constexpr float ATT_SCALE = 0.11547005383792515f;

// flash params
constexpr int NSPL2 = 16;
constexpr int DHP   = 80;
constexpr int BKV   = 32;
constexpr int FITERS= (NVOX/NSPL2)/BKV;  // 16
constexpr int KVROW = 2*HH*DHP;          // 1280
constexpr int LDR   = 84;
constexpr int TILEF = BKV*LDR;
constexpr int BUFF  = 2*TILEF;
constexpr int LDP   = 36;
constexpr int FLASH_SMEM_FLOATS = 2*BUFF + NL*LDP + 2*BKV;
constexpr int FLASH_SMEM_BYTES  = FLASH_SMEM_FLOATS*4;      // 61696

// ---------------- scratch ----------------
__device__ float g_vals [(size_t)B_*NVOX*VC];
__device__ float g_encS [(size_t)96*129];
__device__ float g_ssS  [(size_t)96];
__device__ float g_EPT  [(size_t)DEPTH*96*NKV];
__device__ float g_invn [(size_t)B_*NVOX];
__device__ float g_mask [(size_t)B_*NVOX];
__device__ float g_rsc  [(size_t)B_*NL];
__device__ float g_Wcat [(size_t)DEPTH*LD*NQKV];
__device__ float g_lat  [(size_t)B_*NL*LD];
__device__ float g_Q    [(size_t)B_*NL*IN_];
__device__ float g_KV   [(size_t)B_*NVOX*KVROW];
__device__ float g_QKV  [(size_t)B_*NL*NQKV];
__device__ float g_AO   [(size_t)B_*NL*IN_];
__device__ float g_hid  [(size_t)B_*NL*FF];
__device__ float g_fo   [(size_t)NSPL2*B_*HH*NL*DHP];
__device__ float g_fm   [(size_t)NSPL2*B_*HH*NL];
__device__ float g_fl   [(size_t)NSPL2*B_*HH*NL];

// ---------------- helpers ----------------
__device__ __forceinline__ uint32_t f2tf32(float f){
    uint32_t r; asm("cvt.rna.tf32.f32 %0, %1;" : "=r"(r) : "f"(f)); return r;
}
__device__ __forceinline__ void mma_tf32(float c[4], const uint32_t a[4], const uint32_t b[2]){
    asm("mma.sync.aligned.m16n8k8.row.col.f32.tf32.tf32.f32 "
        "{%0,%1,%2,%3}, {%4,%5,%6,%7}, {%8,%9}, {%0,%1,%2,%3};"
        : "+f"(c[0]), "+f"(c[1]), "+f"(c[2]), "+f"(c[3])
        : "r"(a[0]), "r"(a[1]), "r"(a[2]), "r"(a[3]), "r"(b[0]), "r"(b[1]));
}
__device__ __forceinline__ void cpa16(float* dst, const float* src, int bytes){
    uint32_t d = (uint32_t)__cvta_generic_to_shared(dst);
    asm volatile("cp.async.ca.shared.global [%0], [%1], 16, %2;" :: "r"(d), "l"(src), "r"(bytes));
}
__device__ __forceinline__ void cpa4(float* dst, const float* src, int bytes){
    uint32_t d = (uint32_t)__cvta_generic_to_shared(dst);
    asm volatile("cp.async.ca.shared.global [%0], [%1], 4, %2;" :: "r"(d), "l"(src), "r"(bytes));
}
// fast exp for x <= 0 (FMA pipe)
__device__ __forceinline__ float fexp(float x){
    float t = x * 1.4426950408889634f;
    t = fmaxf(t, -126.0f);
    float fi = floorf(t);
    float f = t - fi;
    float p = 1.5403530e-4f;
    p = fmaf(p, f, 1.3333558e-3f);
    p = fmaf(p, f, 9.6181291e-3f);
    p = fmaf(p, f, 5.5504109e-2f);
    p = fmaf(p, f, 2.4022651e-1f);
    p = fmaf(p, f, 6.9314718e-1f);
    p = fmaf(p, f, 1.0f);
    return p * __int_as_float(((int)fi + 127) << 23);
}

// ---------------- epilogue flags ----------------
#define EPI_BIAS 1
#define EPI_GELU 2
#define EPI_RES  4
#define EPI_KV3  8
#define EPI_KVP  16   // write to padded KV layout
#define EPI_PERM 32   // write logits permuted to out (t,b,n,oc)

// ---------------- pipelined tf32 GEMM (cp.async double buffer) ----------------
template<int BM,int BN,int BK,int WM,int WN,int EPI,int VEC>
__global__ void __launch_bounds__((BM/WM)*(BN/WN)*32)
sip_mma(int M,int N,int K,
        const float* __restrict__ A,int lda,long sA,
        const float* __restrict__ ascale,
        const float* __restrict__ Bp,int ldb,long sB,
        float* __restrict__ C,int ldc,long sC,
        const float* __restrict__ bias,
        const float* __restrict__ resid,
        const float* __restrict__ alphaPtr,float alphaC,
        const float* __restrict__ ep,
        const float* __restrict__ rowscale)
{
    constexpr int NWARP = (BM/WM)*(BN/WN);
    constexpr int NT = NWARP*32;
    constexpr int LDA = BK + 4;
    constexpr int LDB = BN + 4;
    constexpr int ASZ = BM*LDA;
    constexpr int BSZ = BK*LDB;
    constexpr int VE  = VEC/4;
    constexpr int ACP = (BM*BK)/(VE*NT);
    constexpr int BCP = (BN*BK)/(VE*NT);
    __shared__ float As[2][ASZ];
    __shared__ float Bs[2][BSZ];

    int tid = threadIdx.x;
    int batch = blockIdx.z;
    const float* Ab = A + (long)batch*sA;
    const float* Bb = Bp + (long)batch*sB;
    int row0 = blockIdx.y * BM, col0 = blockIdx.x * BN;
    int wid = tid >> 5, lane = tid & 31;
    int g = lane >> 2, tig = lane & 3;
    int wm0 = (wid % (BM/WM)) * WM;
    int wn0 = (wid / (BM/WM)) * WN;
    constexpr int MT = WM/16, NTN = WN/8;

    float rsA[MT][2];
#pragma unroll
    for (int mt=0; mt<MT; mt++){
        int r0 = row0 + wm0 + mt*16 + g;
        rsA[mt][0] = (ascale && r0   < M) ? ascale[r0]   : 1.f;
        rsA[mt][1] = (ascale && r0+8 < M) ? ascale[r0+8] : 1.f;
    }

    float acc[MT][NTN][4];
#pragma unroll
    for (int i=0;i<MT;i++)
#pragma unroll
        for (int j=0;j<NTN;j++)
#pragma unroll
            for (int r=0;r<4;r++) acc[i][j][r] = 0.f;

    int ktiles = (K + BK - 1) / BK;

    auto loadA = [&](int kt, int buf){
#pragma unroll
        for (int e=0; e<ACP; e++){
            int v = e*NT + tid;
            int m = v / (BK/VE), kq = v - m*(BK/VE);
            int gm = row0 + m, gk = kt + kq*VE;
            const float* src = Ab + (long)gm*lda + gk;
            int bytes = 0;
            if (gm < M && gk < K) bytes = min(K - gk, VE) * 4;
            if (!bytes) src = Ab;
            if (VEC == 16) cpa16(&As[buf][m*LDA + kq*VE], src, bytes);
            else           cpa4 (&As[buf][m*LDA + kq*VE], src, bytes);
        }
    };
    auto loadB = [&](int kt, int buf){
#pragma unroll
        for (int e=0; e<BCP; e++){
            int v = e*NT + tid;
            int k = v / (BN/VE), nq = v - k*(BN/VE);
            int gn = col0 + nq*VE, gk = kt + k;
            const float* src = Bb + (long)gk*ldb + gn;
            int bytes = 0;
            if (gk < K && gn < N) bytes = min(N - gn, VE) * 4;
            if (!bytes) src = Bb;
            if (VEC == 16) cpa16(&Bs[buf][k*LDB + nq*VE], src, bytes);
            else           cpa4 (&Bs[buf][k*LDB + nq*VE], src, bytes);
        }
    };

    loadA(0, 0); loadB(0, 0);
    asm volatile("cp.async.commit_group;");

    for (int t=0; t<ktiles; t++){
        int cur = t & 1;
        if (t+1 < ktiles){
            loadA((t+1)*BK, cur^1); loadB((t+1)*BK, cur^1);
            asm volatile("cp.async.commit_group;");
            asm volatile("cp.async.wait_group 1;");
        } else {
            asm volatile("cp.async.wait_group 0;");
        }
        __syncthreads();
#pragma unroll
        for (int ks=0; ks<BK/8; ks++){
            uint32_t af[MT][4], bf[NTN][2];
#pragma unroll
            for (int mt=0; mt<MT; mt++){
                int mb = wm0 + mt*16;
                float a0 = As[cur][(mb+g  )*LDA + ks*8 + tig    ];
                float a1 = As[cur][(mb+g+8)*LDA + ks*8 + tig    ];
                float a2 = As[cur][(mb+g  )*LDA + ks*8 + tig + 4];
                float a3 = As[cur][(mb+g+8)*LDA + ks*8 + tig + 4];
                af[mt][0] = f2tf32(a0 * rsA[mt][0]);
                af[mt][1] = f2tf32(a1 * rsA[mt][1]);
                af[mt][2] = f2tf32(a2 * rsA[mt][0]);
                af[mt][3] = f2tf32(a3 * rsA[mt][1]);
            }
#pragma unroll
            for (int nt=0; nt<NTN; nt++){
                int nb = wn0 + nt*8;
                float b0 = Bs[cur][(ks*8 + tig    )*LDB + nb + g];
                float b1 = Bs[cur][(ks*8 + tig + 4)*LDB + nb + g];
                bf[nt][0] = f2tf32(b0); bf[nt][1] = f2tf32(b1);
            }
#pragma unroll
            for (int mt=0; mt<MT; mt++)
#pragma unroll
                for (int nt=0; nt<NTN; nt++)
                    mma_tf32(acc[mt][nt], af[mt], bf[nt]);
        }
        __syncthreads();
    }

    float alpha = alphaC;
    if (alphaPtr) alpha *= alphaPtr[0];

    float* Cb = C + (long)batch*sC;
    const float* Rb = (EPI & EPI_RES) ? resid + (long)batch * sC : nullptr;

    int colw[NTN][2];
#pragma unroll
    for (int nt=0; nt<NTN; nt++)
#pragma unroll
    for (int c2=0; c2<2; c2++){
        int gn = col0 + wn0 + nt*8 + tig*2 + c2;
        if (EPI & EPI_KVP){
            int kvs = (gn >= IN_) ? 1 : 0;
            int c = gn - kvs*IN_;
            int hh2 = c / DH;
            colw[nt][c2] = kvs*(HH*DHP) + hh2*DHP + (c - hh2*DH);
        } else colw[nt][c2] = gn;
    }
    const long ldcE = (EPI & EPI_KVP) ? (long)KVROW : (long)ldc;

#pragma unroll
    for (int mt=0; mt<MT; mt++)
#pragma unroll
    for (int r2=0; r2<2; r2++){
        int gm = row0 + wm0 + mt*16 + g + r2*8;
        if (gm >= M) continue;
        float rs = alpha;
        const float *e0=nullptr,*e1=nullptr,*e2=nullptr;
        if (EPI & EPI_KV3){
            int jj = gm % NVOX;
            int y = jj>>8, xx = (jj>>3)&31, t = jj&7;
            e0 = ep + (long)y*NKV;
            e1 = ep + (long)(32+xx)*NKV;
            e2 = ep + (long)(64+t)*NKV;
            if (rowscale) rs *= rowscale[gm];
        }
#pragma unroll
        for (int nt=0; nt<NTN; nt++)
#pragma unroll
        for (int c2=0; c2<2; c2++){
            int gn = col0 + wn0 + nt*8 + tig*2 + c2;
            if (gn >= N) continue;
            float v = acc[mt][nt][r2*2 + c2];
            if (EPI & EPI_KV3) v += e0[gn] + e1[gn] + e2[gn];
            v *= rs;
            if (EPI & EPI_BIAS) v += bias[gn];
            if (EPI & EPI_GELU) v = 0.5f * v * (1.f + erff(v * 0.7071067811865476f));
            if (EPI & EPI_RES)  v += Rb[(long)gm*ldc + gn];
            if (EPI & EPI_PERM){
                int bb = gm >> 7, i = gm & 127;
                int nn = i >> 3, tt = i & 7;
                C[(((long)tt*B_ + bb)*16 + nn)*OC + gn] = v;
            } else {
                Cb[gm*ldcE + colw[nt][c2]] = v;
            }
        }
    }
}

// ---------------- zero KV pad columns ----------------
__global__ void sip_zero_kvpad()
{
    long idx = (long)blockIdx.x*blockDim.x + threadIdx.x;
    long total = (long)B_*NVOX*16*5;
    if (idx >= total) return;
    long r = idx / 80;
    int s = (int)((idx % 80) / 5);
    int p = (int)(idx % 5);
    g_KV[r*KVROW + s*DHP + DH + p] = 0.f;
}

// ---------------- pipelined cross-attention flash (split-KV, cp.async) ----------------
__global__ void __launch_bounds__(256)
sip_flash()
{
    extern __shared__ float sm[];
    float* Ps  = sm + 2*BUFF;
    float* msk = Ps + NL*LDP;

    int split = blockIdx.x, bh = blockIdx.y;
    int b = bh / HH, h = bh - b*HH;
    int tid = threadIdx.x, w = tid>>5, lane = tid&31;
    int g = lane>>2, tig = lane&3;
    int kv0 = split * (NVOX/NSPL2);

    const float* KVb = g_KV + (long)b*NVOX*KVROW + h*DHP;
    const float* Mb  = g_mask + (long)b*NVOX;

    uint32_t qf[10][4];
    {
        const float* Qb = g_Q + (long)b*NL*IN_ + (long)h*DH;
        int r0 = w*16 + g;
#pragma unroll
        for (int ks=0; ks<10; ks++){
            int c0 = ks*8 + tig;
            float v00 = (c0   < DH) ? Qb[(long)r0*IN_ + c0]       : 0.f;
            float v10 = (c0   < DH) ? Qb[(long)(r0+8)*IN_ + c0]   : 0.f;
            float v01 = (c0+4 < DH) ? Qb[(long)r0*IN_ + c0+4]     : 0.f;
            float v11 = (c0+4 < DH) ? Qb[(long)(r0+8)*IN_ + c0+4] : 0.f;
            qf[ks][0]=f2tf32(v00); qf[ks][1]=f2tf32(v10);
            qf[ks][2]=f2tf32(v01); qf[ks][3]=f2tf32(v11);
        }
    }

    float o[10][4];
#pragma unroll
    for (int nt=0;nt<10;nt++)
#pragma unroll
        for (int r=0;r<4;r++) o[nt][r]=0.f;
    float mrun[2] = {-FLT_MAX, -FLT_MAX};
    float lrun[2] = {0.f, 0.f};

    auto prefetch = [&](int it, int buf){
        int j0 = kv0 + it*BKV;
#pragma unroll
        for (int e=0;e<5;e++){
            int idx = e*256 + tid;
            int t = idx / 640;
            int v = idx - t*640;
            int r = v / 20, q = v - r*20;
            cpa16(sm + buf*BUFF + t*TILEF + r*LDR + q*4,
                  KVb + (long)(j0+r)*KVROW + t*(HH*DHP) + q*4, 16);
        }
        if (tid < BKV) cpa4(msk + buf*BKV + tid, Mb + j0 + tid, 4);
    };

    prefetch(0, 0);
    asm volatile("cp.async.commit_group;");

    for (int it=0; it<FITERS; it++){
        int cur = it & 1;
        if (it+1 < FITERS){
            prefetch(it+1, cur^1);
            asm volatile("cp.async.commit_group;");
            asm volatile("cp.async.wait_group 1;");
        } else {
            asm volatile("cp.async.wait_group 0;");
        }
        __syncthreads();
        const float* Kt = sm + cur*BUFF;
        const float* Vt = Kt + TILEF;
        const float* mk = msk + cur*BKV;

        float s[4][4];
#pragma unroll
        for (int nt=0;nt<4;nt++)
#pragma unroll
            for (int r=0;r<4;r++) s[nt][r]=0.f;
#pragma unroll
        for (int ks=0; ks<10; ks++){
            uint32_t bfr[4][2];
#pragma unroll
            for (int nt=0;nt<4;nt++){
                bfr[nt][0] = f2tf32(Kt[(nt*8+g)*LDR + ks*8 + tig    ]);
                bfr[nt][1] = f2tf32(Kt[(nt*8+g)*LDR + ks*8 + tig + 4]);
            }
#pragma unroll
            for (int nt=0;nt<4;nt++) mma_tf32(s[nt], qf[ks], bfr[nt]);
        }
#pragma unroll
        for (int nt=0;nt<4;nt++)
#pragma unroll
        for (int r=0;r<4;r++){
            int jl = nt*8 + tig*2 + (r & 1);
            if (mk[jl] < 0.5f) s[nt][r] = -FLT_MAX;
        }
#pragma unroll
        for (int r2=0;r2<2;r2++){
            float mx = -FLT_MAX;
#pragma unroll
            for (int nt=0;nt<4;nt++){
                mx = fmaxf(mx, s[nt][r2*2+0]);
                mx = fmaxf(mx, s[nt][r2*2+1]);
            }
            mx = fmaxf(mx, __shfl_xor_sync(0xffffffffu, mx, 1));
            mx = fmaxf(mx, __shfl_xor_sync(0xffffffffu, mx, 2));
            if (mx > mrun[r2]){           // rescale only when max increases
                float sc = fexp(mrun[r2] - mx);
                mrun[r2] = mx;
                lrun[r2] *= sc;
#pragma unroll
                for (int nt=0;nt<10;nt++){
                    o[nt][r2*2+0] *= sc;
                    o[nt][r2*2+1] *= sc;
                }
            }
            float mnew = mrun[r2];
            float ps = 0.f;
#pragma unroll
            for (int nt=0;nt<4;nt++){
                float p0 = fexp(s[nt][r2*2+0] - mnew);
                float p1 = fexp(s[nt][r2*2+1] - mnew);
                s[nt][r2*2+0] = p0; s[nt][r2*2+1] = p1;
                ps += p0 + p1;
            }
            ps += __shfl_xor_sync(0xffffffffu, ps, 1);
            ps += __shfl_xor_sync(0xffffffffu, ps, 2);
            lrun[r2] += ps;
        }
#pragma unroll
        for (int nt=0;nt<4;nt++)
#pragma unroll
        for (int r=0;r<4;r++){
            int row = w*16 + g + (r>>1)*8;
            int col = nt*8 + tig*2 + (r&1);
            Ps[row*LDP + col] = s[nt][r];
        }
        __syncwarp();
#pragma unroll
        for (int ks=0; ks<4; ks++){
            uint32_t af[4];
            af[0] = f2tf32(Ps[(w*16 + g    )*LDP + ks*8 + tig    ]);
            af[1] = f2tf32(Ps[(w*16 + g + 8)*LDP + ks*8 + tig    ]);
            af[2] = f2tf32(Ps[(w*16 + g    )*LDP + ks*8 + tig + 4]);
            af[3] = f2tf32(Ps[(w*16 + g + 8)*LDP + ks*8 + tig + 4]);
#pragma unroll
            for (int nt=0;nt<10;nt++){
                uint32_t bfr[2];
                bfr[0] = f2tf32(Vt[(ks*8 + tig    )*LDR + nt*8 + g]);
                bfr[1] = f2tf32(Vt[(ks*8 + tig + 4)*LDR + nt*8 + g]);
                mma_tf32(o[nt], af, bfr);
            }
        }
        __syncthreads();
    }

    long base = ((long)split*B_*HH + bh) * NL;
#pragma unroll
    for (int r2=0;r2<2;r2++){
        int row = w*16 + g + r2*8;
        if (tig == 0){
            g_fm[base + row] = mrun[r2];
            g_fl[base + row] = lrun[r2];
        }
#pragma unroll
        for (int nt=0;nt<10;nt++){
            g_fo[(base + row)*DHP + nt*8 + tig*2 + 0] = o[nt][r2*2+0];
            g_fo[(base + row)*DHP + nt*8 + tig*2 + 1] = o[nt][r2*2+1];
        }
    }
}

// ---------------- flash split combine + head merge -> AO ----------------
__global__ void sip_flash_combine()
{
    int blk = blockIdx.x;
    int bh = blk / NL, row = blk - bh*NL;
    int b = bh / HH, h = bh - b*HH;
    int tid = threadIdx.x;           // 128
    __shared__ float sm2[NSPL2], sl[NSPL2];
    __shared__ float sms, sden;
    if (tid < NSPL2){
        long idx = ((long)tid*B_*HH + bh)*NL + row;
        sm2[tid] = g_fm[idx];
        sl[tid] = g_fl[idx];
    }
    __syncthreads();
    if (tid == 0){
        float mx = sm2[0];
#pragma unroll
        for (int s2=1;s2<NSPL2;s2++) mx = fmaxf(mx, sm2[s2]);
        float den = 0.f;
#pragma unroll
        for (int s2=0;s2<NSPL2;s2++) den += sl[s2] * fexp(sm2[s2] - mx);
        sms = mx; sden = den;
    }
    __syncthreads();
    if (tid < DH){
        float acc = 0.f;
#pragma unroll
        for (int s2=0;s2<NSPL2;s2++){
            float wgt = fexp(sm2[s2] - sms);
            acc += g_fo[(((long)s2*B_*HH + bh)*NL + row)*DHP + tid] * wgt;
        }
        g_AO[((long)b*NL + row)*IN_ + h*DH + tid] = acc / sden;
    }
}

// ---------------- fused latent self-attention (per b,h, 4-way Q split) ----------------
__global__ void __launch_bounds__(64)
sip_flash_lat()
{
    __shared__ float Kt[BKV*LDR];
    __shared__ float Vt[BKV*LDR];
    __shared__ float Ps[32*LDP];

    int qs = blockIdx.x;                 // q-row group (0..3)
    int bh = blockIdx.y;
    int b = bh / HH, h = bh - b*HH;
    int tid = threadIdx.x, w = tid>>5, lane = tid&31;
    int g = lane>>2, tig = lane&3;

    const float* Qb = g_QKV + (long)b*NL*NQKV + h*DH;
    const float* Kb = Qb + IN_;
    const float* Vb = Qb + NKV;

    uint32_t qf[10][4];
    {
        int r0 = qs*32 + w*16 + g;
#pragma unroll
        for (int ks=0; ks<10; ks++){
            int c0 = ks*8 + tig;
            float v00 = (c0   < DH) ? Qb[(long)r0*NQKV + c0]       : 0.f;
            float v10 = (c0   < DH) ? Qb[(long)(r0+8)*NQKV + c0]   : 0.f;
            float v01 = (c0+4 < DH) ? Qb[(long)r0*NQKV + c0+4]     : 0.f;
            float v11 = (c0+4 < DH) ? Qb[(long)(r0+8)*NQKV + c0+4] : 0.f;
            qf[ks][0]=f2tf32(v00); qf[ks][1]=f2tf32(v10);
            qf[ks][2]=f2tf32(v01); qf[ks][3]=f2tf32(v11);
        }
    }

    float o[10][4];
#pragma unroll
    for (int nt=0;nt<10;nt++)
#pragma unroll
        for (int r=0;r<4;r++) o[nt][r]=0.f;
    float mrun[2] = {-FLT_MAX, -FLT_MAX};
    float lrun[2] = {0.f, 0.f};

    for (int it=0; it<NL/BKV; it++){
        int j0 = it*BKV;
#pragma unroll
        for (int e=0;e<80;e++){
            int idx = e*64 + tid;            // 0..5119
            int t = idx / 2560;
            int v = idx - t*2560;
            int r = v / 80, c = v - r*80;
            const float* src = t ? Vb : Kb;
            float val = (c < DH) ? src[(long)(j0+r)*NQKV + c] : 0.f;
            (t ? Vt : Kt)[r*LDR + c] = val;
        }
        __syncthreads();

        float s[4][4];
#pragma unroll
        for (int nt=0;nt<4;nt++)
#pragma unroll
            for (int r=0;r<4;r++) s[nt][r]=0.f;
#pragma unroll
        for (int ks=0; ks<10; ks++){
            uint32_t bfr[4][2];
#pragma unroll
            for (int nt=0;nt<4;nt++){
                bfr[nt][0] = f2tf32(Kt[(nt*8+g)*LDR + ks*8 + tig    ]);
                bfr[nt][1] = f2tf32(Kt[(nt*8+g)*LDR + ks*8 + tig + 4]);
            }
#pragma unroll
            for (int nt=0;nt<4;nt++) mma_tf32(s[nt], qf[ks], bfr[nt]);
        }
#pragma unroll
        for (int r2=0;r2<2;r2++){
            float mx = -FLT_MAX;
#pragma unroll
            for (int nt=0;nt<4;nt++){
                mx = fmaxf(mx, s[nt][r2*2+0]);
                mx = fmaxf(mx, s[nt][r2*2+1]);
            }
            mx = fmaxf(mx, __shfl_xor_sync(0xffffffffu, mx, 1));
            mx = fmaxf(mx, __shfl_xor_sync(0xffffffffu, mx, 2));
            if (mx > mrun[r2]){
                float sc = fexp(mrun[r2] - mx);
                mrun[r2] = mx;
                lrun[r2] *= sc;
#pragma unroll
                for (int nt=0;nt<10;nt++){
                    o[nt][r2*2+0] *= sc;
                    o[nt][r2*2+1] *= sc;
                }
            }
            float mnew = mrun[r2];
            float ps = 0.f;
#pragma unroll
            for (int nt=0;nt<4;nt++){
                float p0 = fexp(s[nt][r2*2+0] - mnew);
                float p1 = fexp(s[nt][r2*2+1] - mnew);
                s[nt][r2*2+0] = p0; s[nt][r2*2+1] = p1;
                ps += p0 + p1;
            }
            ps += __shfl_xor_sync(0xffffffffu, ps, 1);
            ps += __shfl_xor_sync(0xffffffffu, ps, 2);
            lrun[r2] += ps;
        }
#pragma unroll
        for (int nt=0;nt<4;nt++)
#pragma unroll
        for (int r=0;r<4;r++){
            int row = w*16 + g + (r>>1)*8;
            int col = nt*8 + tig*2 + (r&1);
            Ps[row*LDP + col] = s[nt][r];
        }
        __syncwarp();
#pragma unroll
        for (int ks=0; ks<4; ks++){
            uint32_t af[4];
            af[0] = f2tf32(Ps[(w*16 + g    )*LDP + ks*8 + tig    ]);
            af[1] = f2tf32(Ps[(w*16 + g + 8)*LDP + ks*8 + tig    ]);
            af[2] = f2tf32(Ps[(w*16 + g    )*LDP + ks*8 + tig + 4]);
            af[3] = f2tf32(Ps[(w*16 + g + 8)*LDP + ks*8 + tig + 4]);
#pragma unroll
            for (int nt=0;nt<10;nt++){
                uint32_t bfr[2];
                bfr[0] = f2tf32(Vt[(ks*8 + tig    )*LDR + nt*8 + g]);
                bfr[1] = f2tf32(Vt[(ks*8 + tig + 4)*LDR + nt*8 + g]);
                mma_tf32(o[nt], af, bfr);
            }
        }
        __syncthreads();
    }

#pragma unroll
    for (int r2=0;r2<2;r2++){
        int row = qs*32 + w*16 + g + r2*8;
        float inv = 1.f / lrun[r2];
#pragma unroll
        for (int nt=0;nt<10;nt++)
#pragma unroll
        for (int c2=0;c2<2;c2++){
            int col = nt*8 + tig*2 + c2;
            if (col < DH)
                g_AO[((long)b*NL + row)*IN_ + h*DH + col] = o[nt][r2*2+c2] * inv;
        }
    }
}

// ---------------- separable fourier features ----------------
__global__ void sip_build_encsmall()
{
    int ri = blockIdx.x;
    int a = ri >> 5, v = ri & 31;
    float dim = (a == 2) ? 8.f : 32.f;
    float x = 2.f*v/dim - 1.f;
    int tid = threadIdx.x;               // 160
    __shared__ float sh[5];
    float val = 0.f;
    if (tid < 129){
        int r = tid;
        if (r < 64)        val = sinf(x * exp2f((float)(-r)));
        else if (r < 128)  val = cosf(x * exp2f((float)(64 - r)));
        else               val = x;
        g_encS[ri*129 + tid] = val;
    }
    float ss = val*val;
    for (int o=16;o>0;o>>=1) ss += __shfl_xor_sync(0xffffffffu, ss, o);
    if ((tid & 31) == 0) sh[tid>>5] = ss;
    __syncthreads();
    if (tid == 0) g_ssS[ri] = sh[0]+sh[1]+sh[2]+sh[3]+sh[4];
}

// ---------------- factored EP tables ----------------
__global__ void __launch_bounds__(256)
sip_ep2(const float* __restrict__ kvw)
{
    __shared__ float E[32][130];
    int a = blockIdx.y, d = blockIdx.z;
    int tid = threadIdx.x;
    for (int i = tid; i < 32*129; i += 256){
        int r = i / 129, cc = i - r*129;
        E[r][cc] = g_encS[(a*32 + r)*129 + cc];
    }
    __syncthreads();
    int c = blockIdx.x*64 + (tid & 63);
    int rg = tid >> 6;
    if (c >= NKV) return;
    const float* W = kvw + (long)d*ID2*NKV + (long)(VC + a*129)*NKV + c;
    float acc[8];
#pragma unroll
    for (int k=0;k<8;k++) acc[k] = 0.f;
    for (int r=0;r<129;r++){
        float w = W[(long)r*NKV];
#pragma unroll
        for (int k=0;k<8;k++) acc[k] = fmaf(E[rg*8+k][r], w, acc[k]);
    }
#pragma unroll
    for (int k=0;k<8;k++)
        g_EPT[((long)d*96 + a*32 + rg*8 + k)*NKV + c] = acc[k];
}

// ---------------- latent weight concat ----------------
__global__ void sip_build_wcat(const float* __restrict__ laq, const float* __restrict__ lakv)
{
    long idx = (long)blockIdx.x * blockDim.x + threadIdx.x;
    long total = (long)DEPTH*LD*NQKV;
    if (idx >= total) return;
    int c = (int)(idx % NQKV);
    long r = idx / NQKV;
    int k = (int)(r % LD);
    int d = (int)(r / LD);
    g_Wcat[idx] = (c < IN_) ? laq[((long)d*LD + k)*IN_ + c] * ATT_SCALE
                            : lakv[((long)d*LD + k)*NKV + (c - IN_)];
}

// ---------------- vals(b,n,48), invn, mask ----------------
__global__ void sip_build_vals(const float* __restrict__ input)
{
    int vox = blockIdx.x;
    int b = vox / NVOX, n = vox % NVOX;
    int hy = n / (GW*T_), wx = (n / T_) % GW, tt = n % T_;
    int tid = threadIdx.x;               // 64
    __shared__ float ssh[2], msh[2];
    float val = 0.f;
    if (tid < VC){
        int py = tid/12, px = (tid/3)%4, c = tid%3;
        val = input[(((long)tt*B_ + b)*3 + c)*16384 + (hy*4+py)*128 + (wx*4+px)];
        g_vals[(long)vox*VC + tid] = val;
    }
    float ss = val*val;
    float mx = (tid < VC) ? val : -FLT_MAX;
    for (int o=16;o>0;o>>=1){
        ss += __shfl_xor_sync(0xffffffffu, ss, o);
        mx = fmaxf(mx, __shfl_xor_sync(0xffffffffu, mx, o));
    }
    if ((tid & 31) == 0){ ssh[tid>>5] = ss; msh[tid>>5] = mx; }
    __syncthreads();
    if (tid == 0){
        float tot = ssh[0] + ssh[1] + g_ssS[hy] + g_ssS[32+wx] + g_ssS[64+tt];
        g_invn[vox] = 1.f / fmaxf(sqrtf(tot), 1e-5f);
        float m = fmaxf(msh[0], msh[1]);
        g_mask[vox] = (fabsf(m) > 0.3f) ? 1.f : 0.f;
    }
}

// ---------------- per-row scale ----------------
__global__ void sip_rowscale(const float* __restrict__ in, float* __restrict__ rsc,
                             const float* __restrict__ gptr)
{
    int row = blockIdx.x*8 + (threadIdx.x >> 5);
    int lane = threadIdx.x & 31;
    const float* p = in + (long)row*LD;
    float s = 0.f;
    for (int j = lane; j < LD; j += 32){ float v = p[j]; s += v*v; }
    for (int o=16;o>0;o>>=1) s += __shfl_xor_sync(0xffffffffu, s, o);
    if (lane == 0) rsc[row] = gptr[0] / fmaxf(sqrtf(s), 1e-5f);
}

__global__ void sip_init_lat(const float* __restrict__ latents, const float* __restrict__ pos)
{
    long idx = (long)blockIdx.x * blockDim.x + threadIdx.x;
    if (idx >= (long)B_*NL*LD) return;
    int r = (int)(idx % (NL*LD));
    g_lat[idx] = latents[r] + pos[r];
}

// ---------------- host ----------------
static inline int cdiv(int a, int b){ return (a + b - 1) / b; }

extern "C" void kernel_launch(void* const* d_in, const int* in_sizes, int n_in,
                              void* d_out, int out_size)
{
    const float* input    = (const float*)d_in[0];
    const float* latents  = (const float*)d_in[1];
    const float* pos_emb  = (const float*)d_in[2];
    const float* ca_g     = (const float*)d_in[3];
    const float* ca_ctx_g = (const float*)d_in[4];
    const float* ca_q     = (const float*)d_in[5];
    const float* ca_kv    = (const float*)d_in[6];
    const float* ca_ow    = (const float*)d_in[7];
    const float* ca_ob    = (const float*)d_in[8];
    const float* cf_g     = (const float*)d_in[9];
    const float* cf_w1    = (const float*)d_in[10];
    const float* cf_b1    = (const float*)d_in[11];
    const float* cf_w2    = (const float*)d_in[12];
    const float* cf_b2    = (const float*)d_in[13];
    const float* la_g     = (const float*)d_in[14];
    const float* la_q     = (const float*)d_in[15];
    const float* la_kv    = (const float*)d_in[16];
    const float* la_ow    = (const float*)d_in[17];
    const float* la_ob    = (const float*)d_in[18];
    const float* lf_g     = (const float*)d_in[19];
    const float* lf_w1    = (const float*)d_in[20];
    const float* lf_b1    = (const float*)d_in[21];
    const float* lf_w2    = (const float*)d_in[22];
    const float* lf_b2    = (const float*)d_in[23];
    const float* logits_w = (const float*)d_in[24];
    const float* logits_b = (const float*)d_in[25];
    float* out = (float*)d_out;

    float *p_vals,*p_EPT,*p_invn,*p_rsc,*p_Wcat,*p_lat,*p_Q,*p_KV,*p_QKV,*p_AO,*p_hid;
#define SYM(p, s) do{ void* _t=nullptr; cudaGetSymbolAddress(&_t, s); p=(float*)_t; }while(0)
    SYM(p_vals, g_vals); SYM(p_EPT, g_EPT); SYM(p_invn, g_invn); SYM(p_rsc, g_rsc);
    SYM(p_Wcat, g_Wcat); SYM(p_lat, g_lat);
    SYM(p_Q, g_Q); SYM(p_KV, g_KV); SYM(p_QKV, g_QKV);
    SYM(p_AO, g_AO); SYM(p_hid, g_hid);
#undef SYM

    static bool attr_set = false;
    if (!attr_set){
        cudaFuncSetAttribute(sip_flash, cudaFuncAttributeMaxDynamicSharedMemorySize, FLASH_SMEM_BYTES);
        attr_set = true;
    }

    const int M0 = B_*NL;  // 512

    // -------- preamble --------
    sip_build_encsmall<<<96, 160>>>();
    sip_ep2<<<dim3(cdiv(NKV,64), 3, DEPTH), 256>>>(ca_kv);
    sip_build_vals<<<B_*NVOX, 64>>>(input);
    sip_init_lat<<<cdiv(B_*NL*LD,256), 256>>>(latents, pos_emb);
    sip_build_wcat<<<cdiv(DEPTH*LD*NQKV,256), 256>>>(la_q, la_kv);
    sip_zero_kvpad<<<cdiv(B_*NVOX*16*5,256), 256>>>();

    for (int d = 0; d < DEPTH; d++){
        // ===== cross attention =====
        sip_rowscale<<<64, 256>>>(p_lat, p_rsc, ca_g + d);
        sip_mma<64,64,32,32,32,0,16><<<dim3(cdiv(IN_,64),cdiv(M0,64),1),128>>>(
            M0, IN_, LD, p_lat, LD, 0, p_rsc, ca_q + (long)d*LD*IN_, IN_, 0,
            p_Q, IN_, 0, nullptr, nullptr, nullptr, ATT_SCALE, nullptr, nullptr);
        sip_mma<128,128,16,64,32,EPI_KV3|EPI_KVP,16><<<dim3(cdiv(NKV,128),cdiv(B_*NVOX,128),1),256>>>(
            B_*NVOX, NKV, VC, p_vals, VC, 0, nullptr, ca_kv + (long)d*ID2*NKV, NKV, 0,
            p_KV, KVROW, 0, nullptr, nullptr, ca_ctx_g + d, 1.f,
            p_EPT + (long)d*96*NKV, p_invn);
        sip_flash<<<dim3(NSPL2, B_*HH), 256, FLASH_SMEM_BYTES>>>();
        sip_flash_combine<<<B_*HH*NL, 128>>>();
        sip_mma<64,64,32,32,32,EPI_BIAS|EPI_RES,16><<<dim3(cdiv(LD,64),cdiv(M0,64),1),128>>>(
            M0, LD, IN_, p_AO, IN_, 0, nullptr, ca_ow + (long)d*IN_*LD, LD, 0,
            p_lat, LD, 0, ca_ob + (long)d*LD, p_lat, nullptr, 1.f, nullptr, nullptr);

        // ===== feed-forward (cross) =====
        sip_rowscale<<<64, 256>>>(p_lat, p_rsc, cf_g + d);
        sip_mma<64,64,32,32,32,EPI_BIAS|EPI_GELU,16><<<dim3(cdiv(FF,64),cdiv(M0,64),1),128>>>(
            M0, FF, LD, p_lat, LD, 0, p_rsc, cf_w1 + (long)d*LD*FF, FF, 0,
            p_hid, FF, 0, cf_b1 + (long)d*FF, nullptr, nullptr, 1.f, nullptr, nullptr);
        sip_mma<64,64,32,32,32,EPI_BIAS|EPI_RES,16><<<dim3(cdiv(LD,64),cdiv(M0,64),1),128>>>(
            M0, LD, FF, p_hid, FF, 0, nullptr, cf_w2 + (long)d*FF*LD, LD, 0,
            p_lat, LD, 0, cf_b2 + (long)d*LD, p_lat, nullptr, 1.f, nullptr, nullptr);

        // ===== latent self-attention (fused) =====
        sip_rowscale<<<64, 256>>>(p_lat, p_rsc, la_g + d);
        sip_mma<64,64,32,32,32,0,16><<<dim3(cdiv(NQKV,64),cdiv(M0,64),1),128>>>(
            M0, NQKV, LD, p_lat, LD, 0, p_rsc, p_Wcat + (long)d*LD*NQKV, NQKV, 0,
            p_QKV, NQKV, 0, nullptr, nullptr, nullptr, 1.f, nullptr, nullptr);
        sip_flash_lat<<<dim3(4, B_*HH), 64>>>();
        sip_mma<64,64,32,32,32,EPI_BIAS|EPI_RES,16><<<dim3(cdiv(LD,64),cdiv(M0,64),1),128>>>(
            M0, LD, IN_, p_AO, IN_, 0, nullptr, la_ow + (long)d*IN_*LD, LD, 0,
            p_lat, LD, 0, la_ob + (long)d*LD, p_lat, nullptr, 1.f, nullptr, nullptr);

        // ===== feed-forward (latent) =====
        sip_rowscale<<<64, 256>>>(p_lat, p_rsc, lf_g + d);
        sip_mma<64,64,32,32,32,EPI_BIAS|EPI_GELU,16><<<dim3(cdiv(FF,64),cdiv(M0,64),1),128>>>(
            M0, FF, LD, p_lat, LD, 0, p_rsc, lf_w1 + (long)d*LD*FF, FF, 0,
            p_hid, FF, 0, lf_b1 + (long)d*FF, nullptr, nullptr, 1.f, nullptr, nullptr);
        sip_mma<64,64,32,32,32,EPI_BIAS|EPI_RES,16><<<dim3(cdiv(LD,64),cdiv(M0,64),1),128>>>(
            M0, LD, FF, p_hid, FF, 0, nullptr, lf_w2 + (long)d*FF*LD, LD, 0,
            p_lat, LD, 0, lf_b2 + (long)d*LD, p_lat, nullptr, 1.f, nullptr, nullptr);
    }

    // ===== logits, permuted directly into out =====
    sip_mma<64,64,32,32,32,EPI_BIAS|EPI_PERM,16><<<dim3(cdiv(OC,64),cdiv(M0,64),1),128>>>(
        M0, OC, LD, p_lat, LD, 0, nullptr, logits_w, OC, 0,
        out, OC, 0, logits_b, nullptr, nullptr, 1.f, nullptr, nullptr);
}